// round 9
// baseline (speedup 1.0000x reference)
#include <cuda_runtime.h>
#include <cuda_fp16.h>
#include <cstdint>

// ---------------------------------------------------------------------------
// Problem constants
// ---------------------------------------------------------------------------
#define NPTS   524288
#define LVLS   16
#define TSIZE  524288u
#define TMASK  (TSIZE - 1u)

__constant__ float c_res[LVLS] = {
    16.f, 24.f, 36.f, 54.f, 81.f, 121.f, 182.f, 273.f,
    410.f, 615.f, 922.f, 1383.f, 2075.f, 3113.f, 4670.f, 7006.f
};

// ---------------------------------------------------------------------------
// Scratch (device globals; no runtime allocation)
// ---------------------------------------------------------------------------
__device__ __align__(16) __half g_enc_s_hi[(size_t)NPTS * 32];
__device__ __align__(16) __half g_enc_s_lo[(size_t)NPTS * 32];
__device__ __align__(16) __half g_enc_d_hi[(size_t)NPTS * 32];
__device__ __align__(16) __half g_enc_d_lo[(size_t)NPTS * 32];
__device__ __align__(16) __half g_feat_hi [(size_t)NPTS * 128];
__device__ __align__(16) __half g_feat_lo [(size_t)NPTS * 128];

// Pre-split weight blobs (hi plane, lo plane at +rows*stride), stride 72/136
#define WB_IN   0
#define WB_H0   4608
#define WB_H1   13824
#define WB_H2   23040
#define WB_OUT  32256
#define WB_TOT  41472
__device__ __align__(16) __half g_wS[WB_TOT];
__device__ __align__(16) __half g_wD[WB_TOT];
#define H1_IN   0
#define H1_H    18432
#define H1_OUT  27648
#define H1_TOT  45056
__device__ __align__(16) __half g_wH1[H1_TOT];
#define H2_IN   0
#define H2_H    18432
#define H2_TOT  27648
__device__ __align__(16) __half g_wH2[H2_TOT];

// ---------------------------------------------------------------------------
__device__ __forceinline__ void split2(float x, __half& h, __half& l) {
    h = __float2half_rn(x);
    l = __float2half_rn(x - __half2float(h));
}

__device__ __forceinline__ uint32_t pack2(__half a, __half b) {
    __half2 v = __halves2half2(a, b);
    return *reinterpret_cast<uint32_t*>(&v);
}

__device__ __forceinline__ void conv_w(__half* dst, const float* __restrict__ src,
                                       int K, int N, int ws, int t0, int nt)
{
    const int tot = K * N / 2;
    const int pl  = K * ws;
    const float2* s2 = (const float2*)src;
    for (int i = t0; i < tot; i += nt) {
        int r = (2 * i) / N, c = (2 * i) % N;
        float2 v = s2[i];
        __half hx, lx, hy, ly;
        split2(v.x, hx, lx);
        split2(v.y, hy, ly);
        *(__half2*)(dst + r * ws + c)      = __halves2half2(hx, hy);
        *(__half2*)(dst + r * ws + pl + c) = __halves2half2(lx, ly);
    }
}

__global__ void __launch_bounds__(256)
prep_weights(const float* __restrict__ ws_in, const float* __restrict__ ws_hid,
             const float* __restrict__ ws_out,
             const float* __restrict__ wd_in, const float* __restrict__ wd_hid,
             const float* __restrict__ wd_out,
             const float* __restrict__ w1_in, const float* __restrict__ w1_hid,
             const float* __restrict__ w1_out,
             const float* __restrict__ w2_in, const float* __restrict__ w2_hid)
{
    const int t0 = blockIdx.x * 256 + threadIdx.x;
    const int nt = gridDim.x * 256;
    conv_w(g_wS + WB_IN,  ws_in,         32, 64, 72, t0, nt);
    conv_w(g_wS + WB_H0,  ws_hid + 0,    64, 64, 72, t0, nt);
    conv_w(g_wS + WB_H1,  ws_hid + 4096, 64, 64, 72, t0, nt);
    conv_w(g_wS + WB_H2,  ws_hid + 8192, 64, 64, 72, t0, nt);
    conv_w(g_wS + WB_OUT, ws_out,        64, 64, 72, t0, nt);
    conv_w(g_wD + WB_IN,  wd_in,         32, 64, 72, t0, nt);
    conv_w(g_wD + WB_H0,  wd_hid + 0,    64, 64, 72, t0, nt);
    conv_w(g_wD + WB_H1,  wd_hid + 4096, 64, 64, 72, t0, nt);
    conv_w(g_wD + WB_H2,  wd_hid + 8192, 64, 64, 72, t0, nt);
    conv_w(g_wD + WB_OUT, wd_out,        64, 64, 72, t0, nt);
    conv_w(g_wH1 + H1_IN,  w1_in,  128, 64,  72,  t0, nt);
    conv_w(g_wH1 + H1_H,   w1_hid, 64,  64,  72,  t0, nt);
    conv_w(g_wH1 + H1_OUT, w1_out, 64,  128, 136, t0, nt);
    conv_w(g_wH2 + H2_IN,  w2_in,  128, 64,  72,  t0, nt);
    conv_w(g_wH2 + H2_H,   w2_hid, 64,  64,  72,  t0, nt);
}

// ---------------------------------------------------------------------------
// Hash-grid encode (one point per thread, all 16 levels) — at gather floor.
// ---------------------------------------------------------------------------
template <int D, int WHICH>
__global__ void __launch_bounds__(256)
encode_kernel(const float* __restrict__ x,
              const float* __restrict__ tptr,
              const float* __restrict__ table)
{
    const int n = blockIdx.x * 256 + threadIdx.x;

    float p[4];
    p[0] = x[3 * n + 0];
    p[1] = x[3 * n + 1];
    p[2] = x[3 * n + 2];
    if (D == 4) p[3] = __ldg(tptr);

    __half2 ehi[16], elo[16];

    #pragma unroll
    for (int l = 0; l < LVLS; l++) {
        const float res = c_res[l];
        uint32_t h[4][2];
        float    w[4][2];
        #pragma unroll
        for (int d = 0; d < D; d++) {
            const uint32_t pr = (d == 0) ? 1u
                              : (d == 1) ? 2654435761u
                              : (d == 2) ? 805459861u
                                         : 3674653429u;
            float pos = p[d] * res;
            float p0f = floorf(pos);
            float fr  = pos - p0f;
            uint32_t p0 = (uint32_t)p0f;
            h[d][0] = p0 * pr;
            h[d][1] = (p0 + 1u) * pr;
            w[d][0] = 1.f - fr;
            w[d][1] = fr;
        }

        const float2* tl = (const float2*)table + (size_t)l * TSIZE;
        float f0 = 0.f, f1 = 0.f;
        #pragma unroll
        for (int c = 0; c < (1 << D); c++) {
            uint32_t hh = h[0][c & 1] ^ h[1][(c >> 1) & 1] ^ h[2][(c >> 2) & 1];
            float    ww = w[0][c & 1] * w[1][(c >> 1) & 1] * w[2][(c >> 2) & 1];
            if (D == 4) {
                hh ^= h[3][(c >> 3) & 1];
                ww *= w[3][(c >> 3) & 1];
            }
            float2 f = __ldg(tl + (hh & TMASK));
            f0 = fmaf(ww, f.x, f0);
            f1 = fmaf(ww, f.y, f1);
        }
        __half h0, l0, h1, l1;
        split2(f0, h0, l0);
        split2(f1, h1, l1);
        ehi[l] = __halves2half2(h0, h1);
        elo[l] = __halves2half2(l0, l1);
    }

    __half* dh = (WHICH == 0 ? g_enc_s_hi : g_enc_d_hi) + (size_t)n * 32;
    __half* dl = (WHICH == 0 ? g_enc_s_lo : g_enc_d_lo) + (size_t)n * 32;
    #pragma unroll
    for (int i = 0; i < 4; i++) ((uint4*)dh)[i] = ((const uint4*)ehi)[i];
    #pragma unroll
    for (int i = 0; i < 4; i++) ((uint4*)dl)[i] = ((const uint4*)elo)[i];
}

// ---------------------------------------------------------------------------
// Tensor-core primitives
// ---------------------------------------------------------------------------
__device__ __forceinline__ uint32_t smem_u32(const void* p) {
    return (uint32_t)__cvta_generic_to_shared(p);
}

__device__ __forceinline__ void ldsm_x4_t(uint32_t& r0, uint32_t& r1,
                                          uint32_t& r2, uint32_t& r3, uint32_t a) {
    asm volatile("ldmatrix.sync.aligned.m8n8.x4.trans.shared.b16 {%0,%1,%2,%3}, [%4];"
                 : "=r"(r0), "=r"(r1), "=r"(r2), "=r"(r3) : "r"(a));
}

__device__ __forceinline__ void mma16816(float* c, const uint32_t* a,
                                         uint32_t b0, uint32_t b1) {
    asm volatile(
        "mma.sync.aligned.m16n8k16.row.col.f32.f16.f16.f32 "
        "{%0,%1,%2,%3}, {%4,%5,%6,%7}, {%8,%9}, {%0,%1,%2,%3};"
        : "+f"(c[0]), "+f"(c[1]), "+f"(c[2]), "+f"(c[3])
        : "r"(a[0]), "r"(a[1]), "r"(a[2]), "r"(a[3]), "r"(b0), "r"(b1));
}

// ---------------------------------------------------------------------------
// A-fragment direct global load: row-major matrix, row stride S halves.
// Fragment convention (lane g=l>>2, t2=l&3):
//   a0=(r0+g, c0+t2*2)  a1=(r0+g+8, same)  a2=(r0+g, c0+8+t2*2)  a3=(r0+g+8, +8)
// ---------------------------------------------------------------------------
__device__ __forceinline__ void ldg_afrag(const __half* __restrict__ base,
                                          size_t row0, int S, int col0,
                                          uint32_t* a)
{
    const int lane = threadIdx.x & 31;
    const int g = lane >> 2, t2 = lane & 3;
    const __half* p = base + (row0 + g) * (size_t)S + col0 + t2 * 2;
    a[0] = *(const uint32_t*)(p);
    a[1] = *(const uint32_t*)(p + 8 * (size_t)S);
    a[2] = *(const uint32_t*)(p + 8);
    a[3] = *(const uint32_t*)(p + 8 * (size_t)S + 8);
}

// ---------------------------------------------------------------------------
// Register-resident split-fp16 layers (16 rows/warp).
// Identity: C-fragments of n-tile pair {2j,2j+1} == A-fragments of k-tile j.
// ---------------------------------------------------------------------------
template <bool RELU>
__device__ __forceinline__ void convert_acc(float (*acc)[4],
                                            uint32_t (*Ah)[4],
                                            uint32_t (*Al)[4])
{
    #pragma unroll
    for (int j = 0; j < 4; j++)
        #pragma unroll
        for (int q = 0; q < 4; q++) {
            float v0 = acc[2 * j + (q >> 1)][(q & 1) * 2 + 0];
            float v1 = acc[2 * j + (q >> 1)][(q & 1) * 2 + 1];
            if (RELU) { v0 = fmaxf(v0, 0.f); v1 = fmaxf(v1, 0.f); }
            __half h0, l0, h1, l1;
            split2(v0, h0, l0);
            split2(v1, h1, l1);
            Ah[j][q] = pack2(h0, h1);
            Al[j][q] = pack2(l0, l1);
        }
}

// Layer with A in registers: K = KT*16 -> N = 64 (in-place A update)
template <int KT, bool RELU>
__device__ __forceinline__ void layer_reg(uint32_t (*Ah)[4], uint32_t (*Al)[4],
                                          const __half* W, int ws, int wpl)
{
    const int lane = threadIdx.x & 31;
    float acc[8][4];
    #pragma unroll
    for (int t = 0; t < 8; t++)
        #pragma unroll
        for (int j = 0; j < 4; j++) acc[t][j] = 0.f;

    #pragma unroll
    for (int kk = 0; kk < KT; kk++) {
        #pragma unroll
        for (int nb = 0; nb < 4; nb++) {
            const __half* wp = W + (kk * 16 + (lane & 7) + ((lane >> 3) & 1) * 8) * ws
                             + nb * 16 + ((lane >> 4) << 3);
            uint32_t bh0, bh1, bh2, bh3, bl0, bl1, bl2, bl3;
            ldsm_x4_t(bh0, bh1, bh2, bh3, smem_u32(wp));
            ldsm_x4_t(bl0, bl1, bl2, bl3, smem_u32(wp + wpl));
            mma16816(acc[2 * nb + 0], Ah[kk], bh0, bh1);
            mma16816(acc[2 * nb + 0], Ah[kk], bl0, bl1);
            mma16816(acc[2 * nb + 0], Al[kk], bh0, bh1);
            mma16816(acc[2 * nb + 1], Ah[kk], bh2, bh3);
            mma16816(acc[2 * nb + 1], Ah[kk], bl2, bl3);
            mma16816(acc[2 * nb + 1], Al[kk], bh2, bh3);
        }
    }
    convert_acc<RELU>(acc, Ah, Al);
}

// Layer with A fragments loaded directly from gmem (hi/lo planes).
template <int KT, bool RELU>
__device__ __forceinline__ void layer_gmemA(const __half* __restrict__ bh,
                                            const __half* __restrict__ bl,
                                            size_t row0, int S,
                                            const __half* W, int ws, int wpl,
                                            uint32_t (*Ah)[4], uint32_t (*Al)[4])
{
    const int lane = threadIdx.x & 31;
    float acc[8][4];
    #pragma unroll
    for (int t = 0; t < 8; t++)
        #pragma unroll
        for (int j = 0; j < 4; j++) acc[t][j] = 0.f;

    #pragma unroll
    for (int kk = 0; kk < KT; kk++) {
        uint32_t th[4], tl[4];
        ldg_afrag(bh, row0, S, kk * 16, th);
        ldg_afrag(bl, row0, S, kk * 16, tl);
        #pragma unroll
        for (int nb = 0; nb < 4; nb++) {
            const __half* wp = W + (kk * 16 + (lane & 7) + ((lane >> 3) & 1) * 8) * ws
                             + nb * 16 + ((lane >> 4) << 3);
            uint32_t bh0, bh1, bh2, bh3, bl0, bl1, bl2, bl3;
            ldsm_x4_t(bh0, bh1, bh2, bh3, smem_u32(wp));
            ldsm_x4_t(bl0, bl1, bl2, bl3, smem_u32(wp + wpl));
            mma16816(acc[2 * nb + 0], th, bh0, bh1);
            mma16816(acc[2 * nb + 0], th, bl0, bl1);
            mma16816(acc[2 * nb + 0], tl, bh0, bh1);
            mma16816(acc[2 * nb + 1], th, bh2, bh3);
            mma16816(acc[2 * nb + 1], th, bl2, bl3);
            mma16816(acc[2 * nb + 1], tl, bh2, bh3);
        }
    }
    convert_acc<RELU>(acc, Ah, Al);
}

// Store register A-fragments (hi/lo) to gmem row-major (stride S halves).
__device__ __forceinline__ void stg_afrags(uint32_t (*Ah)[4], uint32_t (*Al)[4],
                                           __half* __restrict__ dh,
                                           __half* __restrict__ dl,
                                           size_t row0, int S, int col0)
{
    const int lane = threadIdx.x & 31;
    const int g = lane >> 2, t2 = lane & 3;
    #pragma unroll
    for (int j = 0; j < 4; j++) {
        const int c = col0 + j * 16 + t2 * 2;
        size_t o0 = (row0 + g) * (size_t)S + c;
        size_t o1 = (row0 + g + 8) * (size_t)S + c;
        *(uint32_t*)(dh + o0)     = Ah[j][0];
        *(uint32_t*)(dh + o1)     = Ah[j][1];
        *(uint32_t*)(dh + o0 + 8) = Ah[j][2];
        *(uint32_t*)(dh + o1 + 8) = Ah[j][3];
        *(uint32_t*)(dl + o0)     = Al[j][0];
        *(uint32_t*)(dl + o1)     = Al[j][1];
        *(uint32_t*)(dl + o0 + 8) = Al[j][2];
        *(uint32_t*)(dl + o1 + 8) = Al[j][3];
    }
}

// ---------------------------------------------------------------------------
// Branch MLP: 512 threads = 16 warps x 16 pts = 256 pts/block.
// smem = weight blob only; A-frags LDG'd from g_enc; output direct to g_feat.
// ---------------------------------------------------------------------------
#define MLP64_SMEM (WB_TOT * 2)

template <int WHICH>
__global__ void __launch_bounds__(512, 1)
mlp64_tc()
{
    extern __shared__ __align__(16) __half sm[];
    const int tid = threadIdx.x;
    const size_t blockbase = (size_t)blockIdx.x * 256;

    {
        const uint4* src = (const uint4*)(WHICH == 0 ? g_wS : g_wD);
        uint4* dst = (uint4*)sm;
        #pragma unroll 4
        for (int i = tid; i < WB_TOT / 8; i += 512) dst[i] = src[i];
    }
    __syncthreads();

    const int w = tid >> 5;
    const size_t row0 = blockbase + w * 16;
    const __half* W = sm;

    uint32_t Ah[4][4], Al[4][4];

    layer_gmemA<2, true>(WHICH == 0 ? g_enc_s_hi : g_enc_d_hi,
                         WHICH == 0 ? g_enc_s_lo : g_enc_d_lo,
                         row0, 32, W + WB_IN, 72, 32 * 72, Ah, Al);
    layer_reg<4, true >(Ah, Al, W + WB_H0,  72, 64 * 72);
    layer_reg<4, true >(Ah, Al, W + WB_H1,  72, 64 * 72);
    layer_reg<4, true >(Ah, Al, W + WB_H2,  72, 64 * 72);
    layer_reg<4, false>(Ah, Al, W + WB_OUT, 72, 64 * 72);

    stg_afrags(Ah, Al, g_feat_hi, g_feat_lo, row0, 128, WHICH * 64);
}

// ---------------------------------------------------------------------------
// head1: feat128 -> 64 -> 64 -> 128 + blend, written back in-place to g_feat.
// 512 threads = 16 warps x 16 pts = 256 pts/block.  smem = H1 weights only.
// ---------------------------------------------------------------------------
#define HEAD1_SMEM (H1_TOT * 2)

__global__ void __launch_bounds__(512, 1)
head1_tc(const float* __restrict__ alpha_p)
{
    extern __shared__ __align__(16) __half sm[];
    const int tid = threadIdx.x;
    const size_t blockbase = (size_t)blockIdx.x * 256;

    {
        const uint4* src = (const uint4*)g_wH1;
        uint4* dst = (uint4*)sm;
        #pragma unroll 4
        for (int i = tid; i < H1_TOT / 8; i += 512) dst[i] = src[i];
    }
    __syncthreads();

    const int w = tid >> 5;
    const int lane = tid & 31;
    const int g = lane >> 2, t2 = lane & 3;
    const size_t row0 = blockbase + w * 16;

    const float alpha = __ldg(alpha_p);
    const float beta  = 1.f - alpha;

    uint32_t Ah[4][4], Al[4][4];

    layer_gmemA<8, true>(g_feat_hi, g_feat_lo, row0, 128,
                         sm + H1_IN, 72, 128 * 72, Ah, Al);
    layer_reg<4, true>(Ah, Al, sm + H1_H, 72, 64 * 72);

    // w1_out (64 -> 128) in two 64-col halves, fused blend, in-place to g_feat
    #pragma unroll
    for (int half = 0; half < 2; half++) {
        const int noff = half * 64;
        float acc[8][4];
        #pragma unroll
        for (int t = 0; t < 8; t++)
            #pragma unroll
            for (int j = 0; j < 4; j++) acc[t][j] = 0.f;

        #pragma unroll
        for (int kk = 0; kk < 4; kk++) {
            #pragma unroll
            for (int nb = 0; nb < 4; nb++) {
                const __half* wp = sm + H1_OUT
                                 + (kk * 16 + (lane & 7) + ((lane >> 3) & 1) * 8) * 136
                                 + noff + nb * 16 + ((lane >> 4) << 3);
                uint32_t bh0, bh1, bh2, bh3, bl0, bl1, bl2, bl3;
                ldsm_x4_t(bh0, bh1, bh2, bh3, smem_u32(wp));
                ldsm_x4_t(bl0, bl1, bl2, bl3, smem_u32(wp + 64 * 136));
                mma16816(acc[2 * nb + 0], Ah[kk], bh0, bh1);
                mma16816(acc[2 * nb + 0], Ah[kk], bl0, bl1);
                mma16816(acc[2 * nb + 0], Al[kk], bh0, bh1);
                mma16816(acc[2 * nb + 1], Ah[kk], bh2, bh3);
                mma16816(acc[2 * nb + 1], Ah[kk], bl2, bl3);
                mma16816(acc[2 * nb + 1], Al[kk], bh2, bh3);
            }
        }

        // blend with original F (LDG) and write back split planes in place
        #pragma unroll
        for (int j = 0; j < 4; j++)
            #pragma unroll
            for (int q = 0; q < 4; q++) {
                float v0 = acc[2 * j + (q >> 1)][(q & 1) * 2 + 0];
                float v1 = acc[2 * j + (q >> 1)][(q & 1) * 2 + 1];
                const size_t r = row0 + g + ((q & 1) ? 8 : 0);
                const int    c = noff + j * 16 + ((q >> 1) ? 8 : 0) + t2 * 2;
                const size_t off = r * 128 + c;
                uint32_t fh = *(const uint32_t*)(g_feat_hi + off);
                uint32_t fl = *(const uint32_t*)(g_feat_lo + off);
                float2 vh = __half22float2(*reinterpret_cast<__half2*>(&fh));
                float2 vl = __half22float2(*reinterpret_cast<__half2*>(&fl));
                v0 = v0 * alpha + beta * (vh.x + vl.x);
                v1 = v1 * alpha + beta * (vh.y + vl.y);
                __half h0, l0, h1, l1;
                split2(v0, h0, l0);
                split2(v1, h1, l1);
                *(uint32_t*)(g_feat_hi + off) = pack2(h0, h1);
                *(uint32_t*)(g_feat_lo + off) = pack2(l0, l1);
            }
    }
}

// ---------------------------------------------------------------------------
// head2: blended feat128 -> 64 -> 64 -> 1.
// 512 threads = 16 warps x 16 pts = 256 pts/block.  smem = H2 weights + w2_out.
// ---------------------------------------------------------------------------
#define HEAD2_SMEM ((H2_TOT + 128) * 2)

__global__ void __launch_bounds__(512, 1)
head2_tc(const float* __restrict__ w2_out, float* __restrict__ out)
{
    extern __shared__ __align__(16) __half sm[];
    const int tid = threadIdx.x;
    const size_t blockbase = (size_t)blockIdx.x * 256;
    float* wo = (float*)(sm + H2_TOT);

    {
        const uint4* src = (const uint4*)g_wH2;
        uint4* dst = (uint4*)sm;
        #pragma unroll 4
        for (int i = tid; i < H2_TOT / 8; i += 512) dst[i] = src[i];
        for (int i = tid; i < 64; i += 512) wo[i] = w2_out[i];
    }
    __syncthreads();

    const int w = tid >> 5;
    const int lane = tid & 31;
    const size_t row0 = blockbase + w * 16;

    uint32_t Ah[4][4], Al[4][4];

    layer_gmemA<8, true>(g_feat_hi, g_feat_lo, row0, 128,
                         sm + H2_IN, 72, 128 * 72, Ah, Al);
    layer_reg<4, true>(Ah, Al, sm + H2_H, 72, 64 * 72);

    // final 64 -> 1 from register fragments (fp32)
    const int g = lane >> 2, t2 = lane & 3;
    {
        float sg = 0.f, sg8 = 0.f;
        #pragma unroll
        for (int j = 0; j < 4; j++)
            #pragma unroll
            for (int q = 0; q < 4; q++) {
                __half2 hv = *reinterpret_cast<__half2*>(&Ah[j][q]);
                __half2 lv = *reinterpret_cast<__half2*>(&Al[j][q]);
                float2 vh = __half22float2(hv);
                float2 vl = __half22float2(lv);
                int c = j * 16 + ((q >> 1) << 3) + t2 * 2;
                float d = fmaf(vh.x + vl.x, wo[c], (vh.y + vl.y) * wo[c + 1]);
                if ((q & 1) == 0) sg += d; else sg8 += d;
            }
        sg  += __shfl_xor_sync(0xffffffffu, sg, 1);
        sg  += __shfl_xor_sync(0xffffffffu, sg, 2);
        sg8 += __shfl_xor_sync(0xffffffffu, sg8, 1);
        sg8 += __shfl_xor_sync(0xffffffffu, sg8, 2);
        if (t2 == 0) {
            out[row0 + g]     = sg;
            out[row0 + g + 8] = sg8;
        }
    }
}

// ---------------------------------------------------------------------------
// Launch (strictly serial — R5 showed L1-bound kernels must not overlap)
// ---------------------------------------------------------------------------
extern "C" void kernel_launch(void* const* d_in, const int* in_sizes, int n_in,
                              void* d_out, int out_size)
{
    const float* x       = (const float*)d_in[0];
    const float* t       = (const float*)d_in[1];
    const float* alpha   = (const float*)d_in[2];
    const float* table_s = (const float*)d_in[3];
    const float* ws_in   = (const float*)d_in[4];
    const float* ws_hid  = (const float*)d_in[5];
    const float* ws_out  = (const float*)d_in[6];
    const float* table_d = (const float*)d_in[7];
    const float* wd_in   = (const float*)d_in[8];
    const float* wd_hid  = (const float*)d_in[9];
    const float* wd_out  = (const float*)d_in[10];
    const float* w1_in   = (const float*)d_in[11];
    const float* w1_hid  = (const float*)d_in[12];
    const float* w1_out  = (const float*)d_in[13];
    const float* w2_in   = (const float*)d_in[14];
    const float* w2_hid  = (const float*)d_in[15];
    const float* w2_out  = (const float*)d_in[16];
    float* out = (float*)d_out;

    cudaFuncSetAttribute(mlp64_tc<0>, cudaFuncAttributeMaxDynamicSharedMemorySize, MLP64_SMEM);
    cudaFuncSetAttribute(mlp64_tc<1>, cudaFuncAttributeMaxDynamicSharedMemorySize, MLP64_SMEM);
    cudaFuncSetAttribute(head1_tc,    cudaFuncAttributeMaxDynamicSharedMemorySize, HEAD1_SMEM);
    cudaFuncSetAttribute(head2_tc,    cudaFuncAttributeMaxDynamicSharedMemorySize, HEAD2_SMEM);

    const int nblkENC = NPTS / 256;
    const int nblkMLP = NPTS / 256;

    prep_weights<<<64, 256>>>(ws_in, ws_hid, ws_out, wd_in, wd_hid, wd_out,
                              w1_in, w1_hid, w1_out, w2_in, w2_hid);

    encode_kernel<3, 0><<<nblkENC, 256>>>(x, nullptr, table_s);
    encode_kernel<4, 1><<<nblkENC, 256>>>(x, t, table_d);

    mlp64_tc<0><<<nblkMLP, 512, MLP64_SMEM>>>();
    mlp64_tc<1><<<nblkMLP, 512, MLP64_SMEM>>>();

    head1_tc<<<nblkMLP, 512, HEAD1_SMEM>>>(alpha);
    head2_tc<<<nblkMLP, 512, HEAD2_SMEM>>>(w2_out, out);
}

// round 10
// speedup vs baseline: 1.1324x; 1.1324x over previous
#include <cuda_runtime.h>
#include <cuda_fp16.h>
#include <cstdint>

// ---------------------------------------------------------------------------
// Problem constants
// ---------------------------------------------------------------------------
#define NPTS   524288
#define LVLS   16
#define TSIZE  524288u
#define TMASK  (TSIZE - 1u)

__constant__ float c_res[LVLS] = {
    16.f, 24.f, 36.f, 54.f, 81.f, 121.f, 182.f, 273.f,
    410.f, 615.f, 922.f, 1383.f, 2075.f, 3113.f, 4670.f, 7006.f
};

// ---------------------------------------------------------------------------
// Scratch (device globals; no runtime allocation)
// ---------------------------------------------------------------------------
__device__ __align__(16) __half g_enc_s_hi[(size_t)NPTS * 32];
__device__ __align__(16) __half g_enc_s_lo[(size_t)NPTS * 32];
__device__ __align__(16) __half g_enc_d_hi[(size_t)NPTS * 32];
__device__ __align__(16) __half g_enc_d_lo[(size_t)NPTS * 32];
__device__ __align__(16) __half g_feat_hi [(size_t)NPTS * 128];
__device__ __align__(16) __half g_feat_lo [(size_t)NPTS * 128];

// Pre-split weight blobs (hi plane, lo plane at +rows*stride), stride 72/136
#define WB_IN   0
#define WB_H0   4608
#define WB_H1   13824
#define WB_H2   23040
#define WB_OUT  32256
#define WB_TOT  41472
__device__ __align__(16) __half g_wS[WB_TOT];
__device__ __align__(16) __half g_wD[WB_TOT];
#define H1_IN   0
#define H1_H    18432
#define H1_OUT  27648
#define H1_TOT  45056
__device__ __align__(16) __half g_wH1[H1_TOT];
#define H2_IN   0
#define H2_H    18432
#define H2_TOT  27648
__device__ __align__(16) __half g_wH2[H2_TOT];

// ---------------------------------------------------------------------------
__device__ __forceinline__ void split2(float x, __half& h, __half& l) {
    h = __float2half_rn(x);
    l = __float2half_rn(x - __half2float(h));
}

__device__ __forceinline__ uint32_t pack2(__half a, __half b) {
    __half2 v = __halves2half2(a, b);
    return *reinterpret_cast<uint32_t*>(&v);
}

__device__ __forceinline__ void conv_w(__half* dst, const float* __restrict__ src,
                                       int K, int N, int ws, int t0, int nt)
{
    const int tot = K * N / 2;
    const int pl  = K * ws;
    const float2* s2 = (const float2*)src;
    for (int i = t0; i < tot; i += nt) {
        int r = (2 * i) / N, c = (2 * i) % N;
        float2 v = s2[i];
        __half hx, lx, hy, ly;
        split2(v.x, hx, lx);
        split2(v.y, hy, ly);
        *(__half2*)(dst + r * ws + c)      = __halves2half2(hx, hy);
        *(__half2*)(dst + r * ws + pl + c) = __halves2half2(lx, ly);
    }
}

__global__ void __launch_bounds__(256)
prep_weights(const float* __restrict__ ws_in, const float* __restrict__ ws_hid,
             const float* __restrict__ ws_out,
             const float* __restrict__ wd_in, const float* __restrict__ wd_hid,
             const float* __restrict__ wd_out,
             const float* __restrict__ w1_in, const float* __restrict__ w1_hid,
             const float* __restrict__ w1_out,
             const float* __restrict__ w2_in, const float* __restrict__ w2_hid)
{
    const int t0 = blockIdx.x * 256 + threadIdx.x;
    const int nt = gridDim.x * 256;
    conv_w(g_wS + WB_IN,  ws_in,         32, 64, 72, t0, nt);
    conv_w(g_wS + WB_H0,  ws_hid + 0,    64, 64, 72, t0, nt);
    conv_w(g_wS + WB_H1,  ws_hid + 4096, 64, 64, 72, t0, nt);
    conv_w(g_wS + WB_H2,  ws_hid + 8192, 64, 64, 72, t0, nt);
    conv_w(g_wS + WB_OUT, ws_out,        64, 64, 72, t0, nt);
    conv_w(g_wD + WB_IN,  wd_in,         32, 64, 72, t0, nt);
    conv_w(g_wD + WB_H0,  wd_hid + 0,    64, 64, 72, t0, nt);
    conv_w(g_wD + WB_H1,  wd_hid + 4096, 64, 64, 72, t0, nt);
    conv_w(g_wD + WB_H2,  wd_hid + 8192, 64, 64, 72, t0, nt);
    conv_w(g_wD + WB_OUT, wd_out,        64, 64, 72, t0, nt);
    conv_w(g_wH1 + H1_IN,  w1_in,  128, 64,  72,  t0, nt);
    conv_w(g_wH1 + H1_H,   w1_hid, 64,  64,  72,  t0, nt);
    conv_w(g_wH1 + H1_OUT, w1_out, 64,  128, 136, t0, nt);
    conv_w(g_wH2 + H2_IN,  w2_in,  128, 64,  72,  t0, nt);
    conv_w(g_wH2 + H2_H,   w2_hid, 64,  64,  72,  t0, nt);
}

// ---------------------------------------------------------------------------
// Hash-grid encode (one point per thread, all 16 levels) — at gather floor.
// ---------------------------------------------------------------------------
template <int D, int WHICH>
__global__ void __launch_bounds__(256)
encode_kernel(const float* __restrict__ x,
              const float* __restrict__ tptr,
              const float* __restrict__ table)
{
    const int n = blockIdx.x * 256 + threadIdx.x;

    float p[4];
    p[0] = x[3 * n + 0];
    p[1] = x[3 * n + 1];
    p[2] = x[3 * n + 2];
    if (D == 4) p[3] = __ldg(tptr);

    __half2 ehi[16], elo[16];

    #pragma unroll
    for (int l = 0; l < LVLS; l++) {
        const float res = c_res[l];
        uint32_t h[4][2];
        float    w[4][2];
        #pragma unroll
        for (int d = 0; d < D; d++) {
            const uint32_t pr = (d == 0) ? 1u
                              : (d == 1) ? 2654435761u
                              : (d == 2) ? 805459861u
                                         : 3674653429u;
            float pos = p[d] * res;
            float p0f = floorf(pos);
            float fr  = pos - p0f;
            uint32_t p0 = (uint32_t)p0f;
            h[d][0] = p0 * pr;
            h[d][1] = (p0 + 1u) * pr;
            w[d][0] = 1.f - fr;
            w[d][1] = fr;
        }

        const float2* tl = (const float2*)table + (size_t)l * TSIZE;
        float f0 = 0.f, f1 = 0.f;
        #pragma unroll
        for (int c = 0; c < (1 << D); c++) {
            uint32_t hh = h[0][c & 1] ^ h[1][(c >> 1) & 1] ^ h[2][(c >> 2) & 1];
            float    ww = w[0][c & 1] * w[1][(c >> 1) & 1] * w[2][(c >> 2) & 1];
            if (D == 4) {
                hh ^= h[3][(c >> 3) & 1];
                ww *= w[3][(c >> 3) & 1];
            }
            float2 f = __ldg(tl + (hh & TMASK));
            f0 = fmaf(ww, f.x, f0);
            f1 = fmaf(ww, f.y, f1);
        }
        __half h0, l0, h1, l1;
        split2(f0, h0, l0);
        split2(f1, h1, l1);
        ehi[l] = __halves2half2(h0, h1);
        elo[l] = __halves2half2(l0, l1);
    }

    __half* dh = (WHICH == 0 ? g_enc_s_hi : g_enc_d_hi) + (size_t)n * 32;
    __half* dl = (WHICH == 0 ? g_enc_s_lo : g_enc_d_lo) + (size_t)n * 32;
    #pragma unroll
    for (int i = 0; i < 4; i++) ((uint4*)dh)[i] = ((const uint4*)ehi)[i];
    #pragma unroll
    for (int i = 0; i < 4; i++) ((uint4*)dl)[i] = ((const uint4*)elo)[i];
}

// ---------------------------------------------------------------------------
// Tensor-core primitives
// ---------------------------------------------------------------------------
__device__ __forceinline__ uint32_t smem_u32(const void* p) {
    return (uint32_t)__cvta_generic_to_shared(p);
}

__device__ __forceinline__ void ldsm_x4_t(uint32_t& r0, uint32_t& r1,
                                          uint32_t& r2, uint32_t& r3, uint32_t a) {
    asm volatile("ldmatrix.sync.aligned.m8n8.x4.trans.shared.b16 {%0,%1,%2,%3}, [%4];"
                 : "=r"(r0), "=r"(r1), "=r"(r2), "=r"(r3) : "r"(a));
}

__device__ __forceinline__ void mma16816(float* c, const uint32_t* a,
                                         uint32_t b0, uint32_t b1) {
    asm volatile(
        "mma.sync.aligned.m16n8k16.row.col.f32.f16.f16.f32 "
        "{%0,%1,%2,%3}, {%4,%5,%6,%7}, {%8,%9}, {%0,%1,%2,%3};"
        : "+f"(c[0]), "+f"(c[1]), "+f"(c[2]), "+f"(c[3])
        : "r"(a[0]), "r"(a[1]), "r"(a[2]), "r"(a[3]), "r"(b0), "r"(b1));
}

// One k-tile of split-MMA: A (hi/lo, 4+4 regs) x W rows [krow..krow+16) -> acc[8][4]
__device__ __forceinline__ void ktile_mma(const __half* W, int ws, int wpl, int krow,
                                          const uint32_t* ah, const uint32_t* al,
                                          float (*acc)[4])
{
    const int lane = threadIdx.x & 31;
    #pragma unroll
    for (int nb = 0; nb < 4; nb++) {
        const __half* wp = W + (krow + (lane & 7) + ((lane >> 3) & 1) * 8) * ws
                         + nb * 16 + ((lane >> 4) << 3);
        uint32_t bh0, bh1, bh2, bh3, bl0, bl1, bl2, bl3;
        ldsm_x4_t(bh0, bh1, bh2, bh3, smem_u32(wp));
        ldsm_x4_t(bl0, bl1, bl2, bl3, smem_u32(wp + wpl));
        mma16816(acc[2 * nb + 0], ah, bh0, bh1);
        mma16816(acc[2 * nb + 0], ah, bl0, bl1);
        mma16816(acc[2 * nb + 0], al, bh0, bh1);
        mma16816(acc[2 * nb + 1], ah, bh2, bh3);
        mma16816(acc[2 * nb + 1], ah, bl2, bl3);
        mma16816(acc[2 * nb + 1], al, bh2, bh3);
    }
}

// ---------------------------------------------------------------------------
// A-fragment direct global load: row-major matrix, row stride S halves.
// ---------------------------------------------------------------------------
__device__ __forceinline__ void ldg_afrag(const __half* __restrict__ base,
                                          size_t row0, int S, int col0,
                                          uint32_t* a)
{
    const int lane = threadIdx.x & 31;
    const int g = lane >> 2, t2 = lane & 3;
    const __half* p = base + (row0 + g) * (size_t)S + col0 + t2 * 2;
    a[0] = *(const uint32_t*)(p);
    a[1] = *(const uint32_t*)(p + 8 * (size_t)S);
    a[2] = *(const uint32_t*)(p + 8);
    a[3] = *(const uint32_t*)(p + 8 * (size_t)S + 8);
}

// ---------------------------------------------------------------------------
// acc -> A-fragment conversion (identity: n-pair {2j,2j+1} == k-tile j)
// ---------------------------------------------------------------------------
template <bool RELU>
__device__ __forceinline__ void convert_acc(float (*acc)[4],
                                            uint32_t (*Ah)[4],
                                            uint32_t (*Al)[4])
{
    #pragma unroll
    for (int j = 0; j < 4; j++)
        #pragma unroll
        for (int q = 0; q < 4; q++) {
            float v0 = acc[2 * j + (q >> 1)][(q & 1) * 2 + 0];
            float v1 = acc[2 * j + (q >> 1)][(q & 1) * 2 + 1];
            if (RELU) { v0 = fmaxf(v0, 0.f); v1 = fmaxf(v1, 0.f); }
            __half h0, l0, h1, l1;
            split2(v0, h0, l0);
            split2(v1, h1, l1);
            Ah[j][q] = pack2(h0, h1);
            Al[j][q] = pack2(l0, l1);
        }
}

// Layer with A in registers: K = KT*16 -> N = 64 (in-place A update)
template <int KT, bool RELU>
__device__ __forceinline__ void layer_reg(uint32_t (*Ah)[4], uint32_t (*Al)[4],
                                          const __half* W, int ws, int wpl)
{
    float acc[8][4];
    #pragma unroll
    for (int t = 0; t < 8; t++)
        #pragma unroll
        for (int j = 0; j < 4; j++) acc[t][j] = 0.f;
    #pragma unroll
    for (int kk = 0; kk < KT; kk++)
        ktile_mma(W, ws, wpl, kk * 16, Ah[kk], Al[kk], acc);
    convert_acc<RELU>(acc, Ah, Al);
}

// Layer with A fragments loaded directly from gmem (hi/lo planes).
template <int KT, bool RELU>
__device__ __forceinline__ void layer_gmemA(const __half* __restrict__ bh,
                                            const __half* __restrict__ bl,
                                            size_t row0, int S,
                                            const __half* W, int ws, int wpl,
                                            uint32_t (*Ah)[4], uint32_t (*Al)[4])
{
    float acc[8][4];
    #pragma unroll
    for (int t = 0; t < 8; t++)
        #pragma unroll
        for (int j = 0; j < 4; j++) acc[t][j] = 0.f;
    #pragma unroll
    for (int kk = 0; kk < KT; kk++) {
        uint32_t th[4], tl[4];
        ldg_afrag(bh, row0, S, kk * 16, th);
        ldg_afrag(bl, row0, S, kk * 16, tl);
        ktile_mma(W, ws, wpl, kk * 16, th, tl, acc);
    }
    convert_acc<RELU>(acc, Ah, Al);
}

// Store register A-fragments (hi/lo) to gmem row-major (stride S halves).
__device__ __forceinline__ void stg_afrags(uint32_t (*Ah)[4], uint32_t (*Al)[4],
                                           __half* __restrict__ dh,
                                           __half* __restrict__ dl,
                                           size_t row0, int S, int col0)
{
    const int lane = threadIdx.x & 31;
    const int g = lane >> 2, t2 = lane & 3;
    #pragma unroll
    for (int j = 0; j < 4; j++) {
        const int c = col0 + j * 16 + t2 * 2;
        size_t o0 = (row0 + g) * (size_t)S + c;
        size_t o1 = (row0 + g + 8) * (size_t)S + c;
        *(uint32_t*)(dh + o0)     = Ah[j][0];
        *(uint32_t*)(dh + o1)     = Ah[j][1];
        *(uint32_t*)(dh + o0 + 8) = Ah[j][2];
        *(uint32_t*)(dh + o1 + 8) = Ah[j][3];
        *(uint32_t*)(dl + o0)     = Al[j][0];
        *(uint32_t*)(dl + o1)     = Al[j][1];
        *(uint32_t*)(dl + o0 + 8) = Al[j][2];
        *(uint32_t*)(dl + o1 + 8) = Al[j][3];
    }
}

// ---------------------------------------------------------------------------
// Branch MLP: 512 threads = 16 warps x 16 pts = 256 pts/block.
// smem = weight blob only; A-frags LDG'd from g_enc; output direct to g_feat.
// ---------------------------------------------------------------------------
#define MLP64_SMEM (WB_TOT * 2)

template <int WHICH>
__global__ void __launch_bounds__(512, 1)
mlp64_tc()
{
    extern __shared__ __align__(16) __half sm[];
    const int tid = threadIdx.x;
    const size_t blockbase = (size_t)blockIdx.x * 256;

    {
        const uint4* src = (const uint4*)(WHICH == 0 ? g_wS : g_wD);
        uint4* dst = (uint4*)sm;
        #pragma unroll 4
        for (int i = tid; i < WB_TOT / 8; i += 512) dst[i] = src[i];
    }
    __syncthreads();

    const int w = tid >> 5;
    const size_t row0 = blockbase + w * 16;
    const __half* W = sm;

    uint32_t Ah[4][4], Al[4][4];

    layer_gmemA<2, true>(WHICH == 0 ? g_enc_s_hi : g_enc_d_hi,
                         WHICH == 0 ? g_enc_s_lo : g_enc_d_lo,
                         row0, 32, W + WB_IN, 72, 32 * 72, Ah, Al);
    layer_reg<4, true >(Ah, Al, W + WB_H0,  72, 64 * 72);
    layer_reg<4, true >(Ah, Al, W + WB_H1,  72, 64 * 72);
    layer_reg<4, true >(Ah, Al, W + WB_H2,  72, 64 * 72);
    layer_reg<4, false>(Ah, Al, W + WB_OUT, 72, 64 * 72);

    stg_afrags(Ah, Al, g_feat_hi, g_feat_lo, row0, 128, WHICH * 64);
}

// ---------------------------------------------------------------------------
// Merged head: feat128 -> 64 -> 64 -> 128 (+blend, registers only) -> 64 -> 64 -> 1
// 512 threads = 16 warps x 16 pts = 256 pts/block.
// Blended features never touch gmem: w1_out halves are converted to fragments
// and immediately folded into mlp2-in's K accumulation.
// ---------------------------------------------------------------------------
#define HH2    H1_TOT
#define HHO    (HH2 + H2_TOT)
#define HEAD_SMEM ((HHO + 128) * 2)

__global__ void __launch_bounds__(512, 1)
head_tc(const float* __restrict__ alpha_p,
        const float* __restrict__ w2_out, float* __restrict__ out)
{
    extern __shared__ __align__(16) __half sm[];
    const int tid = threadIdx.x;
    const size_t blockbase = (size_t)blockIdx.x * 256;
    float* wo = (float*)(sm + HHO);

    {
        const uint4* s1 = (const uint4*)g_wH1;
        uint4* d1 = (uint4*)sm;
        #pragma unroll 4
        for (int i = tid; i < H1_TOT / 8; i += 512) d1[i] = s1[i];
        const uint4* s2 = (const uint4*)g_wH2;
        uint4* d2 = (uint4*)(sm + HH2);
        #pragma unroll 4
        for (int i = tid; i < H2_TOT / 8; i += 512) d2[i] = s2[i];
        for (int i = tid; i < 64; i += 512) wo[i] = w2_out[i];
    }
    __syncthreads();

    const int w = tid >> 5;
    const int lane = tid & 31;
    const int g = lane >> 2, t2 = lane & 3;
    const size_t row0 = blockbase + w * 16;

    const float alpha = __ldg(alpha_p);
    const float beta  = 1.f - alpha;

    // mlp1: 128 -> 64 -> 64
    uint32_t A1h[4][4], A1l[4][4];
    layer_gmemA<8, true>(g_feat_hi, g_feat_lo, row0, 128,
                         sm + H1_IN, 72, 128 * 72, A1h, A1l);
    layer_reg<4, true>(A1h, A1l, sm + H1_H, 72, 64 * 72);

    // w1_out (64 -> 128) per 64-col half: blend vs original F (fp32), convert
    // to fragments, and immediately accumulate into mlp2-in (K = 128).
    float acc2[8][4];
    #pragma unroll
    for (int t = 0; t < 8; t++)
        #pragma unroll
        for (int j = 0; j < 4; j++) acc2[t][j] = 0.f;

    #pragma unroll
    for (int half = 0; half < 2; half++) {
        const int noff = half * 64;
        float accO[8][4];
        #pragma unroll
        for (int t = 0; t < 8; t++)
            #pragma unroll
            for (int j = 0; j < 4; j++) accO[t][j] = 0.f;

        #pragma unroll
        for (int kk = 0; kk < 4; kk++) {
            const __half* Wb = sm + H1_OUT + noff;
            // stride-136 W with 64-row lo plane
            const __half* wrow = Wb + (kk * 16 + (lane & 7) + ((lane >> 3) & 1) * 8) * 136
                               + ((lane >> 4) << 3);
            #pragma unroll
            for (int nb = 0; nb < 4; nb++) {
                uint32_t bh0, bh1, bh2, bh3, bl0, bl1, bl2, bl3;
                ldsm_x4_t(bh0, bh1, bh2, bh3, smem_u32(wrow + nb * 16));
                ldsm_x4_t(bl0, bl1, bl2, bl3, smem_u32(wrow + nb * 16 + 64 * 136));
                mma16816(accO[2 * nb + 0], A1h[kk], bh0, bh1);
                mma16816(accO[2 * nb + 0], A1h[kk], bl0, bl1);
                mma16816(accO[2 * nb + 0], A1l[kk], bh0, bh1);
                mma16816(accO[2 * nb + 1], A1h[kk], bh2, bh3);
                mma16816(accO[2 * nb + 1], A1h[kk], bl2, bl3);
                mma16816(accO[2 * nb + 1], A1l[kk], bh2, bh3);
            }
        }

        // blend with original F (LDG, L2-hot) -> fragment planes for this half
        uint32_t Fh[4][4], Fl[4][4];
        #pragma unroll
        for (int j = 0; j < 4; j++)
            #pragma unroll
            for (int q = 0; q < 4; q++) {
                float v0 = accO[2 * j + (q >> 1)][(q & 1) * 2 + 0];
                float v1 = accO[2 * j + (q >> 1)][(q & 1) * 2 + 1];
                const size_t r = row0 + g + ((q & 1) ? 8 : 0);
                const int    c = noff + j * 16 + ((q >> 1) ? 8 : 0) + t2 * 2;
                const size_t off = r * 128 + c;
                uint32_t fh = *(const uint32_t*)(g_feat_hi + off);
                uint32_t fl = *(const uint32_t*)(g_feat_lo + off);
                float2 vh = __half22float2(*reinterpret_cast<__half2*>(&fh));
                float2 vl = __half22float2(*reinterpret_cast<__half2*>(&fl));
                v0 = v0 * alpha + beta * (vh.x + vl.x);
                v1 = v1 * alpha + beta * (vh.y + vl.y);
                __half h0, l0, h1, l1;
                split2(v0, h0, l0);
                split2(v1, h1, l1);
                Fh[j][q] = pack2(h0, h1);
                Fl[j][q] = pack2(l0, l1);
            }

        // fold this half's 4 k-tiles into mlp2-in accumulation
        #pragma unroll
        for (int kk = 0; kk < 4; kk++)
            ktile_mma(sm + HH2 + H2_IN, 72, 128 * 72, noff + kk * 16,
                      Fh[kk], Fl[kk], acc2);
    }

    // mlp2: -> 64 (relu) -> 64 (relu)
    uint32_t A2h[4][4], A2l[4][4];
    convert_acc<true>(acc2, A2h, A2l);
    layer_reg<4, true>(A2h, A2l, sm + HH2 + H2_H, 72, 64 * 72);

    // final 64 -> 1 from register fragments (fp32)
    {
        float sg = 0.f, sg8 = 0.f;
        #pragma unroll
        for (int j = 0; j < 4; j++)
            #pragma unroll
            for (int q = 0; q < 4; q++) {
                __half2 hv = *reinterpret_cast<__half2*>(&A2h[j][q]);
                __half2 lv = *reinterpret_cast<__half2*>(&A2l[j][q]);
                float2 vh = __half22float2(hv);
                float2 vl = __half22float2(lv);
                int c = j * 16 + ((q >> 1) << 3) + t2 * 2;
                float d = fmaf(vh.x + vl.x, wo[c], (vh.y + vl.y) * wo[c + 1]);
                if ((q & 1) == 0) sg += d; else sg8 += d;
            }
        sg  += __shfl_xor_sync(0xffffffffu, sg, 1);
        sg  += __shfl_xor_sync(0xffffffffu, sg, 2);
        sg8 += __shfl_xor_sync(0xffffffffu, sg8, 1);
        sg8 += __shfl_xor_sync(0xffffffffu, sg8, 2);
        if (t2 == 0) {
            out[row0 + g]     = sg;
            out[row0 + g + 8] = sg8;
        }
    }
}

// ---------------------------------------------------------------------------
// Launch (strictly serial — R5 showed L1-bound kernels must not overlap)
// ---------------------------------------------------------------------------
extern "C" void kernel_launch(void* const* d_in, const int* in_sizes, int n_in,
                              void* d_out, int out_size)
{
    const float* x       = (const float*)d_in[0];
    const float* t       = (const float*)d_in[1];
    const float* alpha   = (const float*)d_in[2];
    const float* table_s = (const float*)d_in[3];
    const float* ws_in   = (const float*)d_in[4];
    const float* ws_hid  = (const float*)d_in[5];
    const float* ws_out  = (const float*)d_in[6];
    const float* table_d = (const float*)d_in[7];
    const float* wd_in   = (const float*)d_in[8];
    const float* wd_hid  = (const float*)d_in[9];
    const float* wd_out  = (const float*)d_in[10];
    const float* w1_in   = (const float*)d_in[11];
    const float* w1_hid  = (const float*)d_in[12];
    const float* w1_out  = (const float*)d_in[13];
    const float* w2_in   = (const float*)d_in[14];
    const float* w2_hid  = (const float*)d_in[15];
    const float* w2_out  = (const float*)d_in[16];
    float* out = (float*)d_out;

    cudaFuncSetAttribute(mlp64_tc<0>, cudaFuncAttributeMaxDynamicSharedMemorySize, MLP64_SMEM);
    cudaFuncSetAttribute(mlp64_tc<1>, cudaFuncAttributeMaxDynamicSharedMemorySize, MLP64_SMEM);
    cudaFuncSetAttribute(head_tc,     cudaFuncAttributeMaxDynamicSharedMemorySize, HEAD_SMEM);

    const int nblkENC = NPTS / 256;
    const int nblkMLP = NPTS / 256;

    prep_weights<<<64, 256>>>(ws_in, ws_hid, ws_out, wd_in, wd_hid, wd_out,
                              w1_in, w1_hid, w1_out, w2_in, w2_hid);

    encode_kernel<3, 0><<<nblkENC, 256>>>(x, nullptr, table_s);
    encode_kernel<4, 1><<<nblkENC, 256>>>(x, t, table_d);

    mlp64_tc<0><<<nblkMLP, 512, MLP64_SMEM>>>();
    mlp64_tc<1><<<nblkMLP, 512, MLP64_SMEM>>>();

    head_tc<<<nblkMLP, 512, HEAD_SMEM>>>(alpha, w2_out, out);
}

// round 11
// speedup vs baseline: 1.2829x; 1.1328x over previous
#include <cuda_runtime.h>
#include <cuda_fp16.h>
#include <cstdint>

// ---------------------------------------------------------------------------
// Problem constants
// ---------------------------------------------------------------------------
#define NPTS   524288
#define LVLS   16
#define TSIZE  524288u
#define TMASK  (TSIZE - 1u)
#define NTILES 2048          // 256-point tiles
#define PGRID  148           // persistent grid = #SMs

__constant__ float c_res[LVLS] = {
    16.f, 24.f, 36.f, 54.f, 81.f, 121.f, 182.f, 273.f,
    410.f, 615.f, 922.f, 1383.f, 2075.f, 3113.f, 4670.f, 7006.f
};

// ---------------------------------------------------------------------------
// Scratch (device globals; no runtime allocation)
// ---------------------------------------------------------------------------
__device__ __align__(16) __half g_enc_s_hi[(size_t)NPTS * 32];
__device__ __align__(16) __half g_enc_s_lo[(size_t)NPTS * 32];
__device__ __align__(16) __half g_enc_d_hi[(size_t)NPTS * 32];
__device__ __align__(16) __half g_enc_d_lo[(size_t)NPTS * 32];
__device__ __align__(16) __half g_feat_hi [(size_t)NPTS * 128];
__device__ __align__(16) __half g_feat_lo [(size_t)NPTS * 128];

// Pre-split weight blobs (hi plane, lo plane at +rows*stride), stride 72/136
#define WB_IN   0
#define WB_H0   4608
#define WB_H1   13824
#define WB_H2   23040
#define WB_OUT  32256
#define WB_TOT  41472
__device__ __align__(16) __half g_wS[WB_TOT];
__device__ __align__(16) __half g_wD[WB_TOT];
#define H1_IN   0
#define H1_H    18432
#define H1_OUT  27648
#define H1_TOT  45056
__device__ __align__(16) __half g_wH1[H1_TOT];
#define H2_IN   0
#define H2_H    18432
#define H2_TOT  27648
__device__ __align__(16) __half g_wH2[H2_TOT];

// ---------------------------------------------------------------------------
__device__ __forceinline__ void split2(float x, __half& h, __half& l) {
    h = __float2half_rn(x);
    l = __float2half_rn(x - __half2float(h));
}

__device__ __forceinline__ uint32_t pack2(__half a, __half b) {
    __half2 v = __halves2half2(a, b);
    return *reinterpret_cast<uint32_t*>(&v);
}

__device__ __forceinline__ void conv_w(__half* dst, const float* __restrict__ src,
                                       int K, int N, int ws, int t0, int nt)
{
    const int tot = K * N / 2;
    const int pl  = K * ws;
    const float2* s2 = (const float2*)src;
    for (int i = t0; i < tot; i += nt) {
        int r = (2 * i) / N, c = (2 * i) % N;
        float2 v = s2[i];
        __half hx, lx, hy, ly;
        split2(v.x, hx, lx);
        split2(v.y, hy, ly);
        *(__half2*)(dst + r * ws + c)      = __halves2half2(hx, hy);
        *(__half2*)(dst + r * ws + pl + c) = __halves2half2(lx, ly);
    }
}

__global__ void __launch_bounds__(256)
prep_weights(const float* __restrict__ ws_in, const float* __restrict__ ws_hid,
             const float* __restrict__ ws_out,
             const float* __restrict__ wd_in, const float* __restrict__ wd_hid,
             const float* __restrict__ wd_out,
             const float* __restrict__ w1_in, const float* __restrict__ w1_hid,
             const float* __restrict__ w1_out,
             const float* __restrict__ w2_in, const float* __restrict__ w2_hid)
{
    const int t0 = blockIdx.x * 256 + threadIdx.x;
    const int nt = gridDim.x * 256;
    conv_w(g_wS + WB_IN,  ws_in,         32, 64, 72, t0, nt);
    conv_w(g_wS + WB_H0,  ws_hid + 0,    64, 64, 72, t0, nt);
    conv_w(g_wS + WB_H1,  ws_hid + 4096, 64, 64, 72, t0, nt);
    conv_w(g_wS + WB_H2,  ws_hid + 8192, 64, 64, 72, t0, nt);
    conv_w(g_wS + WB_OUT, ws_out,        64, 64, 72, t0, nt);
    conv_w(g_wD + WB_IN,  wd_in,         32, 64, 72, t0, nt);
    conv_w(g_wD + WB_H0,  wd_hid + 0,    64, 64, 72, t0, nt);
    conv_w(g_wD + WB_H1,  wd_hid + 4096, 64, 64, 72, t0, nt);
    conv_w(g_wD + WB_H2,  wd_hid + 8192, 64, 64, 72, t0, nt);
    conv_w(g_wD + WB_OUT, wd_out,        64, 64, 72, t0, nt);
    conv_w(g_wH1 + H1_IN,  w1_in,  128, 64,  72,  t0, nt);
    conv_w(g_wH1 + H1_H,   w1_hid, 64,  64,  72,  t0, nt);
    conv_w(g_wH1 + H1_OUT, w1_out, 64,  128, 136, t0, nt);
    conv_w(g_wH2 + H2_IN,  w2_in,  128, 64,  72,  t0, nt);
    conv_w(g_wH2 + H2_H,   w2_hid, 64,  64,  72,  t0, nt);
}

// ---------------------------------------------------------------------------
// Hash-grid encode (one point per thread, all 16 levels) — at gather floor.
// ---------------------------------------------------------------------------
template <int D, int WHICH>
__global__ void __launch_bounds__(256)
encode_kernel(const float* __restrict__ x,
              const float* __restrict__ tptr,
              const float* __restrict__ table)
{
    const int n = blockIdx.x * 256 + threadIdx.x;

    float p[4];
    p[0] = x[3 * n + 0];
    p[1] = x[3 * n + 1];
    p[2] = x[3 * n + 2];
    if (D == 4) p[3] = __ldg(tptr);

    __half2 ehi[16], elo[16];

    #pragma unroll
    for (int l = 0; l < LVLS; l++) {
        const float res = c_res[l];
        uint32_t h[4][2];
        float    w[4][2];
        #pragma unroll
        for (int d = 0; d < D; d++) {
            const uint32_t pr = (d == 0) ? 1u
                              : (d == 1) ? 2654435761u
                              : (d == 2) ? 805459861u
                                         : 3674653429u;
            float pos = p[d] * res;
            float p0f = floorf(pos);
            float fr  = pos - p0f;
            uint32_t p0 = (uint32_t)p0f;
            h[d][0] = p0 * pr;
            h[d][1] = (p0 + 1u) * pr;
            w[d][0] = 1.f - fr;
            w[d][1] = fr;
        }

        const float2* tl = (const float2*)table + (size_t)l * TSIZE;
        float f0 = 0.f, f1 = 0.f;
        #pragma unroll
        for (int c = 0; c < (1 << D); c++) {
            uint32_t hh = h[0][c & 1] ^ h[1][(c >> 1) & 1] ^ h[2][(c >> 2) & 1];
            float    ww = w[0][c & 1] * w[1][(c >> 1) & 1] * w[2][(c >> 2) & 1];
            if (D == 4) {
                hh ^= h[3][(c >> 3) & 1];
                ww *= w[3][(c >> 3) & 1];
            }
            float2 f = __ldg(tl + (hh & TMASK));
            f0 = fmaf(ww, f.x, f0);
            f1 = fmaf(ww, f.y, f1);
        }
        __half h0, l0, h1, l1;
        split2(f0, h0, l0);
        split2(f1, h1, l1);
        ehi[l] = __halves2half2(h0, h1);
        elo[l] = __halves2half2(l0, l1);
    }

    __half* dh = (WHICH == 0 ? g_enc_s_hi : g_enc_d_hi) + (size_t)n * 32;
    __half* dl = (WHICH == 0 ? g_enc_s_lo : g_enc_d_lo) + (size_t)n * 32;
    #pragma unroll
    for (int i = 0; i < 4; i++) ((uint4*)dh)[i] = ((const uint4*)ehi)[i];
    #pragma unroll
    for (int i = 0; i < 4; i++) ((uint4*)dl)[i] = ((const uint4*)elo)[i];
}

// ---------------------------------------------------------------------------
// Tensor-core primitives
// ---------------------------------------------------------------------------
__device__ __forceinline__ uint32_t smem_u32(const void* p) {
    return (uint32_t)__cvta_generic_to_shared(p);
}

__device__ __forceinline__ void ldsm_x4_t(uint32_t& r0, uint32_t& r1,
                                          uint32_t& r2, uint32_t& r3, uint32_t a) {
    asm volatile("ldmatrix.sync.aligned.m8n8.x4.trans.shared.b16 {%0,%1,%2,%3}, [%4];"
                 : "=r"(r0), "=r"(r1), "=r"(r2), "=r"(r3) : "r"(a));
}

__device__ __forceinline__ void mma16816(float* c, const uint32_t* a,
                                         uint32_t b0, uint32_t b1) {
    asm volatile(
        "mma.sync.aligned.m16n8k16.row.col.f32.f16.f16.f32 "
        "{%0,%1,%2,%3}, {%4,%5,%6,%7}, {%8,%9}, {%0,%1,%2,%3};"
        : "+f"(c[0]), "+f"(c[1]), "+f"(c[2]), "+f"(c[3])
        : "r"(a[0]), "r"(a[1]), "r"(a[2]), "r"(a[3]), "r"(b0), "r"(b1));
}

// One k-tile of split-MMA: A (hi/lo, 4+4 regs) x W rows [krow..krow+16) -> acc[8][4]
__device__ __forceinline__ void ktile_mma(const __half* W, int ws, int wpl, int krow,
                                          const uint32_t* ah, const uint32_t* al,
                                          float (*acc)[4])
{
    const int lane = threadIdx.x & 31;
    #pragma unroll
    for (int nb = 0; nb < 4; nb++) {
        const __half* wp = W + (krow + (lane & 7) + ((lane >> 3) & 1) * 8) * ws
                         + nb * 16 + ((lane >> 4) << 3);
        uint32_t bh0, bh1, bh2, bh3, bl0, bl1, bl2, bl3;
        ldsm_x4_t(bh0, bh1, bh2, bh3, smem_u32(wp));
        ldsm_x4_t(bl0, bl1, bl2, bl3, smem_u32(wp + wpl));
        mma16816(acc[2 * nb + 0], ah, bh0, bh1);
        mma16816(acc[2 * nb + 0], ah, bl0, bl1);
        mma16816(acc[2 * nb + 0], al, bh0, bh1);
        mma16816(acc[2 * nb + 1], ah, bh2, bh3);
        mma16816(acc[2 * nb + 1], ah, bl2, bl3);
        mma16816(acc[2 * nb + 1], al, bh2, bh3);
    }
}

// ---------------------------------------------------------------------------
// A-fragment direct global load: row-major matrix, row stride S halves.
// ---------------------------------------------------------------------------
__device__ __forceinline__ void ldg_afrag(const __half* __restrict__ base,
                                          size_t row0, int S, int col0,
                                          uint32_t* a)
{
    const int lane = threadIdx.x & 31;
    const int g = lane >> 2, t2 = lane & 3;
    const __half* p = base + (row0 + g) * (size_t)S + col0 + t2 * 2;
    a[0] = *(const uint32_t*)(p);
    a[1] = *(const uint32_t*)(p + 8 * (size_t)S);
    a[2] = *(const uint32_t*)(p + 8);
    a[3] = *(const uint32_t*)(p + 8 * (size_t)S + 8);
}

// ---------------------------------------------------------------------------
// acc -> A-fragment conversion (identity: n-pair {2j,2j+1} == k-tile j)
// ---------------------------------------------------------------------------
template <bool RELU>
__device__ __forceinline__ void convert_acc(float (*acc)[4],
                                            uint32_t (*Ah)[4],
                                            uint32_t (*Al)[4])
{
    #pragma unroll
    for (int j = 0; j < 4; j++)
        #pragma unroll
        for (int q = 0; q < 4; q++) {
            float v0 = acc[2 * j + (q >> 1)][(q & 1) * 2 + 0];
            float v1 = acc[2 * j + (q >> 1)][(q & 1) * 2 + 1];
            if (RELU) { v0 = fmaxf(v0, 0.f); v1 = fmaxf(v1, 0.f); }
            __half h0, l0, h1, l1;
            split2(v0, h0, l0);
            split2(v1, h1, l1);
            Ah[j][q] = pack2(h0, h1);
            Al[j][q] = pack2(l0, l1);
        }
}

// Layer with A in registers: K = KT*16 -> N = 64 (in-place A update)
template <int KT, bool RELU>
__device__ __forceinline__ void layer_reg(uint32_t (*Ah)[4], uint32_t (*Al)[4],
                                          const __half* W, int ws, int wpl)
{
    float acc[8][4];
    #pragma unroll
    for (int t = 0; t < 8; t++)
        #pragma unroll
        for (int j = 0; j < 4; j++) acc[t][j] = 0.f;
    #pragma unroll
    for (int kk = 0; kk < KT; kk++)
        ktile_mma(W, ws, wpl, kk * 16, Ah[kk], Al[kk], acc);
    convert_acc<RELU>(acc, Ah, Al);
}

// Layer with A fragments loaded directly from gmem (hi/lo planes).
template <int KT, bool RELU>
__device__ __forceinline__ void layer_gmemA(const __half* __restrict__ bh,
                                            const __half* __restrict__ bl,
                                            size_t row0, int S,
                                            const __half* W, int ws, int wpl,
                                            uint32_t (*Ah)[4], uint32_t (*Al)[4])
{
    float acc[8][4];
    #pragma unroll
    for (int t = 0; t < 8; t++)
        #pragma unroll
        for (int j = 0; j < 4; j++) acc[t][j] = 0.f;
    #pragma unroll
    for (int kk = 0; kk < KT; kk++) {
        uint32_t th[4], tl[4];
        ldg_afrag(bh, row0, S, kk * 16, th);
        ldg_afrag(bl, row0, S, kk * 16, tl);
        ktile_mma(W, ws, wpl, kk * 16, th, tl, acc);
    }
    convert_acc<RELU>(acc, Ah, Al);
}

// Store register A-fragments (hi/lo) to gmem row-major (stride S halves).
__device__ __forceinline__ void stg_afrags(uint32_t (*Ah)[4], uint32_t (*Al)[4],
                                           __half* __restrict__ dh,
                                           __half* __restrict__ dl,
                                           size_t row0, int S, int col0)
{
    const int lane = threadIdx.x & 31;
    const int g = lane >> 2, t2 = lane & 3;
    #pragma unroll
    for (int j = 0; j < 4; j++) {
        const int c = col0 + j * 16 + t2 * 2;
        size_t o0 = (row0 + g) * (size_t)S + c;
        size_t o1 = (row0 + g + 8) * (size_t)S + c;
        *(uint32_t*)(dh + o0)     = Ah[j][0];
        *(uint32_t*)(dh + o1)     = Ah[j][1];
        *(uint32_t*)(dh + o0 + 8) = Ah[j][2];
        *(uint32_t*)(dh + o1 + 8) = Ah[j][3];
        *(uint32_t*)(dl + o0)     = Al[j][0];
        *(uint32_t*)(dl + o1)     = Al[j][1];
        *(uint32_t*)(dl + o0 + 8) = Al[j][2];
        *(uint32_t*)(dl + o1 + 8) = Al[j][3];
    }
}

// ---------------------------------------------------------------------------
// Persistent branch MLP: both S and D blobs resident; 148 blocks x 512 thr;
// each block loops over 2*NTILES point-tiles (256 pts each, 16 pts/warp).
// ---------------------------------------------------------------------------
#define MLPALL_SMEM (WB_TOT * 2 * 2)

__global__ void __launch_bounds__(512, 1)
mlp64_all()
{
    extern __shared__ __align__(16) __half sm[];
    const int tid = threadIdx.x;

    {
        const uint4* s0 = (const uint4*)g_wS;
        const uint4* s1 = (const uint4*)g_wD;
        uint4* d0 = (uint4*)sm;
        uint4* d1 = (uint4*)(sm + WB_TOT);
        #pragma unroll 4
        for (int i = tid; i < WB_TOT / 8; i += 512) { d0[i] = s0[i]; d1[i] = s1[i]; }
    }
    __syncthreads();

    const int w = tid >> 5;

    for (int tile = blockIdx.x; tile < 2 * NTILES; tile += gridDim.x) {
        const int which = tile >= NTILES;
        const size_t row0 = (size_t)(tile & (NTILES - 1)) * 256 + w * 16;
        const __half* W  = sm + which * WB_TOT;
        const __half* eh = which ? g_enc_d_hi : g_enc_s_hi;
        const __half* el = which ? g_enc_d_lo : g_enc_s_lo;

        uint32_t Ah[4][4], Al[4][4];

        layer_gmemA<2, true>(eh, el, row0, 32, W + WB_IN, 72, 32 * 72, Ah, Al);
        layer_reg<4, true >(Ah, Al, W + WB_H0,  72, 64 * 72);
        layer_reg<4, true >(Ah, Al, W + WB_H1,  72, 64 * 72);
        layer_reg<4, true >(Ah, Al, W + WB_H2,  72, 64 * 72);
        layer_reg<4, false>(Ah, Al, W + WB_OUT, 72, 64 * 72);

        stg_afrags(Ah, Al, g_feat_hi, g_feat_lo, row0, 128, which * 64);
    }
}

// ---------------------------------------------------------------------------
// Persistent merged head: feat128 -> 64 -> 64 -> 128 (+blend, regs) -> 64 -> 64 -> 1
// 148 blocks x 512 thr; loops over NTILES tiles.
// ---------------------------------------------------------------------------
#define HH2    H1_TOT
#define HHO    (HH2 + H2_TOT)
#define HEAD_SMEM ((HHO + 128) * 2)

__global__ void __launch_bounds__(512, 1)
head_tc(const float* __restrict__ alpha_p,
        const float* __restrict__ w2_out, float* __restrict__ out)
{
    extern __shared__ __align__(16) __half sm[];
    const int tid = threadIdx.x;
    float* wo = (float*)(sm + HHO);

    {
        const uint4* s1 = (const uint4*)g_wH1;
        uint4* d1 = (uint4*)sm;
        #pragma unroll 4
        for (int i = tid; i < H1_TOT / 8; i += 512) d1[i] = s1[i];
        const uint4* s2 = (const uint4*)g_wH2;
        uint4* d2 = (uint4*)(sm + HH2);
        #pragma unroll 4
        for (int i = tid; i < H2_TOT / 8; i += 512) d2[i] = s2[i];
        for (int i = tid; i < 64; i += 512) wo[i] = w2_out[i];
    }
    __syncthreads();

    const int w = tid >> 5;
    const int lane = tid & 31;
    const int g = lane >> 2, t2 = lane & 3;

    const float alpha = __ldg(alpha_p);
    const float beta  = 1.f - alpha;

    for (int tile = blockIdx.x; tile < NTILES; tile += gridDim.x) {
        const size_t row0 = (size_t)tile * 256 + w * 16;

        // mlp1: 128 -> 64 -> 64
        uint32_t A1h[4][4], A1l[4][4];
        layer_gmemA<8, true>(g_feat_hi, g_feat_lo, row0, 128,
                             sm + H1_IN, 72, 128 * 72, A1h, A1l);
        layer_reg<4, true>(A1h, A1l, sm + H1_H, 72, 64 * 72);

        // w1_out (64 -> 128) per 64-col half: blend vs original F (fp32),
        // convert to fragments, fold straight into mlp2-in accumulation.
        float acc2[8][4];
        #pragma unroll
        for (int t = 0; t < 8; t++)
            #pragma unroll
            for (int j = 0; j < 4; j++) acc2[t][j] = 0.f;

        #pragma unroll
        for (int half = 0; half < 2; half++) {
            const int noff = half * 64;
            float accO[8][4];
            #pragma unroll
            for (int t = 0; t < 8; t++)
                #pragma unroll
                for (int j = 0; j < 4; j++) accO[t][j] = 0.f;

            #pragma unroll
            for (int kk = 0; kk < 4; kk++) {
                const __half* Wb = sm + H1_OUT + noff;
                const __half* wrow = Wb + (kk * 16 + (lane & 7) + ((lane >> 3) & 1) * 8) * 136
                                   + ((lane >> 4) << 3);
                #pragma unroll
                for (int nb = 0; nb < 4; nb++) {
                    uint32_t bh0, bh1, bh2, bh3, bl0, bl1, bl2, bl3;
                    ldsm_x4_t(bh0, bh1, bh2, bh3, smem_u32(wrow + nb * 16));
                    ldsm_x4_t(bl0, bl1, bl2, bl3, smem_u32(wrow + nb * 16 + 64 * 136));
                    mma16816(accO[2 * nb + 0], A1h[kk], bh0, bh1);
                    mma16816(accO[2 * nb + 0], A1h[kk], bl0, bl1);
                    mma16816(accO[2 * nb + 0], A1l[kk], bh0, bh1);
                    mma16816(accO[2 * nb + 1], A1h[kk], bh2, bh3);
                    mma16816(accO[2 * nb + 1], A1h[kk], bl2, bl3);
                    mma16816(accO[2 * nb + 1], A1l[kk], bh2, bh3);
                }
            }

            uint32_t Fh[4][4], Fl[4][4];
            #pragma unroll
            for (int j = 0; j < 4; j++)
                #pragma unroll
                for (int q = 0; q < 4; q++) {
                    float v0 = accO[2 * j + (q >> 1)][(q & 1) * 2 + 0];
                    float v1 = accO[2 * j + (q >> 1)][(q & 1) * 2 + 1];
                    const size_t r = row0 + g + ((q & 1) ? 8 : 0);
                    const int    c = noff + j * 16 + ((q >> 1) ? 8 : 0) + t2 * 2;
                    const size_t off = r * 128 + c;
                    uint32_t fh = *(const uint32_t*)(g_feat_hi + off);
                    uint32_t fl = *(const uint32_t*)(g_feat_lo + off);
                    float2 vh = __half22float2(*reinterpret_cast<__half2*>(&fh));
                    float2 vl = __half22float2(*reinterpret_cast<__half2*>(&fl));
                    v0 = v0 * alpha + beta * (vh.x + vl.x);
                    v1 = v1 * alpha + beta * (vh.y + vl.y);
                    __half h0, l0, h1, l1;
                    split2(v0, h0, l0);
                    split2(v1, h1, l1);
                    Fh[j][q] = pack2(h0, h1);
                    Fl[j][q] = pack2(l0, l1);
                }

            #pragma unroll
            for (int kk = 0; kk < 4; kk++)
                ktile_mma(sm + HH2 + H2_IN, 72, 128 * 72, noff + kk * 16,
                          Fh[kk], Fl[kk], acc2);
        }

        // mlp2: -> 64 (relu) -> 64 (relu)
        uint32_t A2h[4][4], A2l[4][4];
        convert_acc<true>(acc2, A2h, A2l);
        layer_reg<4, true>(A2h, A2l, sm + HH2 + H2_H, 72, 64 * 72);

        // final 64 -> 1 from register fragments (fp32)
        {
            float sg = 0.f, sg8 = 0.f;
            #pragma unroll
            for (int j = 0; j < 4; j++)
                #pragma unroll
                for (int q = 0; q < 4; q++) {
                    __half2 hv = *reinterpret_cast<__half2*>(&A2h[j][q]);
                    __half2 lv = *reinterpret_cast<__half2*>(&A2l[j][q]);
                    float2 vh = __half22float2(hv);
                    float2 vl = __half22float2(lv);
                    int c = j * 16 + ((q >> 1) << 3) + t2 * 2;
                    float d = fmaf(vh.x + vl.x, wo[c], (vh.y + vl.y) * wo[c + 1]);
                    if ((q & 1) == 0) sg += d; else sg8 += d;
                }
            sg  += __shfl_xor_sync(0xffffffffu, sg, 1);
            sg  += __shfl_xor_sync(0xffffffffu, sg, 2);
            sg8 += __shfl_xor_sync(0xffffffffu, sg8, 1);
            sg8 += __shfl_xor_sync(0xffffffffu, sg8, 2);
            if (t2 == 0) {
                out[row0 + g]     = sg;
                out[row0 + g + 8] = sg8;
            }
        }
    }
}

// ---------------------------------------------------------------------------
// Launch (strictly serial — R5 showed L1-bound kernels must not overlap)
// ---------------------------------------------------------------------------
extern "C" void kernel_launch(void* const* d_in, const int* in_sizes, int n_in,
                              void* d_out, int out_size)
{
    const float* x       = (const float*)d_in[0];
    const float* t       = (const float*)d_in[1];
    const float* alpha   = (const float*)d_in[2];
    const float* table_s = (const float*)d_in[3];
    const float* ws_in   = (const float*)d_in[4];
    const float* ws_hid  = (const float*)d_in[5];
    const float* ws_out  = (const float*)d_in[6];
    const float* table_d = (const float*)d_in[7];
    const float* wd_in   = (const float*)d_in[8];
    const float* wd_hid  = (const float*)d_in[9];
    const float* wd_out  = (const float*)d_in[10];
    const float* w1_in   = (const float*)d_in[11];
    const float* w1_hid  = (const float*)d_in[12];
    const float* w1_out  = (const float*)d_in[13];
    const float* w2_in   = (const float*)d_in[14];
    const float* w2_hid  = (const float*)d_in[15];
    const float* w2_out  = (const float*)d_in[16];
    float* out = (float*)d_out;

    cudaFuncSetAttribute(mlp64_all, cudaFuncAttributeMaxDynamicSharedMemorySize, MLPALL_SMEM);
    cudaFuncSetAttribute(head_tc,   cudaFuncAttributeMaxDynamicSharedMemorySize, HEAD_SMEM);

    const int nblkENC = NPTS / 256;

    prep_weights<<<64, 256>>>(ws_in, ws_hid, ws_out, wd_in, wd_hid, wd_out,
                              w1_in, w1_hid, w1_out, w2_in, w2_hid);

    encode_kernel<3, 0><<<nblkENC, 256>>>(x, nullptr, table_s);
    encode_kernel<4, 1><<<nblkENC, 256>>>(x, t, table_d);

    mlp64_all<<<PGRID, 512, MLPALL_SMEM>>>();
    head_tc<<<PGRID, 512, HEAD_SMEM>>>(alpha, w2_out, out);
}

// round 12
// speedup vs baseline: 1.3851x; 1.0797x over previous
#include <cuda_runtime.h>
#include <cuda_fp16.h>
#include <cstdint>

// ---------------------------------------------------------------------------
// Problem constants
// ---------------------------------------------------------------------------
#define NPTS   524288
#define LVLS   16
#define TSIZE  524288u
#define TMASK  (TSIZE - 1u)
#define NTILES 2048          // 256-point tiles
#define PGRID  148           // persistent grid = #SMs

__constant__ float c_res[LVLS] = {
    16.f, 24.f, 36.f, 54.f, 81.f, 121.f, 182.f, 273.f,
    410.f, 615.f, 922.f, 1383.f, 2075.f, 3113.f, 4670.f, 7006.f
};

// ---------------------------------------------------------------------------
// Scratch (device globals; no runtime allocation)
// ---------------------------------------------------------------------------
__device__ __align__(16) __half g_enc_s_hi[(size_t)NPTS * 32];
__device__ __align__(16) __half g_enc_s_lo[(size_t)NPTS * 32];
__device__ __align__(16) __half g_enc_d_hi[(size_t)NPTS * 32];
__device__ __align__(16) __half g_enc_d_lo[(size_t)NPTS * 32];
__device__ __align__(16) __half g_feat_hi [(size_t)NPTS * 128];
__device__ __align__(16) __half g_feat_lo [(size_t)NPTS * 128];

// Pre-split weight blobs (hi plane, lo plane at +rows*stride), stride 72/136
#define WB_IN   0
#define WB_H0   4608
#define WB_H1   13824
#define WB_H2   23040
#define WB_OUT  32256
#define WB_TOT  41472
__device__ __align__(16) __half g_wS[WB_TOT];
__device__ __align__(16) __half g_wD[WB_TOT];
#define H1_IN   0
#define H1_H    18432
#define H1_OUT  27648
#define H1_TOT  45056
__device__ __align__(16) __half g_wH1[H1_TOT];
#define H2_IN   0
#define H2_H    18432
#define H2_TOT  27648
__device__ __align__(16) __half g_wH2[H2_TOT];

// ---------------------------------------------------------------------------
__device__ __forceinline__ void split2(float x, __half& h, __half& l) {
    h = __float2half_rn(x);
    l = __float2half_rn(x - __half2float(h));
}

__device__ __forceinline__ uint32_t pack2(__half a, __half b) {
    __half2 v = __halves2half2(a, b);
    return *reinterpret_cast<uint32_t*>(&v);
}

__device__ __forceinline__ void conv_w(__half* dst, const float* __restrict__ src,
                                       int K, int N, int ws, int t0, int nt)
{
    const int tot = K * N / 2;
    const int pl  = K * ws;
    const float2* s2 = (const float2*)src;
    for (int i = t0; i < tot; i += nt) {
        int r = (2 * i) / N, c = (2 * i) % N;
        float2 v = s2[i];
        __half hx, lx, hy, ly;
        split2(v.x, hx, lx);
        split2(v.y, hy, ly);
        *(__half2*)(dst + r * ws + c)      = __halves2half2(hx, hy);
        *(__half2*)(dst + r * ws + pl + c) = __halves2half2(lx, ly);
    }
}

__global__ void __launch_bounds__(256)
prep_weights(const float* __restrict__ ws_in, const float* __restrict__ ws_hid,
             const float* __restrict__ ws_out,
             const float* __restrict__ wd_in, const float* __restrict__ wd_hid,
             const float* __restrict__ wd_out,
             const float* __restrict__ w1_in, const float* __restrict__ w1_hid,
             const float* __restrict__ w1_out,
             const float* __restrict__ w2_in, const float* __restrict__ w2_hid)
{
    const int t0 = blockIdx.x * 256 + threadIdx.x;
    const int nt = gridDim.x * 256;
    conv_w(g_wS + WB_IN,  ws_in,         32, 64, 72, t0, nt);
    conv_w(g_wS + WB_H0,  ws_hid + 0,    64, 64, 72, t0, nt);
    conv_w(g_wS + WB_H1,  ws_hid + 4096, 64, 64, 72, t0, nt);
    conv_w(g_wS + WB_H2,  ws_hid + 8192, 64, 64, 72, t0, nt);
    conv_w(g_wS + WB_OUT, ws_out,        64, 64, 72, t0, nt);
    conv_w(g_wD + WB_IN,  wd_in,         32, 64, 72, t0, nt);
    conv_w(g_wD + WB_H0,  wd_hid + 0,    64, 64, 72, t0, nt);
    conv_w(g_wD + WB_H1,  wd_hid + 4096, 64, 64, 72, t0, nt);
    conv_w(g_wD + WB_H2,  wd_hid + 8192, 64, 64, 72, t0, nt);
    conv_w(g_wD + WB_OUT, wd_out,        64, 64, 72, t0, nt);
    conv_w(g_wH1 + H1_IN,  w1_in,  128, 64,  72,  t0, nt);
    conv_w(g_wH1 + H1_H,   w1_hid, 64,  64,  72,  t0, nt);
    conv_w(g_wH1 + H1_OUT, w1_out, 64,  128, 136, t0, nt);
    conv_w(g_wH2 + H2_IN,  w2_in,  128, 64,  72,  t0, nt);
    conv_w(g_wH2 + H2_H,   w2_hid, 64,  64,  72,  t0, nt);
}

// ---------------------------------------------------------------------------
// Hash-grid encode with dim-0 corner-pair merging (PRIMES[0] == 1):
// when p0 is even, the two dim-0 corners hash to indices {2k, 2k+1} ->
// one 16B float4 load replaces two float2 gathers (wavefront halved).
// FMA order matches the plain corner loop exactly.
// ---------------------------------------------------------------------------
template <int D, int WHICH>
__global__ void __launch_bounds__(256)
encode_kernel(const float* __restrict__ x,
              const float* __restrict__ tptr,
              const float* __restrict__ table)
{
    const int n = blockIdx.x * 256 + threadIdx.x;

    float p[4];
    p[0] = x[3 * n + 0];
    p[1] = x[3 * n + 1];
    p[2] = x[3 * n + 2];
    if (D == 4) p[3] = __ldg(tptr);

    __half2 ehi[16], elo[16];

    #pragma unroll
    for (int l = 0; l < LVLS; l++) {
        const float res = c_res[l];
        uint32_t h[4][2];
        float    w[4][2];
        uint32_t p0u = 0;
        #pragma unroll
        for (int d = 0; d < D; d++) {
            const uint32_t pr = (d == 0) ? 1u
                              : (d == 1) ? 2654435761u
                              : (d == 2) ? 805459861u
                                         : 3674653429u;
            float pos = p[d] * res;
            float p0f = floorf(pos);
            float fr  = pos - p0f;
            uint32_t p0 = (uint32_t)p0f;
            if (d == 0) p0u = p0;
            h[d][0] = p0 * pr;
            h[d][1] = (p0 + 1u) * pr;
            w[d][0] = 1.f - fr;
            w[d][1] = fr;
        }

        const float2* tl = (const float2*)table + (size_t)l * TSIZE;
        float f0 = 0.f, f1 = 0.f;
        const float w00 = w[0][0], w01 = w[0][1];

        if ((p0u & 1u) == 0u) {
            // merged path: each rest-combo's dim-0 pair is {2k, 2k+1}
            #pragma unroll
            for (int rc = 0; rc < (1 << (D - 1)); rc++) {
                uint32_t A = h[1][rc & 1] ^ h[2][(rc >> 1) & 1];
                float   Wr = w[1][rc & 1] * w[2][(rc >> 1) & 1];
                if (D == 4) {
                    A  ^= h[3][(rc >> 2) & 1];
                    Wr *= w[3][(rc >> 2) & 1];
                }
                uint32_t i0 = (A ^ h[0][0]) & TMASK;       // even-p0: i1 = i0^1
                float4 v = __ldg((const float4*)tl + (i0 >> 1));
                const bool hi = (i0 & 1u);
                float e0x = hi ? v.z : v.x, e0y = hi ? v.w : v.y;
                float e1x = hi ? v.x : v.z, e1y = hi ? v.y : v.w;
                float wa = w00 * Wr, wb = w01 * Wr;
                f0 = fmaf(wa, e0x, f0);
                f1 = fmaf(wa, e0y, f1);
                f0 = fmaf(wb, e1x, f0);
                f1 = fmaf(wb, e1y, f1);
            }
        } else {
            #pragma unroll
            for (int rc = 0; rc < (1 << (D - 1)); rc++) {
                uint32_t A = h[1][rc & 1] ^ h[2][(rc >> 1) & 1];
                float   Wr = w[1][rc & 1] * w[2][(rc >> 1) & 1];
                if (D == 4) {
                    A  ^= h[3][(rc >> 2) & 1];
                    Wr *= w[3][(rc >> 2) & 1];
                }
                uint32_t i0 = (A ^ h[0][0]) & TMASK;
                uint32_t i1 = (A ^ h[0][1]) & TMASK;
                float2 e0 = __ldg(tl + i0);
                float2 e1 = __ldg(tl + i1);
                float wa = w00 * Wr, wb = w01 * Wr;
                f0 = fmaf(wa, e0.x, f0);
                f1 = fmaf(wa, e0.y, f1);
                f0 = fmaf(wb, e1.x, f0);
                f1 = fmaf(wb, e1.y, f1);
            }
        }

        __half h0, l0, h1, l1;
        split2(f0, h0, l0);
        split2(f1, h1, l1);
        ehi[l] = __halves2half2(h0, h1);
        elo[l] = __halves2half2(l0, l1);
    }

    __half* dh = (WHICH == 0 ? g_enc_s_hi : g_enc_d_hi) + (size_t)n * 32;
    __half* dl = (WHICH == 0 ? g_enc_s_lo : g_enc_d_lo) + (size_t)n * 32;
    #pragma unroll
    for (int i = 0; i < 4; i++) ((uint4*)dh)[i] = ((const uint4*)ehi)[i];
    #pragma unroll
    for (int i = 0; i < 4; i++) ((uint4*)dl)[i] = ((const uint4*)elo)[i];
}

// ---------------------------------------------------------------------------
// Tensor-core primitives
// ---------------------------------------------------------------------------
__device__ __forceinline__ uint32_t smem_u32(const void* p) {
    return (uint32_t)__cvta_generic_to_shared(p);
}

__device__ __forceinline__ void ldsm_x4_t(uint32_t& r0, uint32_t& r1,
                                          uint32_t& r2, uint32_t& r3, uint32_t a) {
    asm volatile("ldmatrix.sync.aligned.m8n8.x4.trans.shared.b16 {%0,%1,%2,%3}, [%4];"
                 : "=r"(r0), "=r"(r1), "=r"(r2), "=r"(r3) : "r"(a));
}

__device__ __forceinline__ void mma16816(float* c, const uint32_t* a,
                                         uint32_t b0, uint32_t b1) {
    asm volatile(
        "mma.sync.aligned.m16n8k16.row.col.f32.f16.f16.f32 "
        "{%0,%1,%2,%3}, {%4,%5,%6,%7}, {%8,%9}, {%0,%1,%2,%3};"
        : "+f"(c[0]), "+f"(c[1]), "+f"(c[2]), "+f"(c[3])
        : "r"(a[0]), "r"(a[1]), "r"(a[2]), "r"(a[3]), "r"(b0), "r"(b1));
}

// One k-tile of split-MMA: A (hi/lo, 4+4 regs) x W rows [krow..krow+16) -> acc[8][4]
__device__ __forceinline__ void ktile_mma(const __half* W, int ws, int wpl, int krow,
                                          const uint32_t* ah, const uint32_t* al,
                                          float (*acc)[4])
{
    const int lane = threadIdx.x & 31;
    #pragma unroll
    for (int nb = 0; nb < 4; nb++) {
        const __half* wp = W + (krow + (lane & 7) + ((lane >> 3) & 1) * 8) * ws
                         + nb * 16 + ((lane >> 4) << 3);
        uint32_t bh0, bh1, bh2, bh3, bl0, bl1, bl2, bl3;
        ldsm_x4_t(bh0, bh1, bh2, bh3, smem_u32(wp));
        ldsm_x4_t(bl0, bl1, bl2, bl3, smem_u32(wp + wpl));
        mma16816(acc[2 * nb + 0], ah, bh0, bh1);
        mma16816(acc[2 * nb + 0], ah, bl0, bl1);
        mma16816(acc[2 * nb + 0], al, bh0, bh1);
        mma16816(acc[2 * nb + 1], ah, bh2, bh3);
        mma16816(acc[2 * nb + 1], ah, bl2, bl3);
        mma16816(acc[2 * nb + 1], al, bh2, bh3);
    }
}

// ---------------------------------------------------------------------------
// A-fragment direct global load: row-major matrix, row stride S halves.
// ---------------------------------------------------------------------------
__device__ __forceinline__ void ldg_afrag(const __half* __restrict__ base,
                                          size_t row0, int S, int col0,
                                          uint32_t* a)
{
    const int lane = threadIdx.x & 31;
    const int g = lane >> 2, t2 = lane & 3;
    const __half* p = base + (row0 + g) * (size_t)S + col0 + t2 * 2;
    a[0] = *(const uint32_t*)(p);
    a[1] = *(const uint32_t*)(p + 8 * (size_t)S);
    a[2] = *(const uint32_t*)(p + 8);
    a[3] = *(const uint32_t*)(p + 8 * (size_t)S + 8);
}

// ---------------------------------------------------------------------------
// acc -> A-fragment conversion (identity: n-pair {2j,2j+1} == k-tile j)
// ---------------------------------------------------------------------------
template <bool RELU>
__device__ __forceinline__ void convert_acc(float (*acc)[4],
                                            uint32_t (*Ah)[4],
                                            uint32_t (*Al)[4])
{
    #pragma unroll
    for (int j = 0; j < 4; j++)
        #pragma unroll
        for (int q = 0; q < 4; q++) {
            float v0 = acc[2 * j + (q >> 1)][(q & 1) * 2 + 0];
            float v1 = acc[2 * j + (q >> 1)][(q & 1) * 2 + 1];
            if (RELU) { v0 = fmaxf(v0, 0.f); v1 = fmaxf(v1, 0.f); }
            __half h0, l0, h1, l1;
            split2(v0, h0, l0);
            split2(v1, h1, l1);
            Ah[j][q] = pack2(h0, h1);
            Al[j][q] = pack2(l0, l1);
        }
}

// Layer with A in registers: K = KT*16 -> N = 64 (in-place A update)
template <int KT, bool RELU>
__device__ __forceinline__ void layer_reg(uint32_t (*Ah)[4], uint32_t (*Al)[4],
                                          const __half* W, int ws, int wpl)
{
    float acc[8][4];
    #pragma unroll
    for (int t = 0; t < 8; t++)
        #pragma unroll
        for (int j = 0; j < 4; j++) acc[t][j] = 0.f;
    #pragma unroll
    for (int kk = 0; kk < KT; kk++)
        ktile_mma(W, ws, wpl, kk * 16, Ah[kk], Al[kk], acc);
    convert_acc<RELU>(acc, Ah, Al);
}

// Layer with A fragments loaded directly from gmem (hi/lo planes).
template <int KT, bool RELU>
__device__ __forceinline__ void layer_gmemA(const __half* __restrict__ bh,
                                            const __half* __restrict__ bl,
                                            size_t row0, int S,
                                            const __half* W, int ws, int wpl,
                                            uint32_t (*Ah)[4], uint32_t (*Al)[4])
{
    float acc[8][4];
    #pragma unroll
    for (int t = 0; t < 8; t++)
        #pragma unroll
        for (int j = 0; j < 4; j++) acc[t][j] = 0.f;
    #pragma unroll
    for (int kk = 0; kk < KT; kk++) {
        uint32_t th[4], tl[4];
        ldg_afrag(bh, row0, S, kk * 16, th);
        ldg_afrag(bl, row0, S, kk * 16, tl);
        ktile_mma(W, ws, wpl, kk * 16, th, tl, acc);
    }
    convert_acc<RELU>(acc, Ah, Al);
}

// Store register A-fragments (hi/lo) to gmem row-major (stride S halves).
__device__ __forceinline__ void stg_afrags(uint32_t (*Ah)[4], uint32_t (*Al)[4],
                                           __half* __restrict__ dh,
                                           __half* __restrict__ dl,
                                           size_t row0, int S, int col0)
{
    const int lane = threadIdx.x & 31;
    const int g = lane >> 2, t2 = lane & 3;
    #pragma unroll
    for (int j = 0; j < 4; j++) {
        const int c = col0 + j * 16 + t2 * 2;
        size_t o0 = (row0 + g) * (size_t)S + c;
        size_t o1 = (row0 + g + 8) * (size_t)S + c;
        *(uint32_t*)(dh + o0)     = Ah[j][0];
        *(uint32_t*)(dh + o1)     = Ah[j][1];
        *(uint32_t*)(dh + o0 + 8) = Ah[j][2];
        *(uint32_t*)(dh + o1 + 8) = Ah[j][3];
        *(uint32_t*)(dl + o0)     = Al[j][0];
        *(uint32_t*)(dl + o1)     = Al[j][1];
        *(uint32_t*)(dl + o0 + 8) = Al[j][2];
        *(uint32_t*)(dl + o1 + 8) = Al[j][3];
    }
}

// ---------------------------------------------------------------------------
// Persistent branch MLP: both S and D blobs resident; 148 blocks x 512 thr;
// each block loops over 2*NTILES point-tiles (256 pts each, 16 pts/warp).
// ---------------------------------------------------------------------------
#define MLPALL_SMEM (WB_TOT * 2 * 2)

__global__ void __launch_bounds__(512, 1)
mlp64_all()
{
    extern __shared__ __align__(16) __half sm[];
    const int tid = threadIdx.x;

    {
        const uint4* s0 = (const uint4*)g_wS;
        const uint4* s1 = (const uint4*)g_wD;
        uint4* d0 = (uint4*)sm;
        uint4* d1 = (uint4*)(sm + WB_TOT);
        #pragma unroll 4
        for (int i = tid; i < WB_TOT / 8; i += 512) { d0[i] = s0[i]; d1[i] = s1[i]; }
    }
    __syncthreads();

    const int w = tid >> 5;

    for (int tile = blockIdx.x; tile < 2 * NTILES; tile += gridDim.x) {
        const int which = tile >= NTILES;
        const size_t row0 = (size_t)(tile & (NTILES - 1)) * 256 + w * 16;
        const __half* W  = sm + which * WB_TOT;
        const __half* eh = which ? g_enc_d_hi : g_enc_s_hi;
        const __half* el = which ? g_enc_d_lo : g_enc_s_lo;

        uint32_t Ah[4][4], Al[4][4];

        layer_gmemA<2, true>(eh, el, row0, 32, W + WB_IN, 72, 32 * 72, Ah, Al);
        layer_reg<4, true >(Ah, Al, W + WB_H0,  72, 64 * 72);
        layer_reg<4, true >(Ah, Al, W + WB_H1,  72, 64 * 72);
        layer_reg<4, true >(Ah, Al, W + WB_H2,  72, 64 * 72);
        layer_reg<4, false>(Ah, Al, W + WB_OUT, 72, 64 * 72);

        stg_afrags(Ah, Al, g_feat_hi, g_feat_lo, row0, 128, which * 64);
    }
}

// ---------------------------------------------------------------------------
// Persistent merged head: feat128 -> 64 -> 64 -> 128 (+blend, regs) -> 64 -> 64 -> 1
// 148 blocks x 512 thr; loops over NTILES tiles.
// ---------------------------------------------------------------------------
#define HH2    H1_TOT
#define HHO    (HH2 + H2_TOT)
#define HEAD_SMEM ((HHO + 128) * 2)

__global__ void __launch_bounds__(512, 1)
head_tc(const float* __restrict__ alpha_p,
        const float* __restrict__ w2_out, float* __restrict__ out)
{
    extern __shared__ __align__(16) __half sm[];
    const int tid = threadIdx.x;
    float* wo = (float*)(sm + HHO);

    {
        const uint4* s1 = (const uint4*)g_wH1;
        uint4* d1 = (uint4*)sm;
        #pragma unroll 4
        for (int i = tid; i < H1_TOT / 8; i += 512) d1[i] = s1[i];
        const uint4* s2 = (const uint4*)g_wH2;
        uint4* d2 = (uint4*)(sm + HH2);
        #pragma unroll 4
        for (int i = tid; i < H2_TOT / 8; i += 512) d2[i] = s2[i];
        for (int i = tid; i < 64; i += 512) wo[i] = w2_out[i];
    }
    __syncthreads();

    const int w = tid >> 5;
    const int lane = tid & 31;
    const int g = lane >> 2, t2 = lane & 3;

    const float alpha = __ldg(alpha_p);
    const float beta  = 1.f - alpha;

    for (int tile = blockIdx.x; tile < NTILES; tile += gridDim.x) {
        const size_t row0 = (size_t)tile * 256 + w * 16;

        // mlp1: 128 -> 64 -> 64
        uint32_t A1h[4][4], A1l[4][4];
        layer_gmemA<8, true>(g_feat_hi, g_feat_lo, row0, 128,
                             sm + H1_IN, 72, 128 * 72, A1h, A1l);
        layer_reg<4, true>(A1h, A1l, sm + H1_H, 72, 64 * 72);

        // w1_out (64 -> 128) per 64-col half: blend vs original F (fp32),
        // convert to fragments, fold straight into mlp2-in accumulation.
        float acc2[8][4];
        #pragma unroll
        for (int t = 0; t < 8; t++)
            #pragma unroll
            for (int j = 0; j < 4; j++) acc2[t][j] = 0.f;

        #pragma unroll
        for (int half = 0; half < 2; half++) {
            const int noff = half * 64;
            float accO[8][4];
            #pragma unroll
            for (int t = 0; t < 8; t++)
                #pragma unroll
                for (int j = 0; j < 4; j++) accO[t][j] = 0.f;

            #pragma unroll
            for (int kk = 0; kk < 4; kk++) {
                const __half* Wb = sm + H1_OUT + noff;
                const __half* wrow = Wb + (kk * 16 + (lane & 7) + ((lane >> 3) & 1) * 8) * 136
                                   + ((lane >> 4) << 3);
                #pragma unroll
                for (int nb = 0; nb < 4; nb++) {
                    uint32_t bh0, bh1, bh2, bh3, bl0, bl1, bl2, bl3;
                    ldsm_x4_t(bh0, bh1, bh2, bh3, smem_u32(wrow + nb * 16));
                    ldsm_x4_t(bl0, bl1, bl2, bl3, smem_u32(wrow + nb * 16 + 64 * 136));
                    mma16816(accO[2 * nb + 0], A1h[kk], bh0, bh1);
                    mma16816(accO[2 * nb + 0], A1h[kk], bl0, bl1);
                    mma16816(accO[2 * nb + 0], A1l[kk], bh0, bh1);
                    mma16816(accO[2 * nb + 1], A1h[kk], bh2, bh3);
                    mma16816(accO[2 * nb + 1], A1h[kk], bl2, bl3);
                    mma16816(accO[2 * nb + 1], A1l[kk], bh2, bh3);
                }
            }

            uint32_t Fh[4][4], Fl[4][4];
            #pragma unroll
            for (int j = 0; j < 4; j++)
                #pragma unroll
                for (int q = 0; q < 4; q++) {
                    float v0 = accO[2 * j + (q >> 1)][(q & 1) * 2 + 0];
                    float v1 = accO[2 * j + (q >> 1)][(q & 1) * 2 + 1];
                    const size_t r = row0 + g + ((q & 1) ? 8 : 0);
                    const int    c = noff + j * 16 + ((q >> 1) ? 8 : 0) + t2 * 2;
                    const size_t off = r * 128 + c;
                    uint32_t fh = *(const uint32_t*)(g_feat_hi + off);
                    uint32_t fl = *(const uint32_t*)(g_feat_lo + off);
                    float2 vh = __half22float2(*reinterpret_cast<__half2*>(&fh));
                    float2 vl = __half22float2(*reinterpret_cast<__half2*>(&fl));
                    v0 = v0 * alpha + beta * (vh.x + vl.x);
                    v1 = v1 * alpha + beta * (vh.y + vl.y);
                    __half h0, l0, h1, l1;
                    split2(v0, h0, l0);
                    split2(v1, h1, l1);
                    Fh[j][q] = pack2(h0, h1);
                    Fl[j][q] = pack2(l0, l1);
                }

            #pragma unroll
            for (int kk = 0; kk < 4; kk++)
                ktile_mma(sm + HH2 + H2_IN, 72, 128 * 72, noff + kk * 16,
                          Fh[kk], Fl[kk], acc2);
        }

        // mlp2: -> 64 (relu) -> 64 (relu)
        uint32_t A2h[4][4], A2l[4][4];
        convert_acc<true>(acc2, A2h, A2l);
        layer_reg<4, true>(A2h, A2l, sm + HH2 + H2_H, 72, 64 * 72);

        // final 64 -> 1 from register fragments (fp32)
        {
            float sg = 0.f, sg8 = 0.f;
            #pragma unroll
            for (int j = 0; j < 4; j++)
                #pragma unroll
                for (int q = 0; q < 4; q++) {
                    __half2 hv = *reinterpret_cast<__half2*>(&A2h[j][q]);
                    __half2 lv = *reinterpret_cast<__half2*>(&A2l[j][q]);
                    float2 vh = __half22float2(hv);
                    float2 vl = __half22float2(lv);
                    int c = j * 16 + ((q >> 1) << 3) + t2 * 2;
                    float d = fmaf(vh.x + vl.x, wo[c], (vh.y + vl.y) * wo[c + 1]);
                    if ((q & 1) == 0) sg += d; else sg8 += d;
                }
            sg  += __shfl_xor_sync(0xffffffffu, sg, 1);
            sg  += __shfl_xor_sync(0xffffffffu, sg, 2);
            sg8 += __shfl_xor_sync(0xffffffffu, sg8, 1);
            sg8 += __shfl_xor_sync(0xffffffffu, sg8, 2);
            if (t2 == 0) {
                out[row0 + g]     = sg;
                out[row0 + g + 8] = sg8;
            }
        }
    }
}

// ---------------------------------------------------------------------------
// Launch (strictly serial — R5 showed L1-bound kernels must not overlap)
// ---------------------------------------------------------------------------
extern "C" void kernel_launch(void* const* d_in, const int* in_sizes, int n_in,
                              void* d_out, int out_size)
{
    const float* x       = (const float*)d_in[0];
    const float* t       = (const float*)d_in[1];
    const float* alpha   = (const float*)d_in[2];
    const float* table_s = (const float*)d_in[3];
    const float* ws_in   = (const float*)d_in[4];
    const float* ws_hid  = (const float*)d_in[5];
    const float* ws_out  = (const float*)d_in[6];
    const float* table_d = (const float*)d_in[7];
    const float* wd_in   = (const float*)d_in[8];
    const float* wd_hid  = (const float*)d_in[9];
    const float* wd_out  = (const float*)d_in[10];
    const float* w1_in   = (const float*)d_in[11];
    const float* w1_hid  = (const float*)d_in[12];
    const float* w1_out  = (const float*)d_in[13];
    const float* w2_in   = (const float*)d_in[14];
    const float* w2_hid  = (const float*)d_in[15];
    const float* w2_out  = (const float*)d_in[16];
    float* out = (float*)d_out;

    cudaFuncSetAttribute(mlp64_all, cudaFuncAttributeMaxDynamicSharedMemorySize, MLPALL_SMEM);
    cudaFuncSetAttribute(head_tc,   cudaFuncAttributeMaxDynamicSharedMemorySize, HEAD_SMEM);

    const int nblkENC = NPTS / 256;

    prep_weights<<<64, 256>>>(ws_in, ws_hid, ws_out, wd_in, wd_hid, wd_out,
                              w1_in, w1_hid, w1_out, w2_in, w2_hid);

    encode_kernel<3, 0><<<nblkENC, 256>>>(x, nullptr, table_s);
    encode_kernel<4, 1><<<nblkENC, 256>>>(x, t, table_d);

    mlp64_all<<<PGRID, 512, MLPALL_SMEM>>>();
    head_tc<<<PGRID, 512, HEAD_SMEM>>>(alpha, w2_out, out);
}

// round 13
// speedup vs baseline: 1.4558x; 1.0511x over previous
#include <cuda_runtime.h>
#include <cuda_fp16.h>
#include <cstdint>

// ---------------------------------------------------------------------------
// Problem constants
// ---------------------------------------------------------------------------
#define NPTS   524288
#define LVLS   16
#define TSIZE  524288u
#define TMASK  (TSIZE - 1u)
#define NTILES 2048          // 256-point tiles
#define PGRID  148           // persistent grid = #SMs

__constant__ float c_res[LVLS] = {
    16.f, 24.f, 36.f, 54.f, 81.f, 121.f, 182.f, 273.f,
    410.f, 615.f, 922.f, 1383.f, 2075.f, 3113.f, 4670.f, 7006.f
};

// ---------------------------------------------------------------------------
// Scratch (device globals; no runtime allocation)
// Fragment layout: value32(r16, j, q, lane) at  ((r16*JS + j)*4 + q)*32 + lane
//   r16 = point row / 16, j = 16-col k-tile, q = frag reg index, lane = owner.
//   enc: JS = 2 (32 cols);  feat: JS = 8 (128 cols).
// ---------------------------------------------------------------------------
__device__ __align__(16) uint32_t g_enc_s_hi[(size_t)NPTS * 16];
__device__ __align__(16) uint32_t g_enc_s_lo[(size_t)NPTS * 16];
__device__ __align__(16) uint32_t g_enc_d_hi[(size_t)NPTS * 16];
__device__ __align__(16) uint32_t g_enc_d_lo[(size_t)NPTS * 16];
__device__ __align__(16) uint32_t g_feat_hi [(size_t)NPTS * 64];
__device__ __align__(16) uint32_t g_feat_lo [(size_t)NPTS * 64];

// Pre-split weight blobs (hi plane, lo plane at +rows*stride), stride 72/136
#define WB_IN   0
#define WB_H0   4608
#define WB_H1   13824
#define WB_H2   23040
#define WB_OUT  32256
#define WB_TOT  41472
__device__ __align__(16) __half g_wS[WB_TOT];
__device__ __align__(16) __half g_wD[WB_TOT];
#define H1_IN   0
#define H1_H    18432
#define H1_OUT  27648
#define H1_TOT  45056
__device__ __align__(16) __half g_wH1[H1_TOT];
#define H2_IN   0
#define H2_H    18432
#define H2_TOT  27648
__device__ __align__(16) __half g_wH2[H2_TOT];

// ---------------------------------------------------------------------------
__device__ __forceinline__ void split2(float x, __half& h, __half& l) {
    h = __float2half_rn(x);
    l = __float2half_rn(x - __half2float(h));
}

__device__ __forceinline__ uint32_t pack2(__half a, __half b) {
    __half2 v = __halves2half2(a, b);
    return *reinterpret_cast<uint32_t*>(&v);
}

__device__ __forceinline__ void conv_w(__half* dst, const float* __restrict__ src,
                                       int K, int N, int ws, int t0, int nt)
{
    const int tot = K * N / 2;
    const int pl  = K * ws;
    const float2* s2 = (const float2*)src;
    for (int i = t0; i < tot; i += nt) {
        int r = (2 * i) / N, c = (2 * i) % N;
        float2 v = s2[i];
        __half hx, lx, hy, ly;
        split2(v.x, hx, lx);
        split2(v.y, hy, ly);
        *(__half2*)(dst + r * ws + c)      = __halves2half2(hx, hy);
        *(__half2*)(dst + r * ws + pl + c) = __halves2half2(lx, ly);
    }
}

__global__ void __launch_bounds__(256)
prep_weights(const float* __restrict__ ws_in, const float* __restrict__ ws_hid,
             const float* __restrict__ ws_out,
             const float* __restrict__ wd_in, const float* __restrict__ wd_hid,
             const float* __restrict__ wd_out,
             const float* __restrict__ w1_in, const float* __restrict__ w1_hid,
             const float* __restrict__ w1_out,
             const float* __restrict__ w2_in, const float* __restrict__ w2_hid)
{
    const int t0 = blockIdx.x * 256 + threadIdx.x;
    const int nt = gridDim.x * 256;
    conv_w(g_wS + WB_IN,  ws_in,         32, 64, 72, t0, nt);
    conv_w(g_wS + WB_H0,  ws_hid + 0,    64, 64, 72, t0, nt);
    conv_w(g_wS + WB_H1,  ws_hid + 4096, 64, 64, 72, t0, nt);
    conv_w(g_wS + WB_H2,  ws_hid + 8192, 64, 64, 72, t0, nt);
    conv_w(g_wS + WB_OUT, ws_out,        64, 64, 72, t0, nt);
    conv_w(g_wD + WB_IN,  wd_in,         32, 64, 72, t0, nt);
    conv_w(g_wD + WB_H0,  wd_hid + 0,    64, 64, 72, t0, nt);
    conv_w(g_wD + WB_H1,  wd_hid + 4096, 64, 64, 72, t0, nt);
    conv_w(g_wD + WB_H2,  wd_hid + 8192, 64, 64, 72, t0, nt);
    conv_w(g_wD + WB_OUT, wd_out,        64, 64, 72, t0, nt);
    conv_w(g_wH1 + H1_IN,  w1_in,  128, 64,  72,  t0, nt);
    conv_w(g_wH1 + H1_H,   w1_hid, 64,  64,  72,  t0, nt);
    conv_w(g_wH1 + H1_OUT, w1_out, 64,  128, 136, t0, nt);
    conv_w(g_wH2 + H2_IN,  w2_in,  128, 64,  72,  t0, nt);
    conv_w(g_wH2 + H2_H,   w2_hid, 64,  64,  72,  t0, nt);
}

// ---------------------------------------------------------------------------
// Hash-grid encode with dim-0 corner-pair merging (PRIMES[0] == 1).
// Output written directly in fragment layout (JS = 2).
// ---------------------------------------------------------------------------
template <int D, int WHICH>
__global__ void __launch_bounds__(256)
encode_kernel(const float* __restrict__ x,
              const float* __restrict__ tptr,
              const float* __restrict__ table)
{
    const int n = blockIdx.x * 256 + threadIdx.x;

    float p[4];
    p[0] = x[3 * n + 0];
    p[1] = x[3 * n + 1];
    p[2] = x[3 * n + 2];
    if (D == 4) p[3] = __ldg(tptr);

    uint32_t ehi[16], elo[16];   // packed col-pair values (cols 2i, 2i+1)

    #pragma unroll
    for (int l = 0; l < LVLS; l++) {
        const float res = c_res[l];
        uint32_t h[4][2];
        float    w[4][2];
        uint32_t p0u = 0;
        #pragma unroll
        for (int d = 0; d < D; d++) {
            const uint32_t pr = (d == 0) ? 1u
                              : (d == 1) ? 2654435761u
                              : (d == 2) ? 805459861u
                                         : 3674653429u;
            float pos = p[d] * res;
            float p0f = floorf(pos);
            float fr  = pos - p0f;
            uint32_t p0 = (uint32_t)p0f;
            if (d == 0) p0u = p0;
            h[d][0] = p0 * pr;
            h[d][1] = (p0 + 1u) * pr;
            w[d][0] = 1.f - fr;
            w[d][1] = fr;
        }

        const float2* tl = (const float2*)table + (size_t)l * TSIZE;
        float f0 = 0.f, f1 = 0.f;
        const float w00 = w[0][0], w01 = w[0][1];

        if ((p0u & 1u) == 0u) {
            #pragma unroll
            for (int rc = 0; rc < (1 << (D - 1)); rc++) {
                uint32_t A = h[1][rc & 1] ^ h[2][(rc >> 1) & 1];
                float   Wr = w[1][rc & 1] * w[2][(rc >> 1) & 1];
                if (D == 4) {
                    A  ^= h[3][(rc >> 2) & 1];
                    Wr *= w[3][(rc >> 2) & 1];
                }
                uint32_t i0 = (A ^ h[0][0]) & TMASK;
                float4 v = __ldg((const float4*)tl + (i0 >> 1));
                const bool hi = (i0 & 1u);
                float e0x = hi ? v.z : v.x, e0y = hi ? v.w : v.y;
                float e1x = hi ? v.x : v.z, e1y = hi ? v.y : v.w;
                float wa = w00 * Wr, wb = w01 * Wr;
                f0 = fmaf(wa, e0x, f0);
                f1 = fmaf(wa, e0y, f1);
                f0 = fmaf(wb, e1x, f0);
                f1 = fmaf(wb, e1y, f1);
            }
        } else {
            #pragma unroll
            for (int rc = 0; rc < (1 << (D - 1)); rc++) {
                uint32_t A = h[1][rc & 1] ^ h[2][(rc >> 1) & 1];
                float   Wr = w[1][rc & 1] * w[2][(rc >> 1) & 1];
                if (D == 4) {
                    A  ^= h[3][(rc >> 2) & 1];
                    Wr *= w[3][(rc >> 2) & 1];
                }
                uint32_t i0 = (A ^ h[0][0]) & TMASK;
                uint32_t i1 = (A ^ h[0][1]) & TMASK;
                float2 e0 = __ldg(tl + i0);
                float2 e1 = __ldg(tl + i1);
                float wa = w00 * Wr, wb = w01 * Wr;
                f0 = fmaf(wa, e0.x, f0);
                f1 = fmaf(wa, e0.y, f1);
                f0 = fmaf(wb, e1.x, f0);
                f1 = fmaf(wb, e1.y, f1);
            }
        }

        __half h0, l0, h1, l1;
        split2(f0, h0, l0);
        split2(f1, h1, l1);
        ehi[l] = pack2(h0, h1);
        elo[l] = pack2(l0, l1);
    }

    // Fragment-layout store: thread (row r = n%16) supplies q = hi8 (low 8 cols
    // of each j) and q = hi8+2 (high 8 cols); lane index = g*4 + t2.
    uint32_t* dh = (WHICH == 0 ? g_enc_s_hi : g_enc_d_hi);
    uint32_t* dl = (WHICH == 0 ? g_enc_s_lo : g_enc_d_lo);
    const size_t r16 = (size_t)(n >> 4);
    const int g   = n & 7;
    const int hi8 = (n >> 3) & 1;
    #pragma unroll
    for (int j = 0; j < 2; j++) {
        size_t b0 = ((r16 * 2 + j) * 4 + hi8) * 32 + g * 4;       // cols j*16+0..7
        size_t b1 = ((r16 * 2 + j) * 4 + hi8 + 2) * 32 + g * 4;   // cols j*16+8..15
        *(uint4*)(dh + b0) = make_uint4(ehi[j*8+0], ehi[j*8+1], ehi[j*8+2], ehi[j*8+3]);
        *(uint4*)(dh + b1) = make_uint4(ehi[j*8+4], ehi[j*8+5], ehi[j*8+6], ehi[j*8+7]);
        *(uint4*)(dl + b0) = make_uint4(elo[j*8+0], elo[j*8+1], elo[j*8+2], elo[j*8+3]);
        *(uint4*)(dl + b1) = make_uint4(elo[j*8+4], elo[j*8+5], elo[j*8+6], elo[j*8+7]);
    }
}

// ---------------------------------------------------------------------------
// Tensor-core primitives
// ---------------------------------------------------------------------------
__device__ __forceinline__ uint32_t smem_u32(const void* p) {
    return (uint32_t)__cvta_generic_to_shared(p);
}

__device__ __forceinline__ void ldsm_x4_t(uint32_t& r0, uint32_t& r1,
                                          uint32_t& r2, uint32_t& r3, uint32_t a) {
    asm volatile("ldmatrix.sync.aligned.m8n8.x4.trans.shared.b16 {%0,%1,%2,%3}, [%4];"
                 : "=r"(r0), "=r"(r1), "=r"(r2), "=r"(r3) : "r"(a));
}

__device__ __forceinline__ void mma16816(float* c, const uint32_t* a,
                                         uint32_t b0, uint32_t b1) {
    asm volatile(
        "mma.sync.aligned.m16n8k16.row.col.f32.f16.f16.f32 "
        "{%0,%1,%2,%3}, {%4,%5,%6,%7}, {%8,%9}, {%0,%1,%2,%3};"
        : "+f"(c[0]), "+f"(c[1]), "+f"(c[2]), "+f"(c[3])
        : "r"(a[0]), "r"(a[1]), "r"(a[2]), "r"(a[3]), "r"(b0), "r"(b1));
}

// One k-tile of split-MMA: A (hi/lo) x W rows [krow..krow+16) -> acc[8][4]
__device__ __forceinline__ void ktile_mma(const __half* W, int ws, int wpl, int krow,
                                          const uint32_t* ah, const uint32_t* al,
                                          float (*acc)[4])
{
    const int lane = threadIdx.x & 31;
    #pragma unroll
    for (int nb = 0; nb < 4; nb++) {
        const __half* wp = W + (krow + (lane & 7) + ((lane >> 3) & 1) * 8) * ws
                         + nb * 16 + ((lane >> 4) << 3);
        uint32_t bh0, bh1, bh2, bh3, bl0, bl1, bl2, bl3;
        ldsm_x4_t(bh0, bh1, bh2, bh3, smem_u32(wp));
        ldsm_x4_t(bl0, bl1, bl2, bl3, smem_u32(wp + wpl));
        mma16816(acc[2 * nb + 0], ah, bh0, bh1);
        mma16816(acc[2 * nb + 0], ah, bl0, bl1);
        mma16816(acc[2 * nb + 0], al, bh0, bh1);
        mma16816(acc[2 * nb + 1], ah, bh2, bh3);
        mma16816(acc[2 * nb + 1], ah, bl2, bl3);
        mma16816(acc[2 * nb + 1], al, bh2, bh3);
    }
}

// Fragment load/store in slab layout: slab = r16*JS + j; q-slabs 32 words apart.
__device__ __forceinline__ void ldfrag(const uint32_t* __restrict__ base,
                                       size_t slab, uint32_t* a)
{
    const int lane = threadIdx.x & 31;
    const uint32_t* pp = base + slab * 128 + lane;
    a[0] = pp[0];
    a[1] = pp[32];
    a[2] = pp[64];
    a[3] = pp[96];
}

__device__ __forceinline__ void stfrag(uint32_t* __restrict__ base,
                                       size_t slab, const uint32_t* a)
{
    const int lane = threadIdx.x & 31;
    uint32_t* pp = base + slab * 128 + lane;
    pp[0]  = a[0];
    pp[32] = a[1];
    pp[64] = a[2];
    pp[96] = a[3];
}

// ---------------------------------------------------------------------------
// acc -> A-fragment conversion (identity: n-pair {2j,2j+1} == k-tile j)
// ---------------------------------------------------------------------------
template <bool RELU>
__device__ __forceinline__ void convert_acc(float (*acc)[4],
                                            uint32_t (*Ah)[4],
                                            uint32_t (*Al)[4])
{
    #pragma unroll
    for (int j = 0; j < 4; j++)
        #pragma unroll
        for (int q = 0; q < 4; q++) {
            float v0 = acc[2 * j + (q >> 1)][(q & 1) * 2 + 0];
            float v1 = acc[2 * j + (q >> 1)][(q & 1) * 2 + 1];
            if (RELU) { v0 = fmaxf(v0, 0.f); v1 = fmaxf(v1, 0.f); }
            __half h0, l0, h1, l1;
            split2(v0, h0, l0);
            split2(v1, h1, l1);
            Ah[j][q] = pack2(h0, h1);
            Al[j][q] = pack2(l0, l1);
        }
}

// Layer with A in registers: K = KT*16 -> N = 64 (in-place A update)
template <int KT, bool RELU>
__device__ __forceinline__ void layer_reg(uint32_t (*Ah)[4], uint32_t (*Al)[4],
                                          const __half* W, int ws, int wpl)
{
    float acc[8][4];
    #pragma unroll
    for (int t = 0; t < 8; t++)
        #pragma unroll
        for (int j = 0; j < 4; j++) acc[t][j] = 0.f;
    #pragma unroll
    for (int kk = 0; kk < KT; kk++)
        ktile_mma(W, ws, wpl, kk * 16, Ah[kk], Al[kk], acc);
    convert_acc<RELU>(acc, Ah, Al);
}

// Layer with A fragments loaded from fragment-layout gmem (hi/lo planes).
// slab base = r16*JS; k-tile kk uses slab base + kk.
template <int KT, bool RELU>
__device__ __forceinline__ void layer_gfrag(const uint32_t* __restrict__ bh,
                                            const uint32_t* __restrict__ bl,
                                            size_t slab0,
                                            const __half* W, int ws, int wpl,
                                            uint32_t (*Ah)[4], uint32_t (*Al)[4])
{
    float acc[8][4];
    #pragma unroll
    for (int t = 0; t < 8; t++)
        #pragma unroll
        for (int j = 0; j < 4; j++) acc[t][j] = 0.f;
    #pragma unroll
    for (int kk = 0; kk < KT; kk++) {
        uint32_t th[4], tl[4];
        ldfrag(bh, slab0 + kk, th);
        ldfrag(bl, slab0 + kk, tl);
        ktile_mma(W, ws, wpl, kk * 16, th, tl, acc);
    }
    convert_acc<RELU>(acc, Ah, Al);
}

// ---------------------------------------------------------------------------
// Persistent branch MLP: both S and D blobs resident; 148 blocks x 512 thr;
// each block loops over 2*NTILES point-tiles (256 pts each, 16 pts/warp).
// ---------------------------------------------------------------------------
#define MLPALL_SMEM (WB_TOT * 2 * 2)

__global__ void __launch_bounds__(512, 1)
mlp64_all()
{
    extern __shared__ __align__(16) __half sm[];
    const int tid = threadIdx.x;

    {
        const uint4* s0 = (const uint4*)g_wS;
        const uint4* s1 = (const uint4*)g_wD;
        uint4* d0 = (uint4*)sm;
        uint4* d1 = (uint4*)(sm + WB_TOT);
        #pragma unroll 4
        for (int i = tid; i < WB_TOT / 8; i += 512) { d0[i] = s0[i]; d1[i] = s1[i]; }
    }
    __syncthreads();

    const int w = tid >> 5;

    for (int tile = blockIdx.x; tile < 2 * NTILES; tile += gridDim.x) {
        const int which = tile >= NTILES;
        const size_t r16 = (size_t)(tile & (NTILES - 1)) * 16 + w;
        const __half* W  = sm + which * WB_TOT;
        const uint32_t* eh = which ? g_enc_d_hi : g_enc_s_hi;
        const uint32_t* el = which ? g_enc_d_lo : g_enc_s_lo;

        uint32_t Ah[4][4], Al[4][4];

        layer_gfrag<2, true>(eh, el, r16 * 2, W + WB_IN, 72, 32 * 72, Ah, Al);
        layer_reg<4, true >(Ah, Al, W + WB_H0,  72, 64 * 72);
        layer_reg<4, true >(Ah, Al, W + WB_H1,  72, 64 * 72);
        layer_reg<4, true >(Ah, Al, W + WB_H2,  72, 64 * 72);
        layer_reg<4, false>(Ah, Al, W + WB_OUT, 72, 64 * 72);

        // fragment-layout store to feat: k-tiles which*4 + j
        #pragma unroll
        for (int j = 0; j < 4; j++) {
            stfrag(g_feat_hi, r16 * 8 + which * 4 + j, Ah[j]);
            stfrag(g_feat_lo, r16 * 8 + which * 4 + j, Al[j]);
        }
    }
}

// ---------------------------------------------------------------------------
// Persistent merged head: feat128 -> 64 -> 64 -> 128 (+blend, regs) -> 64 -> 64 -> 1
// 148 blocks x 512 thr; loops over NTILES tiles.
// ---------------------------------------------------------------------------
#define HH2    H1_TOT
#define HHO    (HH2 + H2_TOT)
#define HEAD_SMEM ((HHO + 128) * 2)

__global__ void __launch_bounds__(512, 1)
head_tc(const float* __restrict__ alpha_p,
        const float* __restrict__ w2_out, float* __restrict__ out)
{
    extern __shared__ __align__(16) __half sm[];
    const int tid = threadIdx.x;
    float* wo = (float*)(sm + HHO);

    {
        const uint4* s1 = (const uint4*)g_wH1;
        uint4* d1 = (uint4*)sm;
        #pragma unroll 4
        for (int i = tid; i < H1_TOT / 8; i += 512) d1[i] = s1[i];
        const uint4* s2 = (const uint4*)g_wH2;
        uint4* d2 = (uint4*)(sm + HH2);
        #pragma unroll 4
        for (int i = tid; i < H2_TOT / 8; i += 512) d2[i] = s2[i];
        for (int i = tid; i < 64; i += 512) wo[i] = w2_out[i];
    }
    __syncthreads();

    const int w = tid >> 5;
    const int lane = tid & 31;
    const int g = lane >> 2, t2 = lane & 3;

    const float alpha = __ldg(alpha_p);
    const float beta  = 1.f - alpha;

    for (int tile = blockIdx.x; tile < NTILES; tile += gridDim.x) {
        const size_t r16  = (size_t)tile * 16 + w;
        const size_t row0 = r16 * 16;

        // mlp1: 128 -> 64 -> 64
        uint32_t A1h[4][4], A1l[4][4];
        layer_gfrag<8, true>(g_feat_hi, g_feat_lo, r16 * 8,
                             sm + H1_IN, 72, 128 * 72, A1h, A1l);
        layer_reg<4, true>(A1h, A1l, sm + H1_H, 72, 64 * 72);

        // w1_out (64 -> 128) per 64-col half: blend vs original F (fp32),
        // convert to fragments, fold straight into mlp2-in accumulation.
        float acc2[8][4];
        #pragma unroll
        for (int t = 0; t < 8; t++)
            #pragma unroll
            for (int j = 0; j < 4; j++) acc2[t][j] = 0.f;

        #pragma unroll
        for (int half = 0; half < 2; half++) {
            const int noff = half * 64;
            float accO[8][4];
            #pragma unroll
            for (int t = 0; t < 8; t++)
                #pragma unroll
                for (int j = 0; j < 4; j++) accO[t][j] = 0.f;

            #pragma unroll
            for (int kk = 0; kk < 4; kk++) {
                const __half* Wb = sm + H1_OUT + noff;
                const __half* wrow = Wb + (kk * 16 + (lane & 7) + ((lane >> 3) & 1) * 8) * 136
                                   + ((lane >> 4) << 3);
                #pragma unroll
                for (int nb = 0; nb < 4; nb++) {
                    uint32_t bh0, bh1, bh2, bh3, bl0, bl1, bl2, bl3;
                    ldsm_x4_t(bh0, bh1, bh2, bh3, smem_u32(wrow + nb * 16));
                    ldsm_x4_t(bl0, bl1, bl2, bl3, smem_u32(wrow + nb * 16 + 64 * 136));
                    mma16816(accO[2 * nb + 0], A1h[kk], bh0, bh1);
                    mma16816(accO[2 * nb + 0], A1h[kk], bl0, bl1);
                    mma16816(accO[2 * nb + 0], A1l[kk], bh0, bh1);
                    mma16816(accO[2 * nb + 1], A1h[kk], bh2, bh3);
                    mma16816(accO[2 * nb + 1], A1h[kk], bl2, bl3);
                    mma16816(accO[2 * nb + 1], A1l[kk], bh2, bh3);
                }
            }

            // blend with original F (fragment loads, coalesced) -> fragments
            uint32_t Fh[4][4], Fl[4][4];
            #pragma unroll
            for (int j = 0; j < 4; j++) {
                uint32_t fh[4], fl[4];
                ldfrag(g_feat_hi, r16 * 8 + half * 4 + j, fh);
                ldfrag(g_feat_lo, r16 * 8 + half * 4 + j, fl);
                #pragma unroll
                for (int q = 0; q < 4; q++) {
                    float v0 = accO[2 * j + (q >> 1)][(q & 1) * 2 + 0];
                    float v1 = accO[2 * j + (q >> 1)][(q & 1) * 2 + 1];
                    float2 vh = __half22float2(*reinterpret_cast<__half2*>(&fh[q]));
                    float2 vl = __half22float2(*reinterpret_cast<__half2*>(&fl[q]));
                    v0 = v0 * alpha + beta * (vh.x + vl.x);
                    v1 = v1 * alpha + beta * (vh.y + vl.y);
                    __half h0, l0, h1, l1;
                    split2(v0, h0, l0);
                    split2(v1, h1, l1);
                    Fh[j][q] = pack2(h0, h1);
                    Fl[j][q] = pack2(l0, l1);
                }
            }

            #pragma unroll
            for (int kk = 0; kk < 4; kk++)
                ktile_mma(sm + HH2 + H2_IN, 72, 128 * 72, noff + kk * 16,
                          Fh[kk], Fl[kk], acc2);
        }

        // mlp2: -> 64 (relu) -> 64 (relu)
        uint32_t A2h[4][4], A2l[4][4];
        convert_acc<true>(acc2, A2h, A2l);
        layer_reg<4, true>(A2h, A2l, sm + HH2 + H2_H, 72, 64 * 72);

        // final 64 -> 1 from register fragments (fp32)
        {
            float sg = 0.f, sg8 = 0.f;
            #pragma unroll
            for (int j = 0; j < 4; j++)
                #pragma unroll
                for (int q = 0; q < 4; q++) {
                    __half2 hv = *reinterpret_cast<__half2*>(&A2h[j][q]);
                    __half2 lv = *reinterpret_cast<__half2*>(&A2l[j][q]);
                    float2 vh = __half22float2(hv);
                    float2 vl = __half22float2(lv);
                    int c = j * 16 + ((q >> 1) << 3) + t2 * 2;
                    float d = fmaf(vh.x + vl.x, wo[c], (vh.y + vl.y) * wo[c + 1]);
                    if ((q & 1) == 0) sg += d; else sg8 += d;
                }
            sg  += __shfl_xor_sync(0xffffffffu, sg, 1);
            sg  += __shfl_xor_sync(0xffffffffu, sg, 2);
            sg8 += __shfl_xor_sync(0xffffffffu, sg8, 1);
            sg8 += __shfl_xor_sync(0xffffffffu, sg8, 2);
            if (t2 == 0) {
                out[row0 + g]     = sg;
                out[row0 + g + 8] = sg8;
            }
        }
    }
}

// ---------------------------------------------------------------------------
// Launch (strictly serial — R5 showed L1-bound kernels must not overlap)
// ---------------------------------------------------------------------------
extern "C" void kernel_launch(void* const* d_in, const int* in_sizes, int n_in,
                              void* d_out, int out_size)
{
    const float* x       = (const float*)d_in[0];
    const float* t       = (const float*)d_in[1];
    const float* alpha   = (const float*)d_in[2];
    const float* table_s = (const float*)d_in[3];
    const float* ws_in   = (const float*)d_in[4];
    const float* ws_hid  = (const float*)d_in[5];
    const float* ws_out  = (const float*)d_in[6];
    const float* table_d = (const float*)d_in[7];
    const float* wd_in   = (const float*)d_in[8];
    const float* wd_hid  = (const float*)d_in[9];
    const float* wd_out  = (const float*)d_in[10];
    const float* w1_in   = (const float*)d_in[11];
    const float* w1_hid  = (const float*)d_in[12];
    const float* w1_out  = (const float*)d_in[13];
    const float* w2_in   = (const float*)d_in[14];
    const float* w2_hid  = (const float*)d_in[15];
    const float* w2_out  = (const float*)d_in[16];
    float* out = (float*)d_out;

    cudaFuncSetAttribute(mlp64_all, cudaFuncAttributeMaxDynamicSharedMemorySize, MLPALL_SMEM);
    cudaFuncSetAttribute(head_tc,   cudaFuncAttributeMaxDynamicSharedMemorySize, HEAD_SMEM);

    const int nblkENC = NPTS / 256;

    prep_weights<<<64, 256>>>(ws_in, ws_hid, ws_out, wd_in, wd_hid, wd_out,
                              w1_in, w1_hid, w1_out, w2_in, w2_hid);

    encode_kernel<3, 0><<<nblkENC, 256>>>(x, nullptr, table_s);
    encode_kernel<4, 1><<<nblkENC, 256>>>(x, t, table_d);

    mlp64_all<<<PGRID, 512, MLPALL_SMEM>>>();
    head_tc<<<PGRID, 512, HEAD_SMEM>>>(alpha, w2_out, out);
}

// round 14
// speedup vs baseline: 1.6445x; 1.1296x over previous
#include <cuda_runtime.h>
#include <cuda_fp16.h>
#include <cstdint>

// ---------------------------------------------------------------------------
// Problem constants
// ---------------------------------------------------------------------------
#define NPTS   524288
#define LVLS   16
#define TSIZE  524288u
#define TMASK  (TSIZE - 1u)
#define NTILES 2048          // 256-point tiles
#define PGRID  148           // persistent grid = #SMs

__constant__ float c_res[LVLS] = {
    16.f, 24.f, 36.f, 54.f, 81.f, 121.f, 182.f, 273.f,
    410.f, 615.f, 922.f, 1383.f, 2075.f, 3113.f, 4670.f, 7006.f
};

// ---------------------------------------------------------------------------
// Scratch (device globals; no runtime allocation)
// Fragment layout: value32(r16, j, q, lane) at  ((r16*JS + j)*4 + q)*32 + lane
// ---------------------------------------------------------------------------
__device__ __align__(16) uint32_t g_enc_s_hi[(size_t)NPTS * 16];
__device__ __align__(16) uint32_t g_enc_s_lo[(size_t)NPTS * 16];
__device__ __align__(16) uint32_t g_enc_d_hi[(size_t)NPTS * 16];
__device__ __align__(16) uint32_t g_enc_d_lo[(size_t)NPTS * 16];
__device__ __align__(16) uint32_t g_feat_hi [(size_t)NPTS * 64];
__device__ __align__(16) uint32_t g_feat_lo [(size_t)NPTS * 64];

// Time-folded dynamic table: T'[l][B] = wt0*T[l][B^ht0] + wt1*T[l][B^ht1]
__device__ __align__(16) float2 g_tdt[(size_t)LVLS * TSIZE];

// Pre-split weight blobs (hi plane, lo plane at +rows*stride), stride 72/136
#define WB_IN   0
#define WB_H0   4608
#define WB_H1   13824
#define WB_H2   23040
#define WB_OUT  32256
#define WB_TOT  41472
__device__ __align__(16) __half g_wS[WB_TOT];
__device__ __align__(16) __half g_wD[WB_TOT];
#define H1_IN   0
#define H1_H    18432
#define H1_OUT  27648
#define H1_TOT  45056
__device__ __align__(16) __half g_wH1[H1_TOT];
#define H2_IN   0
#define H2_H    18432
#define H2_TOT  27648
__device__ __align__(16) __half g_wH2[H2_TOT];

// ---------------------------------------------------------------------------
__device__ __forceinline__ void split2(float x, __half& h, __half& l) {
    h = __float2half_rn(x);
    l = __float2half_rn(x - __half2float(h));
}

__device__ __forceinline__ uint32_t pack2(__half a, __half b) {
    __half2 v = __halves2half2(a, b);
    return *reinterpret_cast<uint32_t*>(&v);
}

__device__ __forceinline__ void conv_w(__half* dst, const float* __restrict__ src,
                                       int K, int N, int ws, int t0, int nt)
{
    const int tot = K * N / 2;
    const int pl  = K * ws;
    const float2* s2 = (const float2*)src;
    for (int i = t0; i < tot; i += nt) {
        int r = (2 * i) / N, c = (2 * i) % N;
        float2 v = s2[i];
        __half hx, lx, hy, ly;
        split2(v.x, hx, lx);
        split2(v.y, hy, ly);
        *(__half2*)(dst + r * ws + c)      = __halves2half2(hx, hy);
        *(__half2*)(dst + r * ws + pl + c) = __halves2half2(lx, ly);
    }
}

__global__ void __launch_bounds__(256)
prep_weights(const float* __restrict__ ws_in, const float* __restrict__ ws_hid,
             const float* __restrict__ ws_out,
             const float* __restrict__ wd_in, const float* __restrict__ wd_hid,
             const float* __restrict__ wd_out,
             const float* __restrict__ w1_in, const float* __restrict__ w1_hid,
             const float* __restrict__ w1_out,
             const float* __restrict__ w2_in, const float* __restrict__ w2_hid)
{
    const int t0 = blockIdx.x * 256 + threadIdx.x;
    const int nt = gridDim.x * 256;
    conv_w(g_wS + WB_IN,  ws_in,         32, 64, 72, t0, nt);
    conv_w(g_wS + WB_H0,  ws_hid + 0,    64, 64, 72, t0, nt);
    conv_w(g_wS + WB_H1,  ws_hid + 4096, 64, 64, 72, t0, nt);
    conv_w(g_wS + WB_H2,  ws_hid + 8192, 64, 64, 72, t0, nt);
    conv_w(g_wS + WB_OUT, ws_out,        64, 64, 72, t0, nt);
    conv_w(g_wD + WB_IN,  wd_in,         32, 64, 72, t0, nt);
    conv_w(g_wD + WB_H0,  wd_hid + 0,    64, 64, 72, t0, nt);
    conv_w(g_wD + WB_H1,  wd_hid + 4096, 64, 64, 72, t0, nt);
    conv_w(g_wD + WB_H2,  wd_hid + 8192, 64, 64, 72, t0, nt);
    conv_w(g_wD + WB_OUT, wd_out,        64, 64, 72, t0, nt);
    conv_w(g_wH1 + H1_IN,  w1_in,  128, 64,  72,  t0, nt);
    conv_w(g_wH1 + H1_H,   w1_hid, 64,  64,  72,  t0, nt);
    conv_w(g_wH1 + H1_OUT, w1_out, 64,  128, 136, t0, nt);
    conv_w(g_wH2 + H2_IN,  w2_in,  128, 64,  72,  t0, nt);
    conv_w(g_wH2 + H2_H,   w2_hid, 64,  64,  72,  t0, nt);
}

// ---------------------------------------------------------------------------
// Fold the (scalar) time dimension into the dynamic table.
// grid covers LVLS*TSIZE entries; XOR-permutation reads are line-local.
// ---------------------------------------------------------------------------
__global__ void __launch_bounds__(256)
combine_time(const float* __restrict__ table_d, const float* __restrict__ tptr)
{
    const size_t i = (size_t)blockIdx.x * 256 + threadIdx.x;
    const int    l = (int)(i >> 19);          // TSIZE = 2^19
    const uint32_t B = (uint32_t)i & TMASK;

    const float t   = __ldg(tptr);
    float pos = t * c_res[l];
    float p0f = floorf(pos);
    float fr  = pos - p0f;
    uint32_t p3 = (uint32_t)p0f;
    const uint32_t P3 = 3674653429u;
    uint32_t ht0 = (p3 * P3) & TMASK;
    uint32_t ht1 = ((p3 + 1u) * P3) & TMASK;

    const float2* tl = (const float2*)table_d + (size_t)l * TSIZE;
    float2 a = __ldg(tl + (B ^ ht0));
    float2 b = __ldg(tl + (B ^ ht1));
    const float w0 = 1.f - fr, w1 = fr;
    g_tdt[i] = make_float2(w0 * a.x + w1 * b.x, w0 * a.y + w1 * b.y);
}

// ---------------------------------------------------------------------------
// Hash-grid encode, 3 spatial dims (WHICH=0: static table; WHICH=1: time-folded
// dynamic table g_tdt).  dim-0 corner-pair merge (PRIMES[0]==1) when p0 even.
// Output written directly in fragment layout (JS = 2).
// ---------------------------------------------------------------------------
template <int WHICH>
__global__ void __launch_bounds__(256)
encode_kernel(const float* __restrict__ x,
              const float* __restrict__ table)
{
    const int n = blockIdx.x * 256 + threadIdx.x;

    float p[3];
    p[0] = x[3 * n + 0];
    p[1] = x[3 * n + 1];
    p[2] = x[3 * n + 2];

    uint32_t ehi[16], elo[16];

    #pragma unroll
    for (int l = 0; l < LVLS; l++) {
        const float res = c_res[l];
        uint32_t h[3][2];
        float    w[3][2];
        uint32_t p0u = 0;
        #pragma unroll
        for (int d = 0; d < 3; d++) {
            const uint32_t pr = (d == 0) ? 1u
                              : (d == 1) ? 2654435761u
                                         : 805459861u;
            float pos = p[d] * res;
            float p0f = floorf(pos);
            float fr  = pos - p0f;
            uint32_t p0 = (uint32_t)p0f;
            if (d == 0) p0u = p0;
            h[d][0] = p0 * pr;
            h[d][1] = (p0 + 1u) * pr;
            w[d][0] = 1.f - fr;
            w[d][1] = fr;
        }

        const float2* tl = (WHICH == 0)
            ? (const float2*)table + (size_t)l * TSIZE
            : (const float2*)g_tdt + (size_t)l * TSIZE;
        float f0 = 0.f, f1 = 0.f;
        const float w00 = w[0][0], w01 = w[0][1];

        if ((p0u & 1u) == 0u) {
            #pragma unroll
            for (int rc = 0; rc < 4; rc++) {
                uint32_t A = h[1][rc & 1] ^ h[2][(rc >> 1) & 1];
                float   Wr = w[1][rc & 1] * w[2][(rc >> 1) & 1];
                uint32_t i0 = (A ^ h[0][0]) & TMASK;
                float4 v = __ldg((const float4*)tl + (i0 >> 1));
                const bool hi = (i0 & 1u);
                float e0x = hi ? v.z : v.x, e0y = hi ? v.w : v.y;
                float e1x = hi ? v.x : v.z, e1y = hi ? v.y : v.w;
                float wa = w00 * Wr, wb = w01 * Wr;
                f0 = fmaf(wa, e0x, f0);
                f1 = fmaf(wa, e0y, f1);
                f0 = fmaf(wb, e1x, f0);
                f1 = fmaf(wb, e1y, f1);
            }
        } else {
            #pragma unroll
            for (int rc = 0; rc < 4; rc++) {
                uint32_t A = h[1][rc & 1] ^ h[2][(rc >> 1) & 1];
                float   Wr = w[1][rc & 1] * w[2][(rc >> 1) & 1];
                uint32_t i0 = (A ^ h[0][0]) & TMASK;
                uint32_t i1 = (A ^ h[0][1]) & TMASK;
                float2 e0 = __ldg(tl + i0);
                float2 e1 = __ldg(tl + i1);
                float wa = w00 * Wr, wb = w01 * Wr;
                f0 = fmaf(wa, e0.x, f0);
                f1 = fmaf(wa, e0.y, f1);
                f0 = fmaf(wb, e1.x, f0);
                f1 = fmaf(wb, e1.y, f1);
            }
        }

        __half h0, l0, h1, l1;
        split2(f0, h0, l0);
        split2(f1, h1, l1);
        ehi[l] = pack2(h0, h1);
        elo[l] = pack2(l0, l1);
    }

    uint32_t* dh = (WHICH == 0 ? g_enc_s_hi : g_enc_d_hi);
    uint32_t* dl = (WHICH == 0 ? g_enc_s_lo : g_enc_d_lo);
    const size_t r16 = (size_t)(n >> 4);
    const int g   = n & 7;
    const int hi8 = (n >> 3) & 1;
    #pragma unroll
    for (int j = 0; j < 2; j++) {
        size_t b0 = ((r16 * 2 + j) * 4 + hi8) * 32 + g * 4;
        size_t b1 = ((r16 * 2 + j) * 4 + hi8 + 2) * 32 + g * 4;
        *(uint4*)(dh + b0) = make_uint4(ehi[j*8+0], ehi[j*8+1], ehi[j*8+2], ehi[j*8+3]);
        *(uint4*)(dh + b1) = make_uint4(ehi[j*8+4], ehi[j*8+5], ehi[j*8+6], ehi[j*8+7]);
        *(uint4*)(dl + b0) = make_uint4(elo[j*8+0], elo[j*8+1], elo[j*8+2], elo[j*8+3]);
        *(uint4*)(dl + b1) = make_uint4(elo[j*8+4], elo[j*8+5], elo[j*8+6], elo[j*8+7]);
    }
}

// ---------------------------------------------------------------------------
// Tensor-core primitives
// ---------------------------------------------------------------------------
__device__ __forceinline__ uint32_t smem_u32(const void* p) {
    return (uint32_t)__cvta_generic_to_shared(p);
}

__device__ __forceinline__ void ldsm_x4_t(uint32_t& r0, uint32_t& r1,
                                          uint32_t& r2, uint32_t& r3, uint32_t a) {
    asm volatile("ldmatrix.sync.aligned.m8n8.x4.trans.shared.b16 {%0,%1,%2,%3}, [%4];"
                 : "=r"(r0), "=r"(r1), "=r"(r2), "=r"(r3) : "r"(a));
}

__device__ __forceinline__ void mma16816(float* c, const uint32_t* a,
                                         uint32_t b0, uint32_t b1) {
    asm volatile(
        "mma.sync.aligned.m16n8k16.row.col.f32.f16.f16.f32 "
        "{%0,%1,%2,%3}, {%4,%5,%6,%7}, {%8,%9}, {%0,%1,%2,%3};"
        : "+f"(c[0]), "+f"(c[1]), "+f"(c[2]), "+f"(c[3])
        : "r"(a[0]), "r"(a[1]), "r"(a[2]), "r"(a[3]), "r"(b0), "r"(b1));
}

// One k-tile of split-MMA: A (hi/lo) x W rows [krow..krow+16) -> acc[8][4]
__device__ __forceinline__ void ktile_mma(const __half* W, int ws, int wpl, int krow,
                                          const uint32_t* ah, const uint32_t* al,
                                          float (*acc)[4])
{
    const int lane = threadIdx.x & 31;
    #pragma unroll
    for (int nb = 0; nb < 4; nb++) {
        const __half* wp = W + (krow + (lane & 7) + ((lane >> 3) & 1) * 8) * ws
                         + nb * 16 + ((lane >> 4) << 3);
        uint32_t bh0, bh1, bh2, bh3, bl0, bl1, bl2, bl3;
        ldsm_x4_t(bh0, bh1, bh2, bh3, smem_u32(wp));
        ldsm_x4_t(bl0, bl1, bl2, bl3, smem_u32(wp + wpl));
        mma16816(acc[2 * nb + 0], ah, bh0, bh1);
        mma16816(acc[2 * nb + 0], ah, bl0, bl1);
        mma16816(acc[2 * nb + 0], al, bh0, bh1);
        mma16816(acc[2 * nb + 1], ah, bh2, bh3);
        mma16816(acc[2 * nb + 1], ah, bl2, bl3);
        mma16816(acc[2 * nb + 1], al, bh2, bh3);
    }
}

// Fragment load/store in slab layout: slab = r16*JS + j; q-slabs 32 words apart.
__device__ __forceinline__ void ldfrag(const uint32_t* __restrict__ base,
                                       size_t slab, uint32_t* a)
{
    const int lane = threadIdx.x & 31;
    const uint32_t* pp = base + slab * 128 + lane;
    a[0] = pp[0];
    a[1] = pp[32];
    a[2] = pp[64];
    a[3] = pp[96];
}

__device__ __forceinline__ void stfrag(uint32_t* __restrict__ base,
                                       size_t slab, const uint32_t* a)
{
    const int lane = threadIdx.x & 31;
    uint32_t* pp = base + slab * 128 + lane;
    pp[0]  = a[0];
    pp[32] = a[1];
    pp[64] = a[2];
    pp[96] = a[3];
}

// ---------------------------------------------------------------------------
// acc -> A-fragment conversion (identity: n-pair {2j,2j+1} == k-tile j)
// ---------------------------------------------------------------------------
template <bool RELU>
__device__ __forceinline__ void convert_acc(float (*acc)[4],
                                            uint32_t (*Ah)[4],
                                            uint32_t (*Al)[4])
{
    #pragma unroll
    for (int j = 0; j < 4; j++)
        #pragma unroll
        for (int q = 0; q < 4; q++) {
            float v0 = acc[2 * j + (q >> 1)][(q & 1) * 2 + 0];
            float v1 = acc[2 * j + (q >> 1)][(q & 1) * 2 + 1];
            if (RELU) { v0 = fmaxf(v0, 0.f); v1 = fmaxf(v1, 0.f); }
            __half h0, l0, h1, l1;
            split2(v0, h0, l0);
            split2(v1, h1, l1);
            Ah[j][q] = pack2(h0, h1);
            Al[j][q] = pack2(l0, l1);
        }
}

// Layer with A in registers: K = KT*16 -> N = 64 (in-place A update)
template <int KT, bool RELU>
__device__ __forceinline__ void layer_reg(uint32_t (*Ah)[4], uint32_t (*Al)[4],
                                          const __half* W, int ws, int wpl)
{
    float acc[8][4];
    #pragma unroll
    for (int t = 0; t < 8; t++)
        #pragma unroll
        for (int j = 0; j < 4; j++) acc[t][j] = 0.f;
    #pragma unroll
    for (int kk = 0; kk < KT; kk++)
        ktile_mma(W, ws, wpl, kk * 16, Ah[kk], Al[kk], acc);
    convert_acc<RELU>(acc, Ah, Al);
}

// Layer with A fragments loaded from fragment-layout gmem (hi/lo planes).
template <int KT, bool RELU>
__device__ __forceinline__ void layer_gfrag(const uint32_t* __restrict__ bh,
                                            const uint32_t* __restrict__ bl,
                                            size_t slab0,
                                            const __half* W, int ws, int wpl,
                                            uint32_t (*Ah)[4], uint32_t (*Al)[4])
{
    float acc[8][4];
    #pragma unroll
    for (int t = 0; t < 8; t++)
        #pragma unroll
        for (int j = 0; j < 4; j++) acc[t][j] = 0.f;
    #pragma unroll
    for (int kk = 0; kk < KT; kk++) {
        uint32_t th[4], tl[4];
        ldfrag(bh, slab0 + kk, th);
        ldfrag(bl, slab0 + kk, tl);
        ktile_mma(W, ws, wpl, kk * 16, th, tl, acc);
    }
    convert_acc<RELU>(acc, Ah, Al);
}

// ---------------------------------------------------------------------------
// Persistent branch MLP: both S and D blobs resident; 148 blocks x 512 thr.
// ---------------------------------------------------------------------------
#define MLPALL_SMEM (WB_TOT * 2 * 2)

__global__ void __launch_bounds__(512, 1)
mlp64_all()
{
    extern __shared__ __align__(16) __half sm[];
    const int tid = threadIdx.x;

    {
        const uint4* s0 = (const uint4*)g_wS;
        const uint4* s1 = (const uint4*)g_wD;
        uint4* d0 = (uint4*)sm;
        uint4* d1 = (uint4*)(sm + WB_TOT);
        #pragma unroll 4
        for (int i = tid; i < WB_TOT / 8; i += 512) { d0[i] = s0[i]; d1[i] = s1[i]; }
    }
    __syncthreads();

    const int w = tid >> 5;

    for (int tile = blockIdx.x; tile < 2 * NTILES; tile += gridDim.x) {
        const int which = tile >= NTILES;
        const size_t r16 = (size_t)(tile & (NTILES - 1)) * 16 + w;
        const __half* W  = sm + which * WB_TOT;
        const uint32_t* eh = which ? g_enc_d_hi : g_enc_s_hi;
        const uint32_t* el = which ? g_enc_d_lo : g_enc_s_lo;

        uint32_t Ah[4][4], Al[4][4];

        layer_gfrag<2, true>(eh, el, r16 * 2, W + WB_IN, 72, 32 * 72, Ah, Al);
        layer_reg<4, true >(Ah, Al, W + WB_H0,  72, 64 * 72);
        layer_reg<4, true >(Ah, Al, W + WB_H1,  72, 64 * 72);
        layer_reg<4, true >(Ah, Al, W + WB_H2,  72, 64 * 72);
        layer_reg<4, false>(Ah, Al, W + WB_OUT, 72, 64 * 72);

        #pragma unroll
        for (int j = 0; j < 4; j++) {
            stfrag(g_feat_hi, r16 * 8 + which * 4 + j, Ah[j]);
            stfrag(g_feat_lo, r16 * 8 + which * 4 + j, Al[j]);
        }
    }
}

// ---------------------------------------------------------------------------
// Persistent merged head: feat128 -> 64 -> 64 -> 128 (+blend, regs) -> 64 -> 64 -> 1
// ---------------------------------------------------------------------------
#define HH2    H1_TOT
#define HHO    (HH2 + H2_TOT)
#define HEAD_SMEM ((HHO + 128) * 2)

__global__ void __launch_bounds__(512, 1)
head_tc(const float* __restrict__ alpha_p,
        const float* __restrict__ w2_out, float* __restrict__ out)
{
    extern __shared__ __align__(16) __half sm[];
    const int tid = threadIdx.x;
    float* wo = (float*)(sm + HHO);

    {
        const uint4* s1 = (const uint4*)g_wH1;
        uint4* d1 = (uint4*)sm;
        #pragma unroll 4
        for (int i = tid; i < H1_TOT / 8; i += 512) d1[i] = s1[i];
        const uint4* s2 = (const uint4*)g_wH2;
        uint4* d2 = (uint4*)(sm + HH2);
        #pragma unroll 4
        for (int i = tid; i < H2_TOT / 8; i += 512) d2[i] = s2[i];
        for (int i = tid; i < 64; i += 512) wo[i] = w2_out[i];
    }
    __syncthreads();

    const int w = tid >> 5;
    const int lane = tid & 31;
    const int g = lane >> 2, t2 = lane & 3;

    const float alpha = __ldg(alpha_p);
    const float beta  = 1.f - alpha;

    for (int tile = blockIdx.x; tile < NTILES; tile += gridDim.x) {
        const size_t r16  = (size_t)tile * 16 + w;
        const size_t row0 = r16 * 16;

        uint32_t A1h[4][4], A1l[4][4];
        layer_gfrag<8, true>(g_feat_hi, g_feat_lo, r16 * 8,
                             sm + H1_IN, 72, 128 * 72, A1h, A1l);
        layer_reg<4, true>(A1h, A1l, sm + H1_H, 72, 64 * 72);

        float acc2[8][4];
        #pragma unroll
        for (int t = 0; t < 8; t++)
            #pragma unroll
            for (int j = 0; j < 4; j++) acc2[t][j] = 0.f;

        #pragma unroll
        for (int half = 0; half < 2; half++) {
            const int noff = half * 64;
            float accO[8][4];
            #pragma unroll
            for (int t = 0; t < 8; t++)
                #pragma unroll
                for (int j = 0; j < 4; j++) accO[t][j] = 0.f;

            #pragma unroll
            for (int kk = 0; kk < 4; kk++) {
                const __half* Wb = sm + H1_OUT + noff;
                const __half* wrow = Wb + (kk * 16 + (lane & 7) + ((lane >> 3) & 1) * 8) * 136
                                   + ((lane >> 4) << 3);
                #pragma unroll
                for (int nb = 0; nb < 4; nb++) {
                    uint32_t bh0, bh1, bh2, bh3, bl0, bl1, bl2, bl3;
                    ldsm_x4_t(bh0, bh1, bh2, bh3, smem_u32(wrow + nb * 16));
                    ldsm_x4_t(bl0, bl1, bl2, bl3, smem_u32(wrow + nb * 16 + 64 * 136));
                    mma16816(accO[2 * nb + 0], A1h[kk], bh0, bh1);
                    mma16816(accO[2 * nb + 0], A1h[kk], bl0, bl1);
                    mma16816(accO[2 * nb + 0], A1l[kk], bh0, bh1);
                    mma16816(accO[2 * nb + 1], A1h[kk], bh2, bh3);
                    mma16816(accO[2 * nb + 1], A1h[kk], bl2, bl3);
                    mma16816(accO[2 * nb + 1], A1l[kk], bh2, bh3);
                }
            }

            uint32_t Fh[4][4], Fl[4][4];
            #pragma unroll
            for (int j = 0; j < 4; j++) {
                uint32_t fh[4], fl[4];
                ldfrag(g_feat_hi, r16 * 8 + half * 4 + j, fh);
                ldfrag(g_feat_lo, r16 * 8 + half * 4 + j, fl);
                #pragma unroll
                for (int q = 0; q < 4; q++) {
                    float v0 = accO[2 * j + (q >> 1)][(q & 1) * 2 + 0];
                    float v1 = accO[2 * j + (q >> 1)][(q & 1) * 2 + 1];
                    float2 vh = __half22float2(*reinterpret_cast<__half2*>(&fh[q]));
                    float2 vl = __half22float2(*reinterpret_cast<__half2*>(&fl[q]));
                    v0 = v0 * alpha + beta * (vh.x + vl.x);
                    v1 = v1 * alpha + beta * (vh.y + vl.y);
                    __half h0, l0, h1, l1;
                    split2(v0, h0, l0);
                    split2(v1, h1, l1);
                    Fh[j][q] = pack2(h0, h1);
                    Fl[j][q] = pack2(l0, l1);
                }
            }

            #pragma unroll
            for (int kk = 0; kk < 4; kk++)
                ktile_mma(sm + HH2 + H2_IN, 72, 128 * 72, noff + kk * 16,
                          Fh[kk], Fl[kk], acc2);
        }

        uint32_t A2h[4][4], A2l[4][4];
        convert_acc<true>(acc2, A2h, A2l);
        layer_reg<4, true>(A2h, A2l, sm + HH2 + H2_H, 72, 64 * 72);

        {
            float sg = 0.f, sg8 = 0.f;
            #pragma unroll
            for (int j = 0; j < 4; j++)
                #pragma unroll
                for (int q = 0; q < 4; q++) {
                    __half2 hv = *reinterpret_cast<__half2*>(&A2h[j][q]);
                    __half2 lv = *reinterpret_cast<__half2*>(&A2l[j][q]);
                    float2 vh = __half22float2(hv);
                    float2 vl = __half22float2(lv);
                    int c = j * 16 + ((q >> 1) << 3) + t2 * 2;
                    float d = fmaf(vh.x + vl.x, wo[c], (vh.y + vl.y) * wo[c + 1]);
                    if ((q & 1) == 0) sg += d; else sg8 += d;
                }
            sg  += __shfl_xor_sync(0xffffffffu, sg, 1);
            sg  += __shfl_xor_sync(0xffffffffu, sg, 2);
            sg8 += __shfl_xor_sync(0xffffffffu, sg8, 1);
            sg8 += __shfl_xor_sync(0xffffffffu, sg8, 2);
            if (t2 == 0) {
                out[row0 + g]     = sg;
                out[row0 + g + 8] = sg8;
            }
        }
    }
}

// ---------------------------------------------------------------------------
// Launch (strictly serial — R5 showed L1-bound kernels must not overlap)
// ---------------------------------------------------------------------------
extern "C" void kernel_launch(void* const* d_in, const int* in_sizes, int n_in,
                              void* d_out, int out_size)
{
    const float* x       = (const float*)d_in[0];
    const float* t       = (const float*)d_in[1];
    const float* alpha   = (const float*)d_in[2];
    const float* table_s = (const float*)d_in[3];
    const float* ws_in   = (const float*)d_in[4];
    const float* ws_hid  = (const float*)d_in[5];
    const float* ws_out  = (const float*)d_in[6];
    const float* table_d = (const float*)d_in[7];
    const float* wd_in   = (const float*)d_in[8];
    const float* wd_hid  = (const float*)d_in[9];
    const float* wd_out  = (const float*)d_in[10];
    const float* w1_in   = (const float*)d_in[11];
    const float* w1_hid  = (const float*)d_in[12];
    const float* w1_out  = (const float*)d_in[13];
    const float* w2_in   = (const float*)d_in[14];
    const float* w2_hid  = (const float*)d_in[15];
    const float* w2_out  = (const float*)d_in[16];
    float* out = (float*)d_out;

    cudaFuncSetAttribute(mlp64_all, cudaFuncAttributeMaxDynamicSharedMemorySize, MLPALL_SMEM);
    cudaFuncSetAttribute(head_tc,   cudaFuncAttributeMaxDynamicSharedMemorySize, HEAD_SMEM);

    const int nblkENC = NPTS / 256;
    const int nblkCMB = (LVLS * (int)TSIZE) / 256;

    prep_weights<<<64, 256>>>(ws_in, ws_hid, ws_out, wd_in, wd_hid, wd_out,
                              w1_in, w1_hid, w1_out, w2_in, w2_hid);

    combine_time<<<nblkCMB, 256>>>(table_d, t);

    encode_kernel<0><<<nblkENC, 256>>>(x, table_s);
    encode_kernel<1><<<nblkENC, 256>>>(x, nullptr);

    mlp64_all<<<PGRID, 512, MLPALL_SMEM>>>();
    head_tc<<<PGRID, 512, HEAD_SMEM>>>(alpha, w2_out, out);
}

// round 16
// speedup vs baseline: 1.6517x; 1.0044x over previous
#include <cuda_runtime.h>
#include <cuda_fp16.h>
#include <cstdint>

// ---------------------------------------------------------------------------
// Problem constants
// ---------------------------------------------------------------------------
#define NPTS   524288
#define LVLS   16
#define TSIZE  524288u
#define TMASK  (TSIZE - 1u)
#define NTILES 2048          // 256-point tiles
#define PGRID  148           // persistent grid = #SMs

__constant__ float c_res[LVLS] = {
    16.f, 24.f, 36.f, 54.f, 81.f, 121.f, 182.f, 273.f,
    410.f, 615.f, 922.f, 1383.f, 2075.f, 3113.f, 4670.f, 7006.f
};

// ---------------------------------------------------------------------------
// Scratch (device globals; no runtime allocation)
// Fragment layout: value32(r16, j, q, lane) at  ((r16*JS + j)*4 + q)*32 + lane
// ---------------------------------------------------------------------------
__device__ __align__(16) uint32_t g_enc_s_hi[(size_t)NPTS * 16];
__device__ __align__(16) uint32_t g_enc_s_lo[(size_t)NPTS * 16];
__device__ __align__(16) uint32_t g_enc_d_hi[(size_t)NPTS * 16];
__device__ __align__(16) uint32_t g_enc_d_lo[(size_t)NPTS * 16];
__device__ __align__(16) uint32_t g_feat_hi [(size_t)NPTS * 64];
__device__ __align__(16) uint32_t g_feat_lo [(size_t)NPTS * 64];

// Time-folded dynamic table: T'[l][B] = wt0*T[l][B^ht0] + wt1*T[l][B^ht1]
__device__ __align__(16) float2 g_tdt[(size_t)LVLS * TSIZE];

// Pre-split weight blobs (hi plane, lo plane at +rows*stride), stride 72/136
#define WB_IN   0
#define WB_H0   4608
#define WB_H1   13824
#define WB_H2   23040
#define WB_OUT  32256
#define WB_TOT  41472
__device__ __align__(16) __half g_wS[WB_TOT];
__device__ __align__(16) __half g_wD[WB_TOT];
#define H1_IN   0
#define H1_H    18432
#define H1_OUT  27648
#define H1_TOT  45056
__device__ __align__(16) __half g_wH1[H1_TOT];
#define H2_IN   0
#define H2_H    18432
#define H2_TOT  27648
__device__ __align__(16) __half g_wH2[H2_TOT];

// ---------------------------------------------------------------------------
__device__ __forceinline__ void split2(float x, __half& h, __half& l) {
    h = __float2half_rn(x);
    l = __float2half_rn(x - __half2float(h));
}

__device__ __forceinline__ uint32_t pack2(__half a, __half b) {
    __half2 v = __halves2half2(a, b);
    return *reinterpret_cast<uint32_t*>(&v);
}

__device__ __forceinline__ void conv_w(__half* dst, const float* __restrict__ src,
                                       int K, int N, int ws, int t0, int nt)
{
    const int tot = K * N / 2;
    const int pl  = K * ws;
    const float2* s2 = (const float2*)src;
    for (int i = t0; i < tot; i += nt) {
        int r = (2 * i) / N, c = (2 * i) % N;
        float2 v = s2[i];
        __half hx, lx, hy, ly;
        split2(v.x, hx, lx);
        split2(v.y, hy, ly);
        *(__half2*)(dst + r * ws + c)      = __halves2half2(hx, hy);
        *(__half2*)(dst + r * ws + pl + c) = __halves2half2(lx, ly);
    }
}

__global__ void __launch_bounds__(256)
prep_weights(const float* __restrict__ ws_in, const float* __restrict__ ws_hid,
             const float* __restrict__ ws_out,
             const float* __restrict__ wd_in, const float* __restrict__ wd_hid,
             const float* __restrict__ wd_out,
             const float* __restrict__ w1_in, const float* __restrict__ w1_hid,
             const float* __restrict__ w1_out,
             const float* __restrict__ w2_in, const float* __restrict__ w2_hid)
{
    const int t0 = blockIdx.x * 256 + threadIdx.x;
    const int nt = gridDim.x * 256;
    conv_w(g_wS + WB_IN,  ws_in,         32, 64, 72, t0, nt);
    conv_w(g_wS + WB_H0,  ws_hid + 0,    64, 64, 72, t0, nt);
    conv_w(g_wS + WB_H1,  ws_hid + 4096, 64, 64, 72, t0, nt);
    conv_w(g_wS + WB_H2,  ws_hid + 8192, 64, 64, 72, t0, nt);
    conv_w(g_wS + WB_OUT, ws_out,        64, 64, 72, t0, nt);
    conv_w(g_wD + WB_IN,  wd_in,         32, 64, 72, t0, nt);
    conv_w(g_wD + WB_H0,  wd_hid + 0,    64, 64, 72, t0, nt);
    conv_w(g_wD + WB_H1,  wd_hid + 4096, 64, 64, 72, t0, nt);
    conv_w(g_wD + WB_H2,  wd_hid + 8192, 64, 64, 72, t0, nt);
    conv_w(g_wD + WB_OUT, wd_out,        64, 64, 72, t0, nt);
    conv_w(g_wH1 + H1_IN,  w1_in,  128, 64,  72,  t0, nt);
    conv_w(g_wH1 + H1_H,   w1_hid, 64,  64,  72,  t0, nt);
    conv_w(g_wH1 + H1_OUT, w1_out, 64,  128, 136, t0, nt);
    conv_w(g_wH2 + H2_IN,  w2_in,  128, 64,  72,  t0, nt);
    conv_w(g_wH2 + H2_H,   w2_hid, 64,  64,  72,  t0, nt);
}

// ---------------------------------------------------------------------------
// Fold the (scalar) time dimension into the dynamic table.
// Vectorized: each thread produces outputs {B, B+1} (B even) — 2 float4 loads
// + 1 float4 store.  Per-element arithmetic identical to the scalar version.
// ---------------------------------------------------------------------------
__global__ void __launch_bounds__(256)
combine_time(const float* __restrict__ table_d, const float* __restrict__ tptr)
{
    const size_t i = (size_t)blockIdx.x * 256 + threadIdx.x;   // pair index
    const int    l = (int)(i >> 18);              // TSIZE/2 = 2^18 pairs/level
    const uint32_t B = ((uint32_t)i << 1) & TMASK;             // even

    const float t   = __ldg(tptr);
    float pos = t * c_res[l];
    float p0f = floorf(pos);
    float fr  = pos - p0f;
    uint32_t p3 = (uint32_t)p0f;
    const uint32_t P3 = 3674653429u;
    uint32_t ht0 = (p3 * P3) & TMASK;
    uint32_t ht1 = ((p3 + 1u) * P3) & TMASK;

    const float4* tl4 = (const float4*)((const float2*)table_d + (size_t)l * TSIZE);

    float4 v0 = __ldg(tl4 + ((B ^ ht0) >> 1));
    float4 v1 = __ldg(tl4 + ((B ^ ht1) >> 1));
    const bool s0 = (ht0 & 1u);
    const bool s1 = (ht1 & 1u);
    float aBx  = s0 ? v0.z : v0.x, aBy  = s0 ? v0.w : v0.y;
    float aB1x = s0 ? v0.x : v0.z, aB1y = s0 ? v0.y : v0.w;
    float bBx  = s1 ? v1.z : v1.x, bBy  = s1 ? v1.w : v1.y;
    float bB1x = s1 ? v1.x : v1.z, bB1y = s1 ? v1.y : v1.w;

    const float w0 = 1.f - fr, w1 = fr;
    float4 o;
    o.x = w0 * aBx  + w1 * bBx;
    o.y = w0 * aBy  + w1 * bBy;
    o.z = w0 * aB1x + w1 * bB1x;
    o.w = w0 * aB1y + w1 * bB1y;
    ((float4*)(g_tdt + (size_t)l * TSIZE))[B >> 1] = o;
}

// ---------------------------------------------------------------------------
// Hash-grid encode, 3 spatial dims (WHICH=0: static table; WHICH=1: time-folded
// dynamic table g_tdt).  dim-0 corner-pair merge (PRIMES[0]==1) when p0 even.
// Output written directly in fragment layout (JS = 2).
// ---------------------------------------------------------------------------
template <int WHICH>
__global__ void __launch_bounds__(256)
encode_kernel(const float* __restrict__ x,
              const float* __restrict__ table)
{
    const int n = blockIdx.x * 256 + threadIdx.x;

    float p[3];
    p[0] = x[3 * n + 0];
    p[1] = x[3 * n + 1];
    p[2] = x[3 * n + 2];

    uint32_t ehi[16], elo[16];

    #pragma unroll
    for (int l = 0; l < LVLS; l++) {
        const float res = c_res[l];
        uint32_t h[3][2];
        float    w[3][2];
        uint32_t p0u = 0;
        #pragma unroll
        for (int d = 0; d < 3; d++) {
            const uint32_t pr = (d == 0) ? 1u
                              : (d == 1) ? 2654435761u
                                         : 805459861u;
            float pos = p[d] * res;
            float p0f = floorf(pos);
            float fr  = pos - p0f;
            uint32_t p0 = (uint32_t)p0f;
            if (d == 0) p0u = p0;
            h[d][0] = p0 * pr;
            h[d][1] = (p0 + 1u) * pr;
            w[d][0] = 1.f - fr;
            w[d][1] = fr;
        }

        const float2* tl = (WHICH == 0)
            ? (const float2*)table + (size_t)l * TSIZE
            : (const float2*)g_tdt + (size_t)l * TSIZE;
        float f0 = 0.f, f1 = 0.f;
        const float w00 = w[0][0], w01 = w[0][1];

        if ((p0u & 1u) == 0u) {
            #pragma unroll
            for (int rc = 0; rc < 4; rc++) {
                uint32_t A = h[1][rc & 1] ^ h[2][(rc >> 1) & 1];
                float   Wr = w[1][rc & 1] * w[2][(rc >> 1) & 1];
                uint32_t i0 = (A ^ h[0][0]) & TMASK;
                float4 v = __ldg((const float4*)tl + (i0 >> 1));
                const bool hi = (i0 & 1u);
                float e0x = hi ? v.z : v.x, e0y = hi ? v.w : v.y;
                float e1x = hi ? v.x : v.z, e1y = hi ? v.y : v.w;
                float wa = w00 * Wr, wb = w01 * Wr;
                f0 = fmaf(wa, e0x, f0);
                f1 = fmaf(wa, e0y, f1);
                f0 = fmaf(wb, e1x, f0);
                f1 = fmaf(wb, e1y, f1);
            }
        } else {
            #pragma unroll
            for (int rc = 0; rc < 4; rc++) {
                uint32_t A = h[1][rc & 1] ^ h[2][(rc >> 1) & 1];
                float   Wr = w[1][rc & 1] * w[2][(rc >> 1) & 1];
                uint32_t i0 = (A ^ h[0][0]) & TMASK;
                uint32_t i1 = (A ^ h[0][1]) & TMASK;
                float2 e0 = __ldg(tl + i0);
                float2 e1 = __ldg(tl + i1);
                float wa = w00 * Wr, wb = w01 * Wr;
                f0 = fmaf(wa, e0.x, f0);
                f1 = fmaf(wa, e0.y, f1);
                f0 = fmaf(wb, e1.x, f0);
                f1 = fmaf(wb, e1.y, f1);
            }
        }

        __half h0, l0, h1, l1;
        split2(f0, h0, l0);
        split2(f1, h1, l1);
        ehi[l] = pack2(h0, h1);
        elo[l] = pack2(l0, l1);
    }

    uint32_t* dh = (WHICH == 0 ? g_enc_s_hi : g_enc_d_hi);
    uint32_t* dl = (WHICH == 0 ? g_enc_s_lo : g_enc_d_lo);
    const size_t r16 = (size_t)(n >> 4);
    const int g   = n & 7;
    const int hi8 = (n >> 3) & 1;
    #pragma unroll
    for (int j = 0; j < 2; j++) {
        size_t b0 = ((r16 * 2 + j) * 4 + hi8) * 32 + g * 4;
        size_t b1 = ((r16 * 2 + j) * 4 + hi8 + 2) * 32 + g * 4;
        *(uint4*)(dh + b0) = make_uint4(ehi[j*8+0], ehi[j*8+1], ehi[j*8+2], ehi[j*8+3]);
        *(uint4*)(dh + b1) = make_uint4(ehi[j*8+4], ehi[j*8+5], ehi[j*8+6], ehi[j*8+7]);
        *(uint4*)(dl + b0) = make_uint4(elo[j*8+0], elo[j*8+1], elo[j*8+2], elo[j*8+3]);
        *(uint4*)(dl + b1) = make_uint4(elo[j*8+4], elo[j*8+5], elo[j*8+6], elo[j*8+7]);
    }
}

// ---------------------------------------------------------------------------
// Tensor-core primitives
// ---------------------------------------------------------------------------
__device__ __forceinline__ uint32_t smem_u32(const void* p) {
    return (uint32_t)__cvta_generic_to_shared(p);
}

__device__ __forceinline__ void ldsm_x4_t(uint32_t& r0, uint32_t& r1,
                                          uint32_t& r2, uint32_t& r3, uint32_t a) {
    asm volatile("ldmatrix.sync.aligned.m8n8.x4.trans.shared.b16 {%0,%1,%2,%3}, [%4];"
                 : "=r"(r0), "=r"(r1), "=r"(r2), "=r"(r3) : "r"(a));
}

__device__ __forceinline__ void mma16816(float* c, const uint32_t* a,
                                         uint32_t b0, uint32_t b1) {
    asm volatile(
        "mma.sync.aligned.m16n8k16.row.col.f32.f16.f16.f32 "
        "{%0,%1,%2,%3}, {%4,%5,%6,%7}, {%8,%9}, {%0,%1,%2,%3};"
        : "+f"(c[0]), "+f"(c[1]), "+f"(c[2]), "+f"(c[3])
        : "r"(a[0]), "r"(a[1]), "r"(a[2]), "r"(a[3]), "r"(b0), "r"(b1));
}

// One k-tile of split-MMA: A (hi/lo) x W rows [krow..krow+16) -> acc[8][4]
__device__ __forceinline__ void ktile_mma(const __half* W, int ws, int wpl, int krow,
                                          const uint32_t* ah, const uint32_t* al,
                                          float (*acc)[4])
{
    const int lane = threadIdx.x & 31;
    #pragma unroll
    for (int nb = 0; nb < 4; nb++) {
        const __half* wp = W + (krow + (lane & 7) + ((lane >> 3) & 1) * 8) * ws
                         + nb * 16 + ((lane >> 4) << 3);
        uint32_t bh0, bh1, bh2, bh3, bl0, bl1, bl2, bl3;
        ldsm_x4_t(bh0, bh1, bh2, bh3, smem_u32(wp));
        ldsm_x4_t(bl0, bl1, bl2, bl3, smem_u32(wp + wpl));
        mma16816(acc[2 * nb + 0], ah, bh0, bh1);
        mma16816(acc[2 * nb + 0], ah, bl0, bl1);
        mma16816(acc[2 * nb + 0], al, bh0, bh1);
        mma16816(acc[2 * nb + 1], ah, bh2, bh3);
        mma16816(acc[2 * nb + 1], ah, bl2, bl3);
        mma16816(acc[2 * nb + 1], al, bh2, bh3);
    }
}

// Fragment load/store in slab layout: slab = r16*JS + j; q-slabs 32 words apart.
__device__ __forceinline__ void ldfrag(const uint32_t* __restrict__ base,
                                       size_t slab, uint32_t* a)
{
    const int lane = threadIdx.x & 31;
    const uint32_t* pp = base + slab * 128 + lane;
    a[0] = pp[0];
    a[1] = pp[32];
    a[2] = pp[64];
    a[3] = pp[96];
}

__device__ __forceinline__ void stfrag(uint32_t* __restrict__ base,
                                       size_t slab, const uint32_t* a)
{
    const int lane = threadIdx.x & 31;
    uint32_t* pp = base + slab * 128 + lane;
    pp[0]  = a[0];
    pp[32] = a[1];
    pp[64] = a[2];
    pp[96] = a[3];
}

// ---------------------------------------------------------------------------
// acc -> A-fragment conversion (identity: n-pair {2j,2j+1} == k-tile j)
// ---------------------------------------------------------------------------
template <bool RELU>
__device__ __forceinline__ void convert_acc(float (*acc)[4],
                                            uint32_t (*Ah)[4],
                                            uint32_t (*Al)[4])
{
    #pragma unroll
    for (int j = 0; j < 4; j++)
        #pragma unroll
        for (int q = 0; q < 4; q++) {
            float v0 = acc[2 * j + (q >> 1)][(q & 1) * 2 + 0];
            float v1 = acc[2 * j + (q >> 1)][(q & 1) * 2 + 1];
            if (RELU) { v0 = fmaxf(v0, 0.f); v1 = fmaxf(v1, 0.f); }
            __half h0, l0, h1, l1;
            split2(v0, h0, l0);
            split2(v1, h1, l1);
            Ah[j][q] = pack2(h0, h1);
            Al[j][q] = pack2(l0, l1);
        }
}

// Layer with A in registers: K = KT*16 -> N = 64 (in-place A update)
template <int KT, bool RELU>
__device__ __forceinline__ void layer_reg(uint32_t (*Ah)[4], uint32_t (*Al)[4],
                                          const __half* W, int ws, int wpl)
{
    float acc[8][4];
    #pragma unroll
    for (int t = 0; t < 8; t++)
        #pragma unroll
        for (int j = 0; j < 4; j++) acc[t][j] = 0.f;
    #pragma unroll
    for (int kk = 0; kk < KT; kk++)
        ktile_mma(W, ws, wpl, kk * 16, Ah[kk], Al[kk], acc);
    convert_acc<RELU>(acc, Ah, Al);
}

// Layer with A fragments loaded from fragment-layout gmem (hi/lo planes).
template <int KT, bool RELU>
__device__ __forceinline__ void layer_gfrag(const uint32_t* __restrict__ bh,
                                            const uint32_t* __restrict__ bl,
                                            size_t slab0,
                                            const __half* W, int ws, int wpl,
                                            uint32_t (*Ah)[4], uint32_t (*Al)[4])
{
    float acc[8][4];
    #pragma unroll
    for (int t = 0; t < 8; t++)
        #pragma unroll
        for (int j = 0; j < 4; j++) acc[t][j] = 0.f;
    #pragma unroll
    for (int kk = 0; kk < KT; kk++) {
        uint32_t th[4], tl[4];
        ldfrag(bh, slab0 + kk, th);
        ldfrag(bl, slab0 + kk, tl);
        ktile_mma(W, ws, wpl, kk * 16, th, tl, acc);
    }
    convert_acc<RELU>(acc, Ah, Al);
}

// ---------------------------------------------------------------------------
// Persistent branch MLP: both S and D blobs resident; 148 blocks x 512 thr.
// ---------------------------------------------------------------------------
#define MLPALL_SMEM (WB_TOT * 2 * 2)

__global__ void __launch_bounds__(512, 1)
mlp64_all()
{
    extern __shared__ __align__(16) __half sm[];
    const int tid = threadIdx.x;

    {
        const uint4* s0 = (const uint4*)g_wS;
        const uint4* s1 = (const uint4*)g_wD;
        uint4* d0 = (uint4*)sm;
        uint4* d1 = (uint4*)(sm + WB_TOT);
        #pragma unroll 4
        for (int i = tid; i < WB_TOT / 8; i += 512) { d0[i] = s0[i]; d1[i] = s1[i]; }
    }
    __syncthreads();

    const int w = tid >> 5;

    for (int tile = blockIdx.x; tile < 2 * NTILES; tile += gridDim.x) {
        const int which = tile >= NTILES;
        const size_t r16 = (size_t)(tile & (NTILES - 1)) * 16 + w;
        const __half* W  = sm + which * WB_TOT;
        const uint32_t* eh = which ? g_enc_d_hi : g_enc_s_hi;
        const uint32_t* el = which ? g_enc_d_lo : g_enc_s_lo;

        uint32_t Ah[4][4], Al[4][4];

        layer_gfrag<2, true>(eh, el, r16 * 2, W + WB_IN, 72, 32 * 72, Ah, Al);
        layer_reg<4, true >(Ah, Al, W + WB_H0,  72, 64 * 72);
        layer_reg<4, true >(Ah, Al, W + WB_H1,  72, 64 * 72);
        layer_reg<4, true >(Ah, Al, W + WB_H2,  72, 64 * 72);
        layer_reg<4, false>(Ah, Al, W + WB_OUT, 72, 64 * 72);

        #pragma unroll
        for (int j = 0; j < 4; j++) {
            stfrag(g_feat_hi, r16 * 8 + which * 4 + j, Ah[j]);
            stfrag(g_feat_lo, r16 * 8 + which * 4 + j, Al[j]);
        }
    }
}

// ---------------------------------------------------------------------------
// Persistent merged head: feat128 -> 64 -> 64 -> 128 (+blend, regs) -> 64 -> 64 -> 1
// ---------------------------------------------------------------------------
#define HH2    H1_TOT
#define HHO    (HH2 + H2_TOT)
#define HEAD_SMEM ((HHO + 128) * 2)

__global__ void __launch_bounds__(512, 1)
head_tc(const float* __restrict__ alpha_p,
        const float* __restrict__ w2_out, float* __restrict__ out)
{
    extern __shared__ __align__(16) __half sm[];
    const int tid = threadIdx.x;
    float* wo = (float*)(sm + HHO);

    {
        const uint4* s1 = (const uint4*)g_wH1;
        uint4* d1 = (uint4*)sm;
        #pragma unroll 4
        for (int i = tid; i < H1_TOT / 8; i += 512) d1[i] = s1[i];
        const uint4* s2 = (const uint4*)g_wH2;
        uint4* d2 = (uint4*)(sm + HH2);
        #pragma unroll 4
        for (int i = tid; i < H2_TOT / 8; i += 512) d2[i] = s2[i];
        for (int i = tid; i < 64; i += 512) wo[i] = w2_out[i];
    }
    __syncthreads();

    const int w = tid >> 5;
    const int lane = tid & 31;
    const int g = lane >> 2, t2 = lane & 3;

    const float alpha = __ldg(alpha_p);
    const float beta  = 1.f - alpha;

    for (int tile = blockIdx.x; tile < NTILES; tile += gridDim.x) {
        const size_t r16  = (size_t)tile * 16 + w;
        const size_t row0 = r16 * 16;

        uint32_t A1h[4][4], A1l[4][4];
        layer_gfrag<8, true>(g_feat_hi, g_feat_lo, r16 * 8,
                             sm + H1_IN, 72, 128 * 72, A1h, A1l);
        layer_reg<4, true>(A1h, A1l, sm + H1_H, 72, 64 * 72);

        float acc2[8][4];
        #pragma unroll
        for (int t = 0; t < 8; t++)
            #pragma unroll
            for (int j = 0; j < 4; j++) acc2[t][j] = 0.f;

        #pragma unroll
        for (int half = 0; half < 2; half++) {
            const int noff = half * 64;
            float accO[8][4];
            #pragma unroll
            for (int t = 0; t < 8; t++)
                #pragma unroll
                for (int j = 0; j < 4; j++) accO[t][j] = 0.f;

            #pragma unroll
            for (int kk = 0; kk < 4; kk++) {
                const __half* Wb = sm + H1_OUT + noff;
                const __half* wrow = Wb + (kk * 16 + (lane & 7) + ((lane >> 3) & 1) * 8) * 136
                                   + ((lane >> 4) << 3);
                #pragma unroll
                for (int nb = 0; nb < 4; nb++) {
                    uint32_t bh0, bh1, bh2, bh3, bl0, bl1, bl2, bl3;
                    ldsm_x4_t(bh0, bh1, bh2, bh3, smem_u32(wrow + nb * 16));
                    ldsm_x4_t(bl0, bl1, bl2, bl3, smem_u32(wrow + nb * 16 + 64 * 136));
                    mma16816(accO[2 * nb + 0], A1h[kk], bh0, bh1);
                    mma16816(accO[2 * nb + 0], A1h[kk], bl0, bl1);
                    mma16816(accO[2 * nb + 0], A1l[kk], bh0, bh1);
                    mma16816(accO[2 * nb + 1], A1h[kk], bh2, bh3);
                    mma16816(accO[2 * nb + 1], A1h[kk], bl2, bl3);
                    mma16816(accO[2 * nb + 1], A1l[kk], bh2, bh3);
                }
            }

            uint32_t Fh[4][4], Fl[4][4];
            #pragma unroll
            for (int j = 0; j < 4; j++) {
                uint32_t fh[4], fl[4];
                ldfrag(g_feat_hi, r16 * 8 + half * 4 + j, fh);
                ldfrag(g_feat_lo, r16 * 8 + half * 4 + j, fl);
                #pragma unroll
                for (int q = 0; q < 4; q++) {
                    float v0 = accO[2 * j + (q >> 1)][(q & 1) * 2 + 0];
                    float v1 = accO[2 * j + (q >> 1)][(q & 1) * 2 + 1];
                    float2 vh = __half22float2(*reinterpret_cast<__half2*>(&fh[q]));
                    float2 vl = __half22float2(*reinterpret_cast<__half2*>(&fl[q]));
                    v0 = v0 * alpha + beta * (vh.x + vl.x);
                    v1 = v1 * alpha + beta * (vh.y + vl.y);
                    __half h0, l0, h1, l1;
                    split2(v0, h0, l0);
                    split2(v1, h1, l1);
                    Fh[j][q] = pack2(h0, h1);
                    Fl[j][q] = pack2(l0, l1);
                }
            }

            #pragma unroll
            for (int kk = 0; kk < 4; kk++)
                ktile_mma(sm + HH2 + H2_IN, 72, 128 * 72, noff + kk * 16,
                          Fh[kk], Fl[kk], acc2);
        }

        uint32_t A2h[4][4], A2l[4][4];
        convert_acc<true>(acc2, A2h, A2l);
        layer_reg<4, true>(A2h, A2l, sm + HH2 + H2_H, 72, 64 * 72);

        {
            float sg = 0.f, sg8 = 0.f;
            #pragma unroll
            for (int j = 0; j < 4; j++)
                #pragma unroll
                for (int q = 0; q < 4; q++) {
                    __half2 hv = *reinterpret_cast<__half2*>(&A2h[j][q]);
                    __half2 lv = *reinterpret_cast<__half2*>(&A2l[j][q]);
                    float2 vh = __half22float2(hv);
                    float2 vl = __half22float2(lv);
                    int c = j * 16 + ((q >> 1) << 3) + t2 * 2;
                    float d = fmaf(vh.x + vl.x, wo[c], (vh.y + vl.y) * wo[c + 1]);
                    if ((q & 1) == 0) sg += d; else sg8 += d;
                }
            sg  += __shfl_xor_sync(0xffffffffu, sg, 1);
            sg  += __shfl_xor_sync(0xffffffffu, sg, 2);
            sg8 += __shfl_xor_sync(0xffffffffu, sg8, 1);
            sg8 += __shfl_xor_sync(0xffffffffu, sg8, 2);
            if (t2 == 0) {
                out[row0 + g]     = sg;
                out[row0 + g + 8] = sg8;
            }
        }
    }
}

// ---------------------------------------------------------------------------
// Launch: side stream must FORK from the origin stream (event) for graph
// capture to accept it.  combine_time overlaps prep_weights + encode_s;
// join before encode_d (which consumes g_tdt).
// ---------------------------------------------------------------------------
extern "C" void kernel_launch(void* const* d_in, const int* in_sizes, int n_in,
                              void* d_out, int out_size)
{
    const float* x       = (const float*)d_in[0];
    const float* t       = (const float*)d_in[1];
    const float* alpha   = (const float*)d_in[2];
    const float* table_s = (const float*)d_in[3];
    const float* ws_in   = (const float*)d_in[4];
    const float* ws_hid  = (const float*)d_in[5];
    const float* ws_out  = (const float*)d_in[6];
    const float* table_d = (const float*)d_in[7];
    const float* wd_in   = (const float*)d_in[8];
    const float* wd_hid  = (const float*)d_in[9];
    const float* wd_out  = (const float*)d_in[10];
    const float* w1_in   = (const float*)d_in[11];
    const float* w1_hid  = (const float*)d_in[12];
    const float* w1_out  = (const float*)d_in[13];
    const float* w2_in   = (const float*)d_in[14];
    const float* w2_hid  = (const float*)d_in[15];
    const float* w2_out  = (const float*)d_in[16];
    float* out = (float*)d_out;

    static cudaStream_t s1 = nullptr;
    static cudaEvent_t  eF = nullptr, eC = nullptr;
    if (s1 == nullptr) {
        cudaStreamCreateWithFlags(&s1, cudaStreamNonBlocking);
        cudaEventCreateWithFlags(&eF, cudaEventDisableTiming);
        cudaEventCreateWithFlags(&eC, cudaEventDisableTiming);
    }

    cudaFuncSetAttribute(mlp64_all, cudaFuncAttributeMaxDynamicSharedMemorySize, MLPALL_SMEM);
    cudaFuncSetAttribute(head_tc,   cudaFuncAttributeMaxDynamicSharedMemorySize, HEAD_SMEM);

    const int nblkENC = NPTS / 256;
    const int nblkCMB = (LVLS * (int)TSIZE / 2) / 256;

    // fork side stream from the origin stream (required for graph capture)
    cudaEventRecord(eF, 0);
    cudaStreamWaitEvent(s1, eF, 0);
    combine_time<<<nblkCMB, 256, 0, s1>>>(table_d, t);
    cudaEventRecord(eC, s1);

    prep_weights<<<64, 256>>>(ws_in, ws_hid, ws_out, wd_in, wd_hid, wd_out,
                              w1_in, w1_hid, w1_out, w2_in, w2_hid);

    encode_kernel<0><<<nblkENC, 256>>>(x, table_s);

    cudaStreamWaitEvent(0, eC, 0);
    encode_kernel<1><<<nblkENC, 256>>>(x, nullptr);

    mlp64_all<<<PGRID, 512, MLPALL_SMEM>>>();
    head_tc<<<PGRID, 512, HEAD_SMEM>>>(alpha, w2_out, out);
}

// round 17
// speedup vs baseline: 1.8151x; 1.0989x over previous
#include <cuda_runtime.h>
#include <cuda_fp16.h>
#include <cstdint>

// ---------------------------------------------------------------------------
// Problem constants
// ---------------------------------------------------------------------------
#define NPTS   524288
#define LVLS   16
#define TSIZE  524288u
#define TMASK  (TSIZE - 1u)
#define NTILES 2048          // 256-point tiles
#define PGRID  148           // persistent grid = #SMs

__constant__ float c_res[LVLS] = {
    16.f, 24.f, 36.f, 54.f, 81.f, 121.f, 182.f, 273.f,
    410.f, 615.f, 922.f, 1383.f, 2075.f, 3113.f, 4670.f, 7006.f
};

// ---------------------------------------------------------------------------
// Scratch (device globals; no runtime allocation)
// Fragment layout: value32(r16, j, q, lane) at  ((r16*JS + j)*4 + q)*32 + lane
// ---------------------------------------------------------------------------
__device__ __align__(16) uint32_t g_enc_s_hi[(size_t)NPTS * 16];
__device__ __align__(16) uint32_t g_enc_s_lo[(size_t)NPTS * 16];
__device__ __align__(16) uint32_t g_enc_d_hi[(size_t)NPTS * 16];
__device__ __align__(16) uint32_t g_enc_d_lo[(size_t)NPTS * 16];
__device__ __align__(16) uint32_t g_feat_hi [(size_t)NPTS * 64];
__device__ __align__(16) uint32_t g_feat_lo [(size_t)NPTS * 64];

// Interleaved table: g_tbl[l*TSIZE+B] = (s.x, s.y, dt.x, dt.y)
// where dt = time-folded dynamic entry.
__device__ __align__(16) float4 g_tbl[(size_t)LVLS * TSIZE];

// Pre-split weight blobs (hi plane, lo plane at +rows*stride), stride 72/136
#define WB_IN   0
#define WB_H0   4608
#define WB_H1   13824
#define WB_H2   23040
#define WB_OUT  32256
#define WB_TOT  41472
__device__ __align__(16) __half g_wS[WB_TOT];
__device__ __align__(16) __half g_wD[WB_TOT];
#define H1_IN   0
#define H1_H    18432
#define H1_OUT  27648
#define H1_TOT  45056
__device__ __align__(16) __half g_wH1[H1_TOT];
#define H2_IN   0
#define H2_H    18432
#define H2_TOT  27648
__device__ __align__(16) __half g_wH2[H2_TOT];

// ---------------------------------------------------------------------------
__device__ __forceinline__ void split2(float x, __half& h, __half& l) {
    h = __float2half_rn(x);
    l = __float2half_rn(x - __half2float(h));
}

__device__ __forceinline__ uint32_t pack2(__half a, __half b) {
    __half2 v = __halves2half2(a, b);
    return *reinterpret_cast<uint32_t*>(&v);
}

__device__ __forceinline__ void conv_w(__half* dst, const float* __restrict__ src,
                                       int K, int N, int ws, int t0, int nt)
{
    const int tot = K * N / 2;
    const int pl  = K * ws;
    const float2* s2 = (const float2*)src;
    for (int i = t0; i < tot; i += nt) {
        int r = (2 * i) / N, c = (2 * i) % N;
        float2 v = s2[i];
        __half hx, lx, hy, ly;
        split2(v.x, hx, lx);
        split2(v.y, hy, ly);
        *(__half2*)(dst + r * ws + c)      = __halves2half2(hx, hy);
        *(__half2*)(dst + r * ws + pl + c) = __halves2half2(lx, ly);
    }
}

__global__ void __launch_bounds__(256)
prep_weights(const float* __restrict__ ws_in, const float* __restrict__ ws_hid,
             const float* __restrict__ ws_out,
             const float* __restrict__ wd_in, const float* __restrict__ wd_hid,
             const float* __restrict__ wd_out,
             const float* __restrict__ w1_in, const float* __restrict__ w1_hid,
             const float* __restrict__ w1_out,
             const float* __restrict__ w2_in, const float* __restrict__ w2_hid)
{
    const int t0 = blockIdx.x * 256 + threadIdx.x;
    const int nt = gridDim.x * 256;
    conv_w(g_wS + WB_IN,  ws_in,         32, 64, 72, t0, nt);
    conv_w(g_wS + WB_H0,  ws_hid + 0,    64, 64, 72, t0, nt);
    conv_w(g_wS + WB_H1,  ws_hid + 4096, 64, 64, 72, t0, nt);
    conv_w(g_wS + WB_H2,  ws_hid + 8192, 64, 64, 72, t0, nt);
    conv_w(g_wS + WB_OUT, ws_out,        64, 64, 72, t0, nt);
    conv_w(g_wD + WB_IN,  wd_in,         32, 64, 72, t0, nt);
    conv_w(g_wD + WB_H0,  wd_hid + 0,    64, 64, 72, t0, nt);
    conv_w(g_wD + WB_H1,  wd_hid + 4096, 64, 64, 72, t0, nt);
    conv_w(g_wD + WB_H2,  wd_hid + 8192, 64, 64, 72, t0, nt);
    conv_w(g_wD + WB_OUT, wd_out,        64, 64, 72, t0, nt);
    conv_w(g_wH1 + H1_IN,  w1_in,  128, 64,  72,  t0, nt);
    conv_w(g_wH1 + H1_H,   w1_hid, 64,  64,  72,  t0, nt);
    conv_w(g_wH1 + H1_OUT, w1_out, 64,  128, 136, t0, nt);
    conv_w(g_wH2 + H2_IN,  w2_in,  128, 64,  72,  t0, nt);
    conv_w(g_wH2 + H2_H,   w2_hid, 64,  64,  72,  t0, nt);
}

// ---------------------------------------------------------------------------
// Build interleaved table: copy static entry + time-folded dynamic entry.
// Vectorized per index pair {B, B+1} (B even).
// ---------------------------------------------------------------------------
__global__ void __launch_bounds__(256)
combine_tables(const float* __restrict__ table_s,
               const float* __restrict__ table_d,
               const float* __restrict__ tptr)
{
    const size_t i = (size_t)blockIdx.x * 256 + threadIdx.x;   // pair index
    const int    l = (int)(i >> 18);              // TSIZE/2 = 2^18 pairs/level
    const uint32_t B = ((uint32_t)i << 1) & TMASK;             // even

    const float t   = __ldg(tptr);
    float pos = t * c_res[l];
    float p0f = floorf(pos);
    float fr  = pos - p0f;
    uint32_t p3 = (uint32_t)p0f;
    const uint32_t P3 = 3674653429u;
    uint32_t ht0 = (p3 * P3) & TMASK;
    uint32_t ht1 = ((p3 + 1u) * P3) & TMASK;

    const float4* ts4 = (const float4*)((const float2*)table_s + (size_t)l * TSIZE);
    const float4* td4 = (const float4*)((const float2*)table_d + (size_t)l * TSIZE);

    float4 s  = __ldg(ts4 + (B >> 1));                 // entries B, B+1 (static)
    float4 v0 = __ldg(td4 + ((B ^ ht0) >> 1));
    float4 v1 = __ldg(td4 + ((B ^ ht1) >> 1));
    const bool s0 = (ht0 & 1u);
    const bool s1 = (ht1 & 1u);
    float aBx  = s0 ? v0.z : v0.x, aBy  = s0 ? v0.w : v0.y;
    float aB1x = s0 ? v0.x : v0.z, aB1y = s0 ? v0.y : v0.w;
    float bBx  = s1 ? v1.z : v1.x, bBy  = s1 ? v1.w : v1.y;
    float bB1x = s1 ? v1.x : v1.z, bB1y = s1 ? v1.y : v1.w;

    const float w0 = 1.f - fr, w1 = fr;
    float4* dst = g_tbl + (size_t)l * TSIZE + B;
    dst[0] = make_float4(s.x, s.y, w0 * aBx  + w1 * bBx,  w0 * aBy  + w1 * bBy);
    dst[1] = make_float4(s.z, s.w, w0 * aB1x + w1 * bB1x, w0 * aB1y + w1 * bB1y);
}

// ---------------------------------------------------------------------------
// Merged hash-grid encode: one float4 gather per corner serves BOTH encodes.
// Levels processed in 2 groups of 8 (bounds register liveness); outputs
// written directly in fragment layout (JS = 2, group index = j).
// ---------------------------------------------------------------------------
__global__ void __launch_bounds__(256)
encode_both(const float* __restrict__ x)
{
    const int n = blockIdx.x * 256 + threadIdx.x;

    float p[3];
    p[0] = x[3 * n + 0];
    p[1] = x[3 * n + 1];
    p[2] = x[3 * n + 2];

    const size_t r16 = (size_t)(n >> 4);
    const int g   = n & 7;
    const int hi8 = (n >> 3) & 1;

    #pragma unroll
    for (int jg = 0; jg < 2; jg++) {
        uint32_t shi[8], slo[8], dhi[8], dlo[8];

        #pragma unroll
        for (int li = 0; li < 8; li++) {
            const int l = jg * 8 + li;
            const float res = c_res[l];
            uint32_t h[3][2];
            float    w[3][2];
            #pragma unroll
            for (int d = 0; d < 3; d++) {
                const uint32_t pr = (d == 0) ? 1u
                                  : (d == 1) ? 2654435761u
                                             : 805459861u;
                float pos = p[d] * res;
                float p0f = floorf(pos);
                float fr  = pos - p0f;
                uint32_t p0 = (uint32_t)p0f;
                h[d][0] = p0 * pr;
                h[d][1] = (p0 + 1u) * pr;
                w[d][0] = 1.f - fr;
                w[d][1] = fr;
            }

            const float4* tl = g_tbl + (size_t)l * TSIZE;
            float fs0 = 0.f, fs1 = 0.f, fd0 = 0.f, fd1 = 0.f;
            const float w00 = w[0][0], w01 = w[0][1];

            #pragma unroll
            for (int rc = 0; rc < 4; rc++) {
                uint32_t A = h[1][rc & 1] ^ h[2][(rc >> 1) & 1];
                float   Wr = w[1][rc & 1] * w[2][(rc >> 1) & 1];
                uint32_t i0 = (A ^ h[0][0]) & TMASK;
                uint32_t i1 = (A ^ h[0][1]) & TMASK;   // == i0^1 when p0 even
                float4 v0 = __ldg(tl + i0);
                float4 v1 = __ldg(tl + i1);
                float wa = w00 * Wr, wb = w01 * Wr;
                fs0 = fmaf(wa, v0.x, fs0);
                fs1 = fmaf(wa, v0.y, fs1);
                fd0 = fmaf(wa, v0.z, fd0);
                fd1 = fmaf(wa, v0.w, fd1);
                fs0 = fmaf(wb, v1.x, fs0);
                fs1 = fmaf(wb, v1.y, fs1);
                fd0 = fmaf(wb, v1.z, fd0);
                fd1 = fmaf(wb, v1.w, fd1);
            }

            __half h0, l0, h1, l1;
            split2(fs0, h0, l0);
            split2(fs1, h1, l1);
            shi[li] = pack2(h0, h1);
            slo[li] = pack2(l0, l1);
            split2(fd0, h0, l0);
            split2(fd1, h1, l1);
            dhi[li] = pack2(h0, h1);
            dlo[li] = pack2(l0, l1);
        }

        // fragment-layout store for this 8-level group (k-tile j = jg)
        const size_t b0 = ((r16 * 2 + jg) * 4 + hi8) * 32 + g * 4;
        const size_t b1 = ((r16 * 2 + jg) * 4 + hi8 + 2) * 32 + g * 4;
        *(uint4*)(g_enc_s_hi + b0) = make_uint4(shi[0], shi[1], shi[2], shi[3]);
        *(uint4*)(g_enc_s_hi + b1) = make_uint4(shi[4], shi[5], shi[6], shi[7]);
        *(uint4*)(g_enc_s_lo + b0) = make_uint4(slo[0], slo[1], slo[2], slo[3]);
        *(uint4*)(g_enc_s_lo + b1) = make_uint4(slo[4], slo[5], slo[6], slo[7]);
        *(uint4*)(g_enc_d_hi + b0) = make_uint4(dhi[0], dhi[1], dhi[2], dhi[3]);
        *(uint4*)(g_enc_d_hi + b1) = make_uint4(dhi[4], dhi[5], dhi[6], dhi[7]);
        *(uint4*)(g_enc_d_lo + b0) = make_uint4(dlo[0], dlo[1], dlo[2], dlo[3]);
        *(uint4*)(g_enc_d_lo + b1) = make_uint4(dlo[4], dlo[5], dlo[6], dlo[7]);
    }
}

// ---------------------------------------------------------------------------
// Tensor-core primitives
// ---------------------------------------------------------------------------
__device__ __forceinline__ uint32_t smem_u32(const void* p) {
    return (uint32_t)__cvta_generic_to_shared(p);
}

__device__ __forceinline__ void ldsm_x4_t(uint32_t& r0, uint32_t& r1,
                                          uint32_t& r2, uint32_t& r3, uint32_t a) {
    asm volatile("ldmatrix.sync.aligned.m8n8.x4.trans.shared.b16 {%0,%1,%2,%3}, [%4];"
                 : "=r"(r0), "=r"(r1), "=r"(r2), "=r"(r3) : "r"(a));
}

__device__ __forceinline__ void mma16816(float* c, const uint32_t* a,
                                         uint32_t b0, uint32_t b1) {
    asm volatile(
        "mma.sync.aligned.m16n8k16.row.col.f32.f16.f16.f32 "
        "{%0,%1,%2,%3}, {%4,%5,%6,%7}, {%8,%9}, {%0,%1,%2,%3};"
        : "+f"(c[0]), "+f"(c[1]), "+f"(c[2]), "+f"(c[3])
        : "r"(a[0]), "r"(a[1]), "r"(a[2]), "r"(a[3]), "r"(b0), "r"(b1));
}

// One k-tile of split-MMA: A (hi/lo) x W rows [krow..krow+16) -> acc[8][4]
__device__ __forceinline__ void ktile_mma(const __half* W, int ws, int wpl, int krow,
                                          const uint32_t* ah, const uint32_t* al,
                                          float (*acc)[4])
{
    const int lane = threadIdx.x & 31;
    #pragma unroll
    for (int nb = 0; nb < 4; nb++) {
        const __half* wp = W + (krow + (lane & 7) + ((lane >> 3) & 1) * 8) * ws
                         + nb * 16 + ((lane >> 4) << 3);
        uint32_t bh0, bh1, bh2, bh3, bl0, bl1, bl2, bl3;
        ldsm_x4_t(bh0, bh1, bh2, bh3, smem_u32(wp));
        ldsm_x4_t(bl0, bl1, bl2, bl3, smem_u32(wp + wpl));
        mma16816(acc[2 * nb + 0], ah, bh0, bh1);
        mma16816(acc[2 * nb + 0], ah, bl0, bl1);
        mma16816(acc[2 * nb + 0], al, bh0, bh1);
        mma16816(acc[2 * nb + 1], ah, bh2, bh3);
        mma16816(acc[2 * nb + 1], ah, bl2, bl3);
        mma16816(acc[2 * nb + 1], al, bh2, bh3);
    }
}

// Fragment load/store in slab layout: slab = r16*JS + j; q-slabs 32 words apart.
__device__ __forceinline__ void ldfrag(const uint32_t* __restrict__ base,
                                       size_t slab, uint32_t* a)
{
    const int lane = threadIdx.x & 31;
    const uint32_t* pp = base + slab * 128 + lane;
    a[0] = pp[0];
    a[1] = pp[32];
    a[2] = pp[64];
    a[3] = pp[96];
}

__device__ __forceinline__ void stfrag(uint32_t* __restrict__ base,
                                       size_t slab, const uint32_t* a)
{
    const int lane = threadIdx.x & 31;
    uint32_t* pp = base + slab * 128 + lane;
    pp[0]  = a[0];
    pp[32] = a[1];
    pp[64] = a[2];
    pp[96] = a[3];
}

// ---------------------------------------------------------------------------
// acc -> A-fragment conversion (identity: n-pair {2j,2j+1} == k-tile j)
// ---------------------------------------------------------------------------
template <bool RELU>
__device__ __forceinline__ void convert_acc(float (*acc)[4],
                                            uint32_t (*Ah)[4],
                                            uint32_t (*Al)[4])
{
    #pragma unroll
    for (int j = 0; j < 4; j++)
        #pragma unroll
        for (int q = 0; q < 4; q++) {
            float v0 = acc[2 * j + (q >> 1)][(q & 1) * 2 + 0];
            float v1 = acc[2 * j + (q >> 1)][(q & 1) * 2 + 1];
            if (RELU) { v0 = fmaxf(v0, 0.f); v1 = fmaxf(v1, 0.f); }
            __half h0, l0, h1, l1;
            split2(v0, h0, l0);
            split2(v1, h1, l1);
            Ah[j][q] = pack2(h0, h1);
            Al[j][q] = pack2(l0, l1);
        }
}

// Layer with A in registers: K = KT*16 -> N = 64 (in-place A update)
template <int KT, bool RELU>
__device__ __forceinline__ void layer_reg(uint32_t (*Ah)[4], uint32_t (*Al)[4],
                                          const __half* W, int ws, int wpl)
{
    float acc[8][4];
    #pragma unroll
    for (int t = 0; t < 8; t++)
        #pragma unroll
        for (int j = 0; j < 4; j++) acc[t][j] = 0.f;
    #pragma unroll
    for (int kk = 0; kk < KT; kk++)
        ktile_mma(W, ws, wpl, kk * 16, Ah[kk], Al[kk], acc);
    convert_acc<RELU>(acc, Ah, Al);
}

// Layer with A fragments loaded from fragment-layout gmem (hi/lo planes).
template <int KT, bool RELU>
__device__ __forceinline__ void layer_gfrag(const uint32_t* __restrict__ bh,
                                            const uint32_t* __restrict__ bl,
                                            size_t slab0,
                                            const __half* W, int ws, int wpl,
                                            uint32_t (*Ah)[4], uint32_t (*Al)[4])
{
    float acc[8][4];
    #pragma unroll
    for (int t = 0; t < 8; t++)
        #pragma unroll
        for (int j = 0; j < 4; j++) acc[t][j] = 0.f;
    #pragma unroll
    for (int kk = 0; kk < KT; kk++) {
        uint32_t th[4], tl[4];
        ldfrag(bh, slab0 + kk, th);
        ldfrag(bl, slab0 + kk, tl);
        ktile_mma(W, ws, wpl, kk * 16, th, tl, acc);
    }
    convert_acc<RELU>(acc, Ah, Al);
}

// ---------------------------------------------------------------------------
// Persistent branch MLP: both S and D blobs resident; 148 blocks x 512 thr.
// ---------------------------------------------------------------------------
#define MLPALL_SMEM (WB_TOT * 2 * 2)

__global__ void __launch_bounds__(512, 1)
mlp64_all()
{
    extern __shared__ __align__(16) __half sm[];
    const int tid = threadIdx.x;

    {
        const uint4* s0 = (const uint4*)g_wS;
        const uint4* s1 = (const uint4*)g_wD;
        uint4* d0 = (uint4*)sm;
        uint4* d1 = (uint4*)(sm + WB_TOT);
        #pragma unroll 4
        for (int i = tid; i < WB_TOT / 8; i += 512) { d0[i] = s0[i]; d1[i] = s1[i]; }
    }
    __syncthreads();

    const int w = tid >> 5;

    for (int tile = blockIdx.x; tile < 2 * NTILES; tile += gridDim.x) {
        const int which = tile >= NTILES;
        const size_t r16 = (size_t)(tile & (NTILES - 1)) * 16 + w;
        const __half* W  = sm + which * WB_TOT;
        const uint32_t* eh = which ? g_enc_d_hi : g_enc_s_hi;
        const uint32_t* el = which ? g_enc_d_lo : g_enc_s_lo;

        uint32_t Ah[4][4], Al[4][4];

        layer_gfrag<2, true>(eh, el, r16 * 2, W + WB_IN, 72, 32 * 72, Ah, Al);
        layer_reg<4, true >(Ah, Al, W + WB_H0,  72, 64 * 72);
        layer_reg<4, true >(Ah, Al, W + WB_H1,  72, 64 * 72);
        layer_reg<4, true >(Ah, Al, W + WB_H2,  72, 64 * 72);
        layer_reg<4, false>(Ah, Al, W + WB_OUT, 72, 64 * 72);

        #pragma unroll
        for (int j = 0; j < 4; j++) {
            stfrag(g_feat_hi, r16 * 8 + which * 4 + j, Ah[j]);
            stfrag(g_feat_lo, r16 * 8 + which * 4 + j, Al[j]);
        }
    }
}

// ---------------------------------------------------------------------------
// Persistent merged head: feat128 -> 64 -> 64 -> 128 (+blend, regs) -> 64 -> 64 -> 1
// ---------------------------------------------------------------------------
#define HH2    H1_TOT
#define HHO    (HH2 + H2_TOT)
#define HEAD_SMEM ((HHO + 128) * 2)

__global__ void __launch_bounds__(512, 1)
head_tc(const float* __restrict__ alpha_p,
        const float* __restrict__ w2_out, float* __restrict__ out)
{
    extern __shared__ __align__(16) __half sm[];
    const int tid = threadIdx.x;
    float* wo = (float*)(sm + HHO);

    {
        const uint4* s1 = (const uint4*)g_wH1;
        uint4* d1 = (uint4*)sm;
        #pragma unroll 4
        for (int i = tid; i < H1_TOT / 8; i += 512) d1[i] = s1[i];
        const uint4* s2 = (const uint4*)g_wH2;
        uint4* d2 = (uint4*)(sm + HH2);
        #pragma unroll 4
        for (int i = tid; i < H2_TOT / 8; i += 512) d2[i] = s2[i];
        for (int i = tid; i < 64; i += 512) wo[i] = w2_out[i];
    }
    __syncthreads();

    const int w = tid >> 5;
    const int lane = tid & 31;
    const int g = lane >> 2, t2 = lane & 3;

    const float alpha = __ldg(alpha_p);
    const float beta  = 1.f - alpha;

    for (int tile = blockIdx.x; tile < NTILES; tile += gridDim.x) {
        const size_t r16  = (size_t)tile * 16 + w;
        const size_t row0 = r16 * 16;

        uint32_t A1h[4][4], A1l[4][4];
        layer_gfrag<8, true>(g_feat_hi, g_feat_lo, r16 * 8,
                             sm + H1_IN, 72, 128 * 72, A1h, A1l);
        layer_reg<4, true>(A1h, A1l, sm + H1_H, 72, 64 * 72);

        float acc2[8][4];
        #pragma unroll
        for (int t = 0; t < 8; t++)
            #pragma unroll
            for (int j = 0; j < 4; j++) acc2[t][j] = 0.f;

        #pragma unroll
        for (int half = 0; half < 2; half++) {
            const int noff = half * 64;
            float accO[8][4];
            #pragma unroll
            for (int t = 0; t < 8; t++)
                #pragma unroll
                for (int j = 0; j < 4; j++) accO[t][j] = 0.f;

            #pragma unroll
            for (int kk = 0; kk < 4; kk++) {
                const __half* Wb = sm + H1_OUT + noff;
                const __half* wrow = Wb + (kk * 16 + (lane & 7) + ((lane >> 3) & 1) * 8) * 136
                                   + ((lane >> 4) << 3);
                #pragma unroll
                for (int nb = 0; nb < 4; nb++) {
                    uint32_t bh0, bh1, bh2, bh3, bl0, bl1, bl2, bl3;
                    ldsm_x4_t(bh0, bh1, bh2, bh3, smem_u32(wrow + nb * 16));
                    ldsm_x4_t(bl0, bl1, bl2, bl3, smem_u32(wrow + nb * 16 + 64 * 136));
                    mma16816(accO[2 * nb + 0], A1h[kk], bh0, bh1);
                    mma16816(accO[2 * nb + 0], A1h[kk], bl0, bl1);
                    mma16816(accO[2 * nb + 0], A1l[kk], bh0, bh1);
                    mma16816(accO[2 * nb + 1], A1h[kk], bh2, bh3);
                    mma16816(accO[2 * nb + 1], A1h[kk], bl2, bl3);
                    mma16816(accO[2 * nb + 1], A1l[kk], bh2, bh3);
                }
            }

            uint32_t Fh[4][4], Fl[4][4];
            #pragma unroll
            for (int j = 0; j < 4; j++) {
                uint32_t fh[4], fl[4];
                ldfrag(g_feat_hi, r16 * 8 + half * 4 + j, fh);
                ldfrag(g_feat_lo, r16 * 8 + half * 4 + j, fl);
                #pragma unroll
                for (int q = 0; q < 4; q++) {
                    float v0 = accO[2 * j + (q >> 1)][(q & 1) * 2 + 0];
                    float v1 = accO[2 * j + (q >> 1)][(q & 1) * 2 + 1];
                    float2 vh = __half22float2(*reinterpret_cast<__half2*>(&fh[q]));
                    float2 vl = __half22float2(*reinterpret_cast<__half2*>(&fl[q]));
                    v0 = v0 * alpha + beta * (vh.x + vl.x);
                    v1 = v1 * alpha + beta * (vh.y + vl.y);
                    __half h0, l0, h1, l1;
                    split2(v0, h0, l0);
                    split2(v1, h1, l1);
                    Fh[j][q] = pack2(h0, h1);
                    Fl[j][q] = pack2(l0, l1);
                }
            }

            #pragma unroll
            for (int kk = 0; kk < 4; kk++)
                ktile_mma(sm + HH2 + H2_IN, 72, 128 * 72, noff + kk * 16,
                          Fh[kk], Fl[kk], acc2);
        }

        uint32_t A2h[4][4], A2l[4][4];
        convert_acc<true>(acc2, A2h, A2l);
        layer_reg<4, true>(A2h, A2l, sm + HH2 + H2_H, 72, 64 * 72);

        {
            float sg = 0.f, sg8 = 0.f;
            #pragma unroll
            for (int j = 0; j < 4; j++)
                #pragma unroll
                for (int q = 0; q < 4; q++) {
                    __half2 hv = *reinterpret_cast<__half2*>(&A2h[j][q]);
                    __half2 lv = *reinterpret_cast<__half2*>(&A2l[j][q]);
                    float2 vh = __half22float2(hv);
                    float2 vl = __half22float2(lv);
                    int c = j * 16 + ((q >> 1) << 3) + t2 * 2;
                    float d = fmaf(vh.x + vl.x, wo[c], (vh.y + vl.y) * wo[c + 1]);
                    if ((q & 1) == 0) sg += d; else sg8 += d;
                }
            sg  += __shfl_xor_sync(0xffffffffu, sg, 1);
            sg  += __shfl_xor_sync(0xffffffffu, sg, 2);
            sg8 += __shfl_xor_sync(0xffffffffu, sg8, 1);
            sg8 += __shfl_xor_sync(0xffffffffu, sg8, 2);
            if (t2 == 0) {
                out[row0 + g]     = sg;
                out[row0 + g + 8] = sg8;
            }
        }
    }
}

// ---------------------------------------------------------------------------
// Launch: prep_weights runs on a forked side stream under combine_tables;
// join before mlp64_all.  combine -> encode_both -> mlp -> head on stream 0.
// ---------------------------------------------------------------------------
extern "C" void kernel_launch(void* const* d_in, const int* in_sizes, int n_in,
                              void* d_out, int out_size)
{
    const float* x       = (const float*)d_in[0];
    const float* t       = (const float*)d_in[1];
    const float* alpha   = (const float*)d_in[2];
    const float* table_s = (const float*)d_in[3];
    const float* ws_in   = (const float*)d_in[4];
    const float* ws_hid  = (const float*)d_in[5];
    const float* ws_out  = (const float*)d_in[6];
    const float* table_d = (const float*)d_in[7];
    const float* wd_in   = (const float*)d_in[8];
    const float* wd_hid  = (const float*)d_in[9];
    const float* wd_out  = (const float*)d_in[10];
    const float* w1_in   = (const float*)d_in[11];
    const float* w1_hid  = (const float*)d_in[12];
    const float* w1_out  = (const float*)d_in[13];
    const float* w2_in   = (const float*)d_in[14];
    const float* w2_hid  = (const float*)d_in[15];
    const float* w2_out  = (const float*)d_in[16];
    float* out = (float*)d_out;

    static cudaStream_t s1 = nullptr;
    static cudaEvent_t  eF = nullptr, eP = nullptr;
    if (s1 == nullptr) {
        cudaStreamCreateWithFlags(&s1, cudaStreamNonBlocking);
        cudaEventCreateWithFlags(&eF, cudaEventDisableTiming);
        cudaEventCreateWithFlags(&eP, cudaEventDisableTiming);
    }

    cudaFuncSetAttribute(mlp64_all, cudaFuncAttributeMaxDynamicSharedMemorySize, MLPALL_SMEM);
    cudaFuncSetAttribute(head_tc,   cudaFuncAttributeMaxDynamicSharedMemorySize, HEAD_SMEM);

    const int nblkENC = NPTS / 256;
    const int nblkCMB = (LVLS * (int)TSIZE / 2) / 256;

    // fork side stream: weight prep overlaps the table combine
    cudaEventRecord(eF, 0);
    cudaStreamWaitEvent(s1, eF, 0);
    prep_weights<<<64, 256, 0, s1>>>(ws_in, ws_hid, ws_out, wd_in, wd_hid, wd_out,
                                     w1_in, w1_hid, w1_out, w2_in, w2_hid);
    cudaEventRecord(eP, s1);

    combine_tables<<<nblkCMB, 256>>>(table_s, table_d, t);
    encode_both<<<nblkENC, 256>>>(x);

    cudaStreamWaitEvent(0, eP, 0);
    mlp64_all<<<PGRID, 512, MLPALL_SMEM>>>();
    head_tc<<<PGRID, 512, HEAD_SMEM>>>(alpha, w2_out, out);
}